// round 1
// baseline (speedup 1.0000x reference)
#include <cuda_runtime.h>
#include <cstdint>
#include <cstddef>

#define L_SEQ 2048
#define DM    1024
#define NH    16
#define HD    64
#define RSCALE 0.125f   // 1/sqrt(64)

// ---------------- scratch (device globals; no allocs allowed) ----------------
__device__ float g_t0[L_SEQ * DM];        // x @ wq_attn (pre-rope, [i][h*64+d])
__device__ float g_t1[L_SEQ * DM];        // x @ wq_rel
__device__ float g_qa[NH * L_SEQ * HD];   // rope'd + scaled, head-major [h][i][d]
__device__ float g_qr[NH * L_SEQ * HD];   // scaled, head-major
__device__ float g_ka[L_SEQ * HD];        // rope'd in place
__device__ float g_kr[L_SEQ * HD];
__device__ float g_v [L_SEQ * HD];
__device__ float g_kaT[HD * L_SEQ];       // [d][j]
__device__ float g_krT[HD * L_SEQ];
__device__ float g_ao[L_SEQ * DM];        // attention output pre-wo, [i][h*64+d]

// ---------------- generic fp32 SGEMM: C[M,N] = A[M,K] @ B[K,N] ----------------
// BM=128, BN=128, BK=16, 256 threads, 8x8 micro-tile.
__global__ __launch_bounds__(256) void sgemm128(const float* __restrict__ A,
                                                const float* __restrict__ B,
                                                float* __restrict__ C,
                                                int M, int N, int K)
{
    __shared__ float As[128 * 20];   // [m][k], stride 20 (pad)
    __shared__ float Bs[16 * 128];   // [k][n]
    const int tid = threadIdx.x;
    const int tx = tid & 15, ty = tid >> 4;
    const int m0 = blockIdx.y * 128;
    const int n0 = blockIdx.x * 128;

    float acc[8][8];
#pragma unroll
    for (int r = 0; r < 8; ++r)
#pragma unroll
        for (int c = 0; c < 8; ++c) acc[r][c] = 0.f;

    for (int k0 = 0; k0 < K; k0 += 16) {
        __syncthreads();
#pragma unroll
        for (int it = 0; it < 2; ++it) {
            int idx = it * 256 + tid;          // 512 float4 of A tile
            int m = idx >> 2, kq = idx & 3;
            float4 v = *reinterpret_cast<const float4*>(&A[(size_t)(m0 + m) * K + k0 + kq * 4]);
            *reinterpret_cast<float4*>(&As[m * 20 + kq * 4]) = v;
        }
#pragma unroll
        for (int it = 0; it < 2; ++it) {
            int idx = it * 256 + tid;          // 512 float4 of B tile
            int kr = idx >> 5, nq = idx & 31;
            float4 v = *reinterpret_cast<const float4*>(&B[(size_t)(k0 + kr) * N + n0 + nq * 4]);
            *reinterpret_cast<float4*>(&Bs[kr * 128 + nq * 4]) = v;
        }
        __syncthreads();
#pragma unroll
        for (int kk = 0; kk < 16; ++kk) {
            float a[8], b[8];
#pragma unroll
            for (int r = 0; r < 8; ++r) a[r] = As[(ty * 8 + r) * 20 + kk];
#pragma unroll
            for (int c = 0; c < 8; ++c) b[c] = Bs[kk * 128 + tx * 8 + c];
#pragma unroll
            for (int r = 0; r < 8; ++r)
#pragma unroll
                for (int c = 0; c < 8; ++c) acc[r][c] = fmaf(a[r], b[c], acc[r][c]);
        }
    }
#pragma unroll
    for (int r = 0; r < 8; ++r) {
        float4* p = reinterpret_cast<float4*>(&C[(size_t)(m0 + ty * 8 + r) * N + n0 + tx * 8]);
        p[0] = make_float4(acc[r][0], acc[r][1], acc[r][2], acc[r][3]);
        p[1] = make_float4(acc[r][4], acc[r][5], acc[r][6], acc[r][7]);
    }
}

// ---------------- small projections: ka, kr, v (N=64, K=1024) ----------------
__global__ __launch_bounds__(256) void proj_small(const float* __restrict__ x,
                                                  const float* __restrict__ sym,
                                                  const float* __restrict__ wka,
                                                  const float* __restrict__ wkr,
                                                  const float* __restrict__ wv)
{
    __shared__ float As[64 * 20];
    __shared__ float Bs[16 * 64];
    const int sel = blockIdx.y;                    // 0: ka, 1: kr, 2: v
    const float* A = (sel == 2) ? sym : x;
    const float* B = (sel == 0) ? wka : (sel == 1) ? wkr : wv;
    float* C = (sel == 0) ? g_ka : (sel == 1) ? g_kr : g_v;

    const int tid = threadIdx.x;
    const int tx = tid & 15, ty = tid >> 4;
    const int m0 = blockIdx.x * 64;

    float acc[4][4];
#pragma unroll
    for (int r = 0; r < 4; ++r)
#pragma unroll
        for (int c = 0; c < 4; ++c) acc[r][c] = 0.f;

    for (int k0 = 0; k0 < DM; k0 += 16) {
        __syncthreads();
        {
            int m = tid >> 2, kq = tid & 3;        // 256 float4 of A tile
            *reinterpret_cast<float4*>(&As[m * 20 + kq * 4]) =
                *reinterpret_cast<const float4*>(&A[(size_t)(m0 + m) * DM + k0 + kq * 4]);
        }
        {
            int kr = tid >> 4, nq = tid & 15;      // 256 float4 of B tile
            *reinterpret_cast<float4*>(&Bs[kr * 64 + nq * 4]) =
                *reinterpret_cast<const float4*>(&B[(size_t)(k0 + kr) * 64 + nq * 4]);
        }
        __syncthreads();
#pragma unroll
        for (int kk = 0; kk < 16; ++kk) {
            float a[4], b[4];
#pragma unroll
            for (int r = 0; r < 4; ++r) a[r] = As[(ty * 4 + r) * 20 + kk];
#pragma unroll
            for (int c = 0; c < 4; ++c) b[c] = Bs[kk * 64 + tx * 4 + c];
#pragma unroll
            for (int r = 0; r < 4; ++r)
#pragma unroll
                for (int c = 0; c < 4; ++c) acc[r][c] = fmaf(a[r], b[c], acc[r][c]);
        }
    }
#pragma unroll
    for (int r = 0; r < 4; ++r)
        *reinterpret_cast<float4*>(&C[(size_t)(m0 + ty * 4 + r) * 64 + tx * 4]) =
            make_float4(acc[r][0], acc[r][1], acc[r][2], acc[r][3]);
}

// ---------------- RoPE + head-major permute + pre-scale ----------------
__global__ void rope_permute(const float* __restrict__ t0, const float* __restrict__ t1,
                             const float* __restrict__ fcos, const float* __restrict__ fsin)
{
    const int NQA = L_SEQ * NH * 32;   // qa pairs
    const int NQR = L_SEQ * NH * 32;   // qr pairs
    const int NKA = L_SEQ * 32;        // ka pairs
    int idx = blockIdx.x * blockDim.x + threadIdx.x;
    if (idx < NQA) {
        int p = idx & 31, h = (idx >> 5) & 15, i = idx >> 9;
        float xr = t0[(size_t)(i * NH + h) * HD + 2 * p];
        float xi = t0[(size_t)(i * NH + h) * HD + 2 * p + 1];
        float c = fcos[i * 32 + p], s = fsin[i * 32 + p];
        size_t o = ((size_t)h * L_SEQ + i) * HD + 2 * p;
        g_qa[o]     = (xr * c - xi * s) * RSCALE;
        g_qa[o + 1] = (xr * s + xi * c) * RSCALE;
    } else if (idx < NQA + NQR) {
        int k = idx - NQA;
        int p = k & 31, h = (k >> 5) & 15, i = k >> 9;
        float xr = t1[(size_t)(i * NH + h) * HD + 2 * p];
        float xi = t1[(size_t)(i * NH + h) * HD + 2 * p + 1];
        size_t o = ((size_t)h * L_SEQ + i) * HD + 2 * p;
        g_qr[o]     = xr * RSCALE;
        g_qr[o + 1] = xi * RSCALE;
    } else if (idx < NQA + NQR + NKA) {
        int k = idx - NQA - NQR;
        int p = k & 31, i = k >> 5;
        float xr = g_ka[i * HD + 2 * p];
        float xi = g_ka[i * HD + 2 * p + 1];
        float c = fcos[i * 32 + p], s = fsin[i * 32 + p];
        g_ka[i * HD + 2 * p]     = xr * c - xi * s;
        g_ka[i * HD + 2 * p + 1] = xr * s + xi * c;
    }
}

// ---------------- transpose k matrices to [d][j] for coalesced tile loads ----
__global__ void transpose_k()
{
    int idx = blockIdx.x * blockDim.x + threadIdx.x;
    const int NE = L_SEQ * HD;
    if (idx < NE) {
        int j = idx >> 6, d = idx & 63;
        g_kaT[d * L_SEQ + j] = g_ka[idx];
    } else if (idx < 2 * NE) {
        int k = idx - NE;
        int j = k >> 6, d = k & 63;
        g_krT[d * L_SEQ + j] = g_kr[k];
    }
}

// ---------------- micro gemm: acc[8][4] += A(128xK tile) @ B(64x64 tile) -----
__device__ __forceinline__ void micro_gemm(const float* __restrict__ Asm, int astride_f4,
                                           const float* __restrict__ Bsm,
                                           int ty, int tx, float acc[8][4])
{
#pragma unroll
    for (int k4 = 0; k4 < 16; ++k4) {
        float b[4][4];
#pragma unroll
        for (int q = 0; q < 4; ++q) {
            float4 bv = reinterpret_cast<const float4*>(Bsm)[(k4 * 4 + q) * 16 + tx];
            b[q][0] = bv.x; b[q][1] = bv.y; b[q][2] = bv.z; b[q][3] = bv.w;
        }
#pragma unroll
        for (int r = 0; r < 8; ++r) {
            float4 av = reinterpret_cast<const float4*>(Asm)[(ty * 8 + r) * astride_f4 + k4];
            float a[4] = {av.x, av.y, av.z, av.w};
#pragma unroll
            for (int q = 0; q < 4; ++q)
#pragma unroll
                for (int c = 0; c < 4; ++c)
                    acc[r][c] = fmaf(a[q], b[q][c], acc[r][c]);
        }
    }
}

// ---------------- fused attention: softmax(QKᵀ), rel, (P·R)V ----------------
// grid (16 i-blocks, 16 heads), 256 threads, BM=128, BN=64.
__global__ __launch_bounds__(256, 1) void attn_kernel(float* __restrict__ attn_out,
                                                      float* __restrict__ rel_out,
                                                      float* __restrict__ ao)
{
    extern __shared__ float sm[];
    float* qa_s = sm;              // [128][64]
    float* qr_s = sm + 8192;       // [128][64]
    float* kaT  = sm + 16384;      // [64][64]
    float* krT  = kaT + 4096;      // [64][64]
    float* v_s  = krT + 4096;      // [64][64]  ([j][d])
    float* pr_s = v_s + 4096;      // [128][68] (pad)

    const int h  = blockIdx.y;
    const int ib = blockIdx.x;
    const int i0 = ib * 128;
    const int tid = threadIdx.x;
    const int tx = tid & 15, ty = tid >> 4;

    const float* qab = g_qa + ((size_t)h * L_SEQ + i0) * HD;
    const float* qrb = g_qr + ((size_t)h * L_SEQ + i0) * HD;
#pragma unroll
    for (int it = 0; it < 8; ++it) {
        int idx = it * 256 + tid;  // 2048 float4
        reinterpret_cast<float4*>(qa_s)[idx] = reinterpret_cast<const float4*>(qab)[idx];
        reinterpret_cast<float4*>(qr_s)[idx] = reinterpret_cast<const float4*>(qrb)[idx];
    }

    float l[8];
#pragma unroll
    for (int r = 0; r < 8; ++r) l[r] = 0.f;
    const int jt_max = 2 * ib + 1;

    // -------- pass 1: row sums of exp(scores) over causal region --------
    for (int jt = 0; jt <= jt_max; ++jt) {
        __syncthreads();
#pragma unroll
        for (int it = 0; it < 4; ++it) {
            int idx = it * 256 + tid;            // 1024 float4
            int d = idx >> 4, jq = idx & 15;
            reinterpret_cast<float4*>(kaT)[d * 16 + jq] =
                *reinterpret_cast<const float4*>(&g_kaT[d * L_SEQ + jt * 64 + jq * 4]);
        }
        __syncthreads();
        float s[8][4];
#pragma unroll
        for (int r = 0; r < 8; ++r)
#pragma unroll
            for (int c = 0; c < 4; ++c) s[r][c] = 0.f;
        micro_gemm(qa_s, 16, kaT, ty, tx, s);

        if (jt <= 2 * ib - 1) {                  // fully unmasked tile
#pragma unroll
            for (int r = 0; r < 8; ++r)
#pragma unroll
                for (int c = 0; c < 4; ++c) l[r] += __expf(s[r][c]);
        } else {                                  // partial / diagonal tile
#pragma unroll
            for (int r = 0; r < 8; ++r) {
                int irow = i0 + ty * 8 + r;
#pragma unroll
                for (int c = 0; c < 4; ++c) {
                    int jcol = jt * 64 + tx * 4 + c;
                    if (jcol <= irow) l[r] += __expf(s[r][c]);
                }
            }
        }
    }
    // reduce row sums across the 16 tx threads, then invert
#pragma unroll
    for (int r = 0; r < 8; ++r) {
        l[r] += __shfl_xor_sync(0xffffffffu, l[r], 1);
        l[r] += __shfl_xor_sync(0xffffffffu, l[r], 2);
        l[r] += __shfl_xor_sync(0xffffffffu, l[r], 4);
        l[r] += __shfl_xor_sync(0xffffffffu, l[r], 8);
        l[r] = __fdividef(1.0f, l[r]);           // now 1/l
    }

    float o[8][4];
#pragma unroll
    for (int r = 0; r < 8; ++r)
#pragma unroll
        for (int c = 0; c < 4; ++c) o[r][c] = 0.f;

    float* attnp = attn_out + (size_t)h * L_SEQ * L_SEQ;
    float* relp  = rel_out  + (size_t)h * L_SEQ * L_SEQ;

    // -------- pass 2: rel everywhere; P, P·R, O on causal tiles --------
    for (int jt = 0; jt < 32; ++jt) {
        const bool causal = (jt <= jt_max);
        __syncthreads();
#pragma unroll
        for (int it = 0; it < 4; ++it) {
            int idx = it * 256 + tid;
            int d = idx >> 4, jq = idx & 15;
            reinterpret_cast<float4*>(krT)[d * 16 + jq] =
                *reinterpret_cast<const float4*>(&g_krT[d * L_SEQ + jt * 64 + jq * 4]);
        }
        if (causal) {
#pragma unroll
            for (int it = 0; it < 4; ++it) {
                int idx = it * 256 + tid;
                int d = idx >> 4, jq = idx & 15;
                reinterpret_cast<float4*>(kaT)[d * 16 + jq] =
                    *reinterpret_cast<const float4*>(&g_kaT[d * L_SEQ + jt * 64 + jq * 4]);
            }
#pragma unroll
            for (int it = 0; it < 4; ++it) {
                int idx = it * 256 + tid;
                int j = idx >> 4, dq = idx & 15;
                reinterpret_cast<float4*>(v_s)[j * 16 + dq] =
                    *reinterpret_cast<const float4*>(&g_v[(size_t)(jt * 64 + j) * 64 + dq * 4]);
            }
        }
        __syncthreads();

        float rr[8][4];
#pragma unroll
        for (int r = 0; r < 8; ++r)
#pragma unroll
            for (int c = 0; c < 4; ++c) rr[r][c] = 0.f;
        micro_gemm(qr_s, 16, krT, ty, tx, rr);

        // write rel tile
#pragma unroll
        for (int r = 0; r < 8; ++r) {
            size_t off = (size_t)(i0 + ty * 8 + r) * L_SEQ + jt * 64 + tx * 4;
            *reinterpret_cast<float4*>(&relp[off]) =
                make_float4(rr[r][0], rr[r][1], rr[r][2], rr[r][3]);
        }

        if (causal) {
            float s[8][4];
#pragma unroll
            for (int r = 0; r < 8; ++r)
#pragma unroll
                for (int c = 0; c < 4; ++c) s[r][c] = 0.f;
            micro_gemm(qa_s, 16, kaT, ty, tx, s);

            const bool needMask = (jt >= 2 * ib);
#pragma unroll
            for (int r = 0; r < 8; ++r) {
                int irow = i0 + ty * 8 + r;
#pragma unroll
                for (int c = 0; c < 4; ++c) {
                    float p = __expf(s[r][c]) * l[r];
                    if (needMask && (jt * 64 + tx * 4 + c > irow)) p = 0.f;
                    s[r][c] = p;
                }
            }
            // write attn tile
#pragma unroll
            for (int r = 0; r < 8; ++r) {
                size_t off = (size_t)(i0 + ty * 8 + r) * L_SEQ + jt * 64 + tx * 4;
                *reinterpret_cast<float4*>(&attnp[off]) =
                    make_float4(s[r][0], s[r][1], s[r][2], s[r][3]);
            }
            // stage P*R into smem
#pragma unroll
            for (int r = 0; r < 8; ++r) {
                *reinterpret_cast<float4*>(&pr_s[(ty * 8 + r) * 68 + tx * 4]) =
                    make_float4(s[r][0] * rr[r][0], s[r][1] * rr[r][1],
                                s[r][2] * rr[r][2], s[r][3] * rr[r][3]);
            }
            __syncthreads();
            micro_gemm(pr_s, 17, v_s, ty, tx, o);   // O += (P·R) @ V
        } else {
            float4 z = make_float4(0.f, 0.f, 0.f, 0.f);
#pragma unroll
            for (int r = 0; r < 8; ++r) {
                size_t off = (size_t)(i0 + ty * 8 + r) * L_SEQ + jt * 64 + tx * 4;
                *reinterpret_cast<float4*>(&attnp[off]) = z;
            }
        }
    }

    // store O block to g_ao[i][h*64+d]
#pragma unroll
    for (int r = 0; r < 8; ++r) {
        size_t off = (size_t)(i0 + ty * 8 + r) * DM + h * HD + tx * 4;
        *reinterpret_cast<float4*>(&ao[off]) =
            make_float4(o[r][0], o[r][1], o[r][2], o[r][3]);
    }
}

// ---------------------------------- launch ----------------------------------
extern "C" void kernel_launch(void* const* d_in, const int* in_sizes, int n_in,
                              void* d_out, int out_size)
{
    (void)in_sizes; (void)n_in; (void)out_size;
    const float* x    = (const float*)d_in[0];
    const float* sym  = (const float*)d_in[1];
    const float* fcos = (const float*)d_in[2];
    const float* fsin = (const float*)d_in[3];
    const float* wqa  = (const float*)d_in[4];
    const float* wka  = (const float*)d_in[5];
    const float* wqr  = (const float*)d_in[6];
    const float* wkr  = (const float*)d_in[7];
    const float* wv   = (const float*)d_in[8];
    const float* wo   = (const float*)d_in[9];

    float* out  = (float*)d_out;
    float* attn = out + (size_t)L_SEQ * DM;
    float* rel  = attn + (size_t)NH * L_SEQ * L_SEQ;

    void* p;
    cudaGetSymbolAddress(&p, g_t0); float* t0 = (float*)p;
    cudaGetSymbolAddress(&p, g_t1); float* t1 = (float*)p;
    cudaGetSymbolAddress(&p, g_ao); float* ao = (float*)p;

    dim3 blk(256);
    // big projections: xq_attn, xq_rel
    sgemm128<<<dim3(DM / 128, L_SEQ / 128), blk>>>(x, wqa, t0, L_SEQ, DM, DM);
    sgemm128<<<dim3(DM / 128, L_SEQ / 128), blk>>>(x, wqr, t1, L_SEQ, DM, DM);
    // small projections: ka, kr, v
    proj_small<<<dim3(L_SEQ / 64, 3), blk>>>(x, sym, wka, wkr, wv);
    // rope + permute + pre-scale
    {
        int total = L_SEQ * NH * 32 * 2 + L_SEQ * 32;
        rope_permute<<<(total + 255) / 256, 256>>>(t0, t1, fcos, fsin);
    }
    // transpose k tensors
    transpose_k<<<(2 * L_SEQ * HD + 255) / 256, 256>>>();
    // fused attention
    {
        size_t smem = 37376 * sizeof(float);   // 149,504 B
        cudaFuncSetAttribute(attn_kernel, cudaFuncAttributeMaxDynamicSharedMemorySize, (int)smem);
        attn_kernel<<<dim3(16, 16), blk, smem>>>(attn, rel, ao);
    }
    // output projection
    sgemm128<<<dim3(DM / 128, L_SEQ / 128), blk>>>(ao, wo, out, L_SEQ, DM, DM);
}

// round 2
// speedup vs baseline: 1.0788x; 1.0788x over previous
#include <cuda_runtime.h>
#include <cstdint>
#include <cstddef>

#define L_SEQ 2048
#define DM    1024
#define NH    16
#define HD    64
#define RSCALE 0.125f   // 1/sqrt(64)

// ---------------- scratch (device globals; no allocs allowed) ----------------
__device__ float g_t0[L_SEQ * DM];        // x @ wq_attn (pre-rope, [i][h*64+d])
__device__ float g_t1[L_SEQ * DM];        // x @ wq_rel
__device__ float g_qa[NH * L_SEQ * HD];   // rope'd + scaled, head-major [h][i][d]
__device__ float g_qr[NH * L_SEQ * HD];   // scaled, head-major
__device__ float g_ka[L_SEQ * HD];        // rope'd in place
__device__ float g_kr[L_SEQ * HD];
__device__ float g_v [L_SEQ * HD];
__device__ float g_kaT[HD * L_SEQ];       // [d][j]
__device__ float g_krT[HD * L_SEQ];
__device__ float g_ao[L_SEQ * DM];        // attention output pre-wo, [i][h*64+d]

// ---------------- generic fp32 SGEMM: C[M,N] = A[M,K] @ B[K,N] ----------------
// BM=128, BN=128, BK=16, 256 threads, 8x8 micro-tile.
__global__ __launch_bounds__(256) void sgemm128(const float* __restrict__ A,
                                                const float* __restrict__ B,
                                                float* __restrict__ C,
                                                int M, int N, int K)
{
    __shared__ float As[128 * 20];   // [m][k], stride 20 (pad)
    __shared__ float Bs[16 * 128];   // [k][n]
    const int tid = threadIdx.x;
    const int tx = tid & 15, ty = tid >> 4;
    const int m0 = blockIdx.y * 128;
    const int n0 = blockIdx.x * 128;

    float acc[8][8];
#pragma unroll
    for (int r = 0; r < 8; ++r)
#pragma unroll
        for (int c = 0; c < 8; ++c) acc[r][c] = 0.f;

    for (int k0 = 0; k0 < K; k0 += 16) {
        __syncthreads();
#pragma unroll
        for (int it = 0; it < 2; ++it) {
            int idx = it * 256 + tid;          // 512 float4 of A tile
            int m = idx >> 2, kq = idx & 3;
            float4 v = *reinterpret_cast<const float4*>(&A[(size_t)(m0 + m) * K + k0 + kq * 4]);
            *reinterpret_cast<float4*>(&As[m * 20 + kq * 4]) = v;
        }
#pragma unroll
        for (int it = 0; it < 2; ++it) {
            int idx = it * 256 + tid;          // 512 float4 of B tile
            int kr = idx >> 5, nq = idx & 31;
            float4 v = *reinterpret_cast<const float4*>(&B[(size_t)(k0 + kr) * N + n0 + nq * 4]);
            *reinterpret_cast<float4*>(&Bs[kr * 128 + nq * 4]) = v;
        }
        __syncthreads();
#pragma unroll
        for (int kk = 0; kk < 16; ++kk) {
            float a[8], b[8];
#pragma unroll
            for (int r = 0; r < 8; ++r) a[r] = As[(ty * 8 + r) * 20 + kk];
#pragma unroll
            for (int c = 0; c < 8; ++c) b[c] = Bs[kk * 128 + tx * 8 + c];
#pragma unroll
            for (int r = 0; r < 8; ++r)
#pragma unroll
                for (int c = 0; c < 8; ++c) acc[r][c] = fmaf(a[r], b[c], acc[r][c]);
        }
    }
#pragma unroll
    for (int r = 0; r < 8; ++r) {
        float4* p = reinterpret_cast<float4*>(&C[(size_t)(m0 + ty * 8 + r) * N + n0 + tx * 8]);
        p[0] = make_float4(acc[r][0], acc[r][1], acc[r][2], acc[r][3]);
        p[1] = make_float4(acc[r][4], acc[r][5], acc[r][6], acc[r][7]);
    }
}

// ---------------- small projections: ka, kr, v (N=64, K=1024) ----------------
__global__ __launch_bounds__(256) void proj_small(const float* __restrict__ x,
                                                  const float* __restrict__ sym,
                                                  const float* __restrict__ wka,
                                                  const float* __restrict__ wkr,
                                                  const float* __restrict__ wv)
{
    __shared__ float As[64 * 20];
    __shared__ float Bs[16 * 64];
    const int sel = blockIdx.y;                    // 0: ka, 1: kr, 2: v
    const float* A = (sel == 2) ? sym : x;
    const float* B = (sel == 0) ? wka : (sel == 1) ? wkr : wv;
    float* C = (sel == 0) ? g_ka : (sel == 1) ? g_kr : g_v;

    const int tid = threadIdx.x;
    const int tx = tid & 15, ty = tid >> 4;
    const int m0 = blockIdx.x * 64;

    float acc[4][4];
#pragma unroll
    for (int r = 0; r < 4; ++r)
#pragma unroll
        for (int c = 0; c < 4; ++c) acc[r][c] = 0.f;

    for (int k0 = 0; k0 < DM; k0 += 16) {
        __syncthreads();
        {
            int m = tid >> 2, kq = tid & 3;        // 256 float4 of A tile
            *reinterpret_cast<float4*>(&As[m * 20 + kq * 4]) =
                *reinterpret_cast<const float4*>(&A[(size_t)(m0 + m) * DM + k0 + kq * 4]);
        }
        {
            int kr = tid >> 4, nq = tid & 15;      // 256 float4 of B tile
            *reinterpret_cast<float4*>(&Bs[kr * 64 + nq * 4]) =
                *reinterpret_cast<const float4*>(&B[(size_t)(k0 + kr) * 64 + nq * 4]);
        }
        __syncthreads();
#pragma unroll
        for (int kk = 0; kk < 16; ++kk) {
            float a[4], b[4];
#pragma unroll
            for (int r = 0; r < 4; ++r) a[r] = As[(ty * 4 + r) * 20 + kk];
#pragma unroll
            for (int c = 0; c < 4; ++c) b[c] = Bs[kk * 64 + tx * 4 + c];
#pragma unroll
            for (int r = 0; r < 4; ++r)
#pragma unroll
                for (int c = 0; c < 4; ++c) acc[r][c] = fmaf(a[r], b[c], acc[r][c]);
        }
    }
#pragma unroll
    for (int r = 0; r < 4; ++r)
        *reinterpret_cast<float4*>(&C[(size_t)(m0 + ty * 4 + r) * 64 + tx * 4]) =
            make_float4(acc[r][0], acc[r][1], acc[r][2], acc[r][3]);
}

// ---------------- RoPE + head-major permute + pre-scale ----------------
__global__ void rope_permute(const float* __restrict__ t0, const float* __restrict__ t1,
                             const float* __restrict__ fcos, const float* __restrict__ fsin)
{
    const int NQA = L_SEQ * NH * 32;   // qa pairs
    const int NQR = L_SEQ * NH * 32;   // qr pairs
    const int NKA = L_SEQ * 32;        // ka pairs
    int idx = blockIdx.x * blockDim.x + threadIdx.x;
    if (idx < NQA) {
        int p = idx & 31, h = (idx >> 5) & 15, i = idx >> 9;
        float xr = t0[(size_t)(i * NH + h) * HD + 2 * p];
        float xi = t0[(size_t)(i * NH + h) * HD + 2 * p + 1];
        float c = fcos[i * 32 + p], s = fsin[i * 32 + p];
        size_t o = ((size_t)h * L_SEQ + i) * HD + 2 * p;
        g_qa[o]     = (xr * c - xi * s) * RSCALE;
        g_qa[o + 1] = (xr * s + xi * c) * RSCALE;
    } else if (idx < NQA + NQR) {
        int k = idx - NQA;
        int p = k & 31, h = (k >> 5) & 15, i = k >> 9;
        float xr = t1[(size_t)(i * NH + h) * HD + 2 * p];
        float xi = t1[(size_t)(i * NH + h) * HD + 2 * p + 1];
        size_t o = ((size_t)h * L_SEQ + i) * HD + 2 * p;
        g_qr[o]     = xr * RSCALE;
        g_qr[o + 1] = xi * RSCALE;
    } else if (idx < NQA + NQR + NKA) {
        int k = idx - NQA - NQR;
        int p = k & 31, i = k >> 5;
        float xr = g_ka[i * HD + 2 * p];
        float xi = g_ka[i * HD + 2 * p + 1];
        float c = fcos[i * 32 + p], s = fsin[i * 32 + p];
        g_ka[i * HD + 2 * p]     = xr * c - xi * s;
        g_ka[i * HD + 2 * p + 1] = xr * s + xi * c;
    }
}

// ---------------- transpose k matrices to [d][j] for coalesced tile loads ----
__global__ void transpose_k()
{
    int idx = blockIdx.x * blockDim.x + threadIdx.x;
    const int NE = L_SEQ * HD;
    if (idx < NE) {
        int j = idx >> 6, d = idx & 63;
        g_kaT[d * L_SEQ + j] = g_ka[idx];
    } else if (idx < 2 * NE) {
        int k = idx - NE;
        int j = k >> 6, d = k & 63;
        g_krT[d * L_SEQ + j] = g_kr[k];
    }
}

// ---------------- micro gemm: acc[8][4] += A(128xK tile) @ B(64x64 tile) -----
__device__ __forceinline__ void micro_gemm(const float* __restrict__ Asm, int astride_f4,
                                           const float* __restrict__ Bsm,
                                           int ty, int tx, float acc[8][4])
{
#pragma unroll
    for (int k4 = 0; k4 < 16; ++k4) {
        float b[4][4];
#pragma unroll
        for (int q = 0; q < 4; ++q) {
            float4 bv = reinterpret_cast<const float4*>(Bsm)[(k4 * 4 + q) * 16 + tx];
            b[q][0] = bv.x; b[q][1] = bv.y; b[q][2] = bv.z; b[q][3] = bv.w;
        }
#pragma unroll
        for (int r = 0; r < 8; ++r) {
            float4 av = reinterpret_cast<const float4*>(Asm)[(ty * 8 + r) * astride_f4 + k4];
            float a[4] = {av.x, av.y, av.z, av.w};
#pragma unroll
            for (int q = 0; q < 4; ++q)
#pragma unroll
                for (int c = 0; c < 4; ++c)
                    acc[r][c] = fmaf(a[q], b[q][c], acc[r][c]);
        }
    }
}

// ---------------- fused attention: softmax(QKᵀ), rel, (P·R)V ----------------
// grid (16 i-blocks, 16 heads), 256 threads, BM=128, BN=64.
__global__ __launch_bounds__(256, 1) void attn_kernel(float* __restrict__ attn_out,
                                                      float* __restrict__ rel_out,
                                                      float* __restrict__ ao)
{
    extern __shared__ float sm[];
    float* qa_s = sm;              // [128][64]
    float* qr_s = sm + 8192;       // [128][64]
    float* kaT  = sm + 16384;      // [64][64]
    float* krT  = kaT + 4096;      // [64][64]
    float* v_s  = krT + 4096;      // [64][64]  ([j][d])
    float* pr_s = v_s + 4096;      // [128][68] (pad)

    const int h  = blockIdx.y;
    const int ib = blockIdx.x;
    const int i0 = ib * 128;
    const int tid = threadIdx.x;
    const int tx = tid & 15, ty = tid >> 4;

    const float* qab = g_qa + ((size_t)h * L_SEQ + i0) * HD;
    const float* qrb = g_qr + ((size_t)h * L_SEQ + i0) * HD;
#pragma unroll
    for (int it = 0; it < 8; ++it) {
        int idx = it * 256 + tid;  // 2048 float4
        reinterpret_cast<float4*>(qa_s)[idx] = reinterpret_cast<const float4*>(qab)[idx];
        reinterpret_cast<float4*>(qr_s)[idx] = reinterpret_cast<const float4*>(qrb)[idx];
    }

    float l[8];
#pragma unroll
    for (int r = 0; r < 8; ++r) l[r] = 0.f;
    const int jt_max = 2 * ib + 1;

    // -------- pass 1: row sums of exp(scores) over causal region --------
    for (int jt = 0; jt <= jt_max; ++jt) {
        __syncthreads();
#pragma unroll
        for (int it = 0; it < 4; ++it) {
            int idx = it * 256 + tid;            // 1024 float4
            int d = idx >> 4, jq = idx & 15;
            reinterpret_cast<float4*>(kaT)[d * 16 + jq] =
                *reinterpret_cast<const float4*>(&g_kaT[d * L_SEQ + jt * 64 + jq * 4]);
        }
        __syncthreads();
        float s[8][4];
#pragma unroll
        for (int r = 0; r < 8; ++r)
#pragma unroll
            for (int c = 0; c < 4; ++c) s[r][c] = 0.f;
        micro_gemm(qa_s, 16, kaT, ty, tx, s);

        if (jt <= 2 * ib - 1) {                  // fully unmasked tile
#pragma unroll
            for (int r = 0; r < 8; ++r)
#pragma unroll
                for (int c = 0; c < 4; ++c) l[r] += __expf(s[r][c]);
        } else {                                  // partial / diagonal tile
#pragma unroll
            for (int r = 0; r < 8; ++r) {
                int irow = i0 + ty * 8 + r;
#pragma unroll
                for (int c = 0; c < 4; ++c) {
                    int jcol = jt * 64 + tx * 4 + c;
                    if (jcol <= irow) l[r] += __expf(s[r][c]);
                }
            }
        }
    }
    // reduce row sums across the 16 tx threads, then invert
#pragma unroll
    for (int r = 0; r < 8; ++r) {
        l[r] += __shfl_xor_sync(0xffffffffu, l[r], 1);
        l[r] += __shfl_xor_sync(0xffffffffu, l[r], 2);
        l[r] += __shfl_xor_sync(0xffffffffu, l[r], 4);
        l[r] += __shfl_xor_sync(0xffffffffu, l[r], 8);
        l[r] = __fdividef(1.0f, l[r]);           // now 1/l
    }

    float o[8][4];
#pragma unroll
    for (int r = 0; r < 8; ++r)
#pragma unroll
        for (int c = 0; c < 4; ++c) o[r][c] = 0.f;

    float* attnp = attn_out + (size_t)h * L_SEQ * L_SEQ;
    float* relp  = rel_out  + (size_t)h * L_SEQ * L_SEQ;

    // -------- pass 2: rel everywhere; P, P·R, O on causal tiles --------
    for (int jt = 0; jt < 32; ++jt) {
        const bool causal = (jt <= jt_max);
        __syncthreads();
#pragma unroll
        for (int it = 0; it < 4; ++it) {
            int idx = it * 256 + tid;
            int d = idx >> 4, jq = idx & 15;
            reinterpret_cast<float4*>(krT)[d * 16 + jq] =
                *reinterpret_cast<const float4*>(&g_krT[d * L_SEQ + jt * 64 + jq * 4]);
        }
        if (causal) {
#pragma unroll
            for (int it = 0; it < 4; ++it) {
                int idx = it * 256 + tid;
                int d = idx >> 4, jq = idx & 15;
                reinterpret_cast<float4*>(kaT)[d * 16 + jq] =
                    *reinterpret_cast<const float4*>(&g_kaT[d * L_SEQ + jt * 64 + jq * 4]);
            }
#pragma unroll
            for (int it = 0; it < 4; ++it) {
                int idx = it * 256 + tid;
                int j = idx >> 4, dq = idx & 15;
                reinterpret_cast<float4*>(v_s)[j * 16 + dq] =
                    *reinterpret_cast<const float4*>(&g_v[(size_t)(jt * 64 + j) * 64 + dq * 4]);
            }
        }
        __syncthreads();

        float rr[8][4];
#pragma unroll
        for (int r = 0; r < 8; ++r)
#pragma unroll
            for (int c = 0; c < 4; ++c) rr[r][c] = 0.f;
        micro_gemm(qr_s, 16, krT, ty, tx, rr);

        // write rel tile
#pragma unroll
        for (int r = 0; r < 8; ++r) {
            size_t off = (size_t)(i0 + ty * 8 + r) * L_SEQ + jt * 64 + tx * 4;
            *reinterpret_cast<float4*>(&relp[off]) =
                make_float4(rr[r][0], rr[r][1], rr[r][2], rr[r][3]);
        }

        if (causal) {
            float s[8][4];
#pragma unroll
            for (int r = 0; r < 8; ++r)
#pragma unroll
                for (int c = 0; c < 4; ++c) s[r][c] = 0.f;
            micro_gemm(qa_s, 16, kaT, ty, tx, s);

            const bool needMask = (jt >= 2 * ib);
#pragma unroll
            for (int r = 0; r < 8; ++r) {
                int irow = i0 + ty * 8 + r;
#pragma unroll
                for (int c = 0; c < 4; ++c) {
                    float p = __expf(s[r][c]) * l[r];
                    if (needMask && (jt * 64 + tx * 4 + c > irow)) p = 0.f;
                    s[r][c] = p;
                }
            }
            // write attn tile
#pragma unroll
            for (int r = 0; r < 8; ++r) {
                size_t off = (size_t)(i0 + ty * 8 + r) * L_SEQ + jt * 64 + tx * 4;
                *reinterpret_cast<float4*>(&attnp[off]) =
                    make_float4(s[r][0], s[r][1], s[r][2], s[r][3]);
            }
            // stage P*R into smem
#pragma unroll
            for (int r = 0; r < 8; ++r) {
                *reinterpret_cast<float4*>(&pr_s[(ty * 8 + r) * 68 + tx * 4]) =
                    make_float4(s[r][0] * rr[r][0], s[r][1] * rr[r][1],
                                s[r][2] * rr[r][2], s[r][3] * rr[r][3]);
            }
            __syncthreads();
            micro_gemm(pr_s, 17, v_s, ty, tx, o);   // O += (P·R) @ V
        } else {
            float4 z = make_float4(0.f, 0.f, 0.f, 0.f);
#pragma unroll
            for (int r = 0; r < 8; ++r) {
                size_t off = (size_t)(i0 + ty * 8 + r) * L_SEQ + jt * 64 + tx * 4;
                *reinterpret_cast<float4*>(&attnp[off]) = z;
            }
        }
    }

    // store O block to g_ao[i][h*64+d]
#pragma unroll
    for (int r = 0; r < 8; ++r) {
        size_t off = (size_t)(i0 + ty * 8 + r) * DM + h * HD + tx * 4;
        *reinterpret_cast<float4*>(&ao[off]) =
            make_float4(o[r][0], o[r][1], o[r][2], o[r][3]);
    }
}

// ---------------------------------- launch ----------------------------------
extern "C" void kernel_launch(void* const* d_in, const int* in_sizes, int n_in,
                              void* d_out, int out_size)
{
    (void)in_sizes; (void)n_in; (void)out_size;
    const float* x    = (const float*)d_in[0];
    const float* sym  = (const float*)d_in[1];
    const float* fcos = (const float*)d_in[2];
    const float* fsin = (const float*)d_in[3];
    const float* wqa  = (const float*)d_in[4];
    const float* wka  = (const float*)d_in[5];
    const float* wqr  = (const float*)d_in[6];
    const float* wkr  = (const float*)d_in[7];
    const float* wv   = (const float*)d_in[8];
    const float* wo   = (const float*)d_in[9];

    float* out  = (float*)d_out;
    float* attn = out + (size_t)L_SEQ * DM;
    float* rel  = attn + (size_t)NH * L_SEQ * L_SEQ;

    void* p;
    cudaGetSymbolAddress(&p, g_t0); float* t0 = (float*)p;
    cudaGetSymbolAddress(&p, g_t1); float* t1 = (float*)p;
    cudaGetSymbolAddress(&p, g_ao); float* ao = (float*)p;

    dim3 blk(256);
    // big projections: xq_attn, xq_rel
    sgemm128<<<dim3(DM / 128, L_SEQ / 128), blk>>>(x, wqa, t0, L_SEQ, DM, DM);
    sgemm128<<<dim3(DM / 128, L_SEQ / 128), blk>>>(x, wqr, t1, L_SEQ, DM, DM);
    // small projections: ka, kr, v
    proj_small<<<dim3(L_SEQ / 64, 3), blk>>>(x, sym, wka, wkr, wv);
    // rope + permute + pre-scale
    {
        int total = L_SEQ * NH * 32 * 2 + L_SEQ * 32;
        rope_permute<<<(total + 255) / 256, 256>>>(t0, t1, fcos, fsin);
    }
    // transpose k tensors
    transpose_k<<<(2 * L_SEQ * HD + 255) / 256, 256>>>();
    // fused attention
    {
        size_t smem = 37376 * sizeof(float);   // 149,504 B
        cudaFuncSetAttribute(attn_kernel, cudaFuncAttributeMaxDynamicSharedMemorySize, (int)smem);
        attn_kernel<<<dim3(16, 16), blk, smem>>>(attn, rel, ao);
    }
    // output projection
    sgemm128<<<dim3(DM / 128, L_SEQ / 128), blk>>>(ao, wo, out, L_SEQ, DM, DM);
}

// round 3
// speedup vs baseline: 2.2814x; 2.1148x over previous
#include <cuda_runtime.h>
#include <cuda_bf16.h>
#include <cstdint>
#include <cstddef>

#define L_SEQ 2048
#define DM    1024
#define NH    16
#define HD    64
#define RSCALE 0.125f
typedef __nv_bfloat16 bf16;
typedef unsigned int u32;

// ---------------- scratch (device globals; no allocs allowed) ----------------
__device__ bf16 g_xh[L_SEQ*DM],  g_xl[L_SEQ*DM];
__device__ bf16 g_sh[L_SEQ*DM],  g_sl[L_SEQ*DM];
__device__ bf16 g_wqah[DM*DM], g_wqal[DM*DM];
__device__ bf16 g_wqrh[DM*DM], g_wqrl[DM*DM];
__device__ bf16 g_woh [DM*DM], g_wol [DM*DM];
__device__ bf16 g_wkah[HD*DM], g_wkal[HD*DM];
__device__ bf16 g_wkrh[HD*DM], g_wkrl[HD*DM];
__device__ bf16 g_wvh [HD*DM], g_wvl [HD*DM];
__device__ float g_t0[L_SEQ*DM], g_t1[L_SEQ*DM];
__device__ float g_kaf[L_SEQ*HD], g_krf[L_SEQ*HD], g_vf[L_SEQ*HD];
__device__ bf16 g_qah[NH*L_SEQ*HD], g_qal[NH*L_SEQ*HD];
__device__ bf16 g_qrh[NH*L_SEQ*HD], g_qrl[NH*L_SEQ*HD];
__device__ bf16 g_kah[L_SEQ*HD], g_kal[L_SEQ*HD];
__device__ bf16 g_krh[L_SEQ*HD], g_krl[L_SEQ*HD];
__device__ bf16 g_vth[HD*L_SEQ], g_vtl[HD*L_SEQ];
__device__ bf16 g_aoh[L_SEQ*DM], g_aol[L_SEQ*DM];

// ---------------- helpers ----------------
__device__ __forceinline__ void split2(float v, bf16& hi, bf16& lo) {
    hi = __float2bfloat16(v);
    lo = __float2bfloat16(v - __bfloat162float(hi));
}

__device__ __forceinline__ void packsplit(float a, float b, u32& ph, u32& pl) {
    float ah = __bfloat162float(__float2bfloat16(a));
    float bh = __bfloat162float(__float2bfloat16(b));
    __nv_bfloat162 hv = __floats2bfloat162_rn(ah, bh);
    __nv_bfloat162 lv = __floats2bfloat162_rn(a - ah, b - bh);
    ph = *reinterpret_cast<u32*>(&hv);
    pl = *reinterpret_cast<u32*>(&lv);
}

__device__ __forceinline__ void ldsm4(u32 addr, u32& r0, u32& r1, u32& r2, u32& r3) {
    asm volatile("ldmatrix.sync.aligned.m8n8.x4.shared.b16 {%0,%1,%2,%3}, [%4];"
                 : "=r"(r0), "=r"(r1), "=r"(r2), "=r"(r3) : "r"(addr));
}

__device__ __forceinline__ void hmma(float* c, u32 a0, u32 a1, u32 a2, u32 a3,
                                     u32 b0, u32 b1) {
    asm volatile("mma.sync.aligned.m16n8k16.row.col.f32.bf16.bf16.f32 "
                 "{%0,%1,%2,%3},{%4,%5,%6,%7},{%8,%9},{%0,%1,%2,%3};"
                 : "+f"(c[0]), "+f"(c[1]), "+f"(c[2]), "+f"(c[3])
                 : "r"(a0), "r"(a1), "r"(a2), "r"(a3), "r"(b0), "r"(b1));
}

// A-frag addr (m16k16 at (m0,k0) in row-major smem, ldb = row stride BYTES)
__device__ __forceinline__ u32 addrA(u32 base, int ldb, int m0, int k0, int lane) {
    int g = lane & 7, grp = lane >> 3;
    return base + (u32)((m0 + g + (grp & 1) * 8) * ldb + (k0 + (grp >> 1) * 8) * 2);
}
// B-frag addr (n16k16 at (n0,k0) in row-major [n][k] smem)
__device__ __forceinline__ u32 addrB(u32 base, int ldb, int n0, int k0, int lane) {
    int g = lane & 7, grp = lane >> 3;
    return base + (u32)((n0 + g + (grp >> 1) * 8) * ldb + (k0 + (grp & 1) * 8) * 2);
}

// ---------------- input split ----------------
__global__ void split_in(const float* __restrict__ x, const float* __restrict__ s) {
    int i = blockIdx.x * 256 + threadIdx.x;
    if (i < L_SEQ * DM) {
        split2(x[i], g_xh[i], g_xl[i]);
    } else {
        int k = i - L_SEQ * DM;
        if (k < L_SEQ * DM) split2(s[k], g_sh[k], g_sl[k]);
    }
}

// ---------------- weight transpose + split: src [K=1024][N] -> dst planes [N][1024]
__global__ void tsplit_big(const float* __restrict__ w0, const float* __restrict__ w1,
                           const float* __restrict__ w2) {
    __shared__ float t[32][33];
    int z = blockIdx.z;
    const float* src = (z == 0) ? w0 : (z == 1) ? w1 : w2;
    bf16* dh = (z == 0) ? g_wqah : (z == 1) ? g_wqrh : g_woh;
    bf16* dl = (z == 0) ? g_wqal : (z == 1) ? g_wqrl : g_wol;
    int k0 = blockIdx.x * 32, n0 = blockIdx.y * 32;
    int tx = threadIdx.x & 31, ty0 = threadIdx.x >> 5;
#pragma unroll
    for (int q = 0; q < 4; ++q) {
        int ty = ty0 * 4 + q;
        t[ty][tx] = src[(size_t)(k0 + ty) * DM + n0 + tx];
    }
    __syncthreads();
#pragma unroll
    for (int q = 0; q < 4; ++q) {
        int ty = ty0 * 4 + q;
        bf16 hh, ll; split2(t[tx][ty], hh, ll);
        size_t o = (size_t)(n0 + ty) * DM + k0 + tx;
        dh[o] = hh; dl[o] = ll;
    }
}

__global__ void tsplit_small(const float* __restrict__ w0, const float* __restrict__ w1,
                             const float* __restrict__ w2) {
    __shared__ float t[32][33];
    int z = blockIdx.z;
    const float* src = (z == 0) ? w0 : (z == 1) ? w1 : w2;
    bf16* dh = (z == 0) ? g_wkah : (z == 1) ? g_wkrh : g_wvh;
    bf16* dl = (z == 0) ? g_wkal : (z == 1) ? g_wkrl : g_wvl;
    int k0 = blockIdx.x * 32, n0 = blockIdx.y * 32;
    int tx = threadIdx.x & 31, ty0 = threadIdx.x >> 5;
#pragma unroll
    for (int q = 0; q < 4; ++q) {
        int ty = ty0 * 4 + q;
        t[ty][tx] = src[(size_t)(k0 + ty) * HD + n0 + tx];
    }
    __syncthreads();
#pragma unroll
    for (int q = 0; q < 4; ++q) {
        int ty = ty0 * 4 + q;
        bf16 hh, ll; split2(t[tx][ty], hh, ll);
        size_t o = (size_t)(n0 + ty) * DM + k0 + tx;
        dh[o] = hh; dl[o] = ll;
    }
}

// ---------------- split-bf16 GEMM: C[*,N] fp32 = A[2048,1024] @ B^T (B planes [n][1024])
// BM=128, BN=64, BK=32, 256 threads (8 warps: 4 wm x 2 wn).
__global__ __launch_bounds__(256, 2) void gemm_split(const bf16* __restrict__ Ah,
                                                     const bf16* __restrict__ Al,
                                                     const bf16* __restrict__ Bh,
                                                     const bf16* __restrict__ Bl,
                                                     float* __restrict__ C, int N) {
    __shared__ bf16 sA[2 * 128 * 40];
    __shared__ bf16 sB[2 * 64 * 40];
    const int tid = threadIdx.x, lane = tid & 31, warp = tid >> 5;
    const int wm = warp & 3, wn = warp >> 2;
    const int m0 = blockIdx.y * 128, n0 = blockIdx.x * 64;

    float acc[2][4][4];
#pragma unroll
    for (int m2 = 0; m2 < 2; ++m2)
#pragma unroll
        for (int o = 0; o < 4; ++o)
#pragma unroll
            for (int k = 0; k < 4; ++k) acc[m2][o][k] = 0.f;

    u32 ua = (u32)__cvta_generic_to_shared(sA);
    u32 ub = (u32)__cvta_generic_to_shared(sB);

    for (int k0 = 0; k0 < DM; k0 += 32) {
        __syncthreads();
#pragma unroll
        for (int it = 0; it < 4; ++it) {
            int idx = it * 256 + tid;
            int pl = idx >> 9, rem = idx & 511, r = rem >> 2, s = rem & 3;
            const bf16* src = pl ? Al : Ah;
            *(uint4*)&sA[pl * 128 * 40 + r * 40 + s * 8] =
                *(const uint4*)&src[(size_t)(m0 + r) * DM + k0 + s * 8];
        }
#pragma unroll
        for (int it = 0; it < 2; ++it) {
            int idx = it * 256 + tid;
            int pl = idx >> 8, rem = idx & 255, r = rem >> 2, s = rem & 3;
            const bf16* src = pl ? Bl : Bh;
            *(uint4*)&sB[pl * 64 * 40 + r * 40 + s * 8] =
                *(const uint4*)&src[(size_t)(n0 + r) * DM + k0 + s * 8];
        }
        __syncthreads();
#pragma unroll
        for (int ks = 0; ks < 2; ++ks) {
            int kk = ks * 16;
            u32 ah[2][4], al[2][4], bh[2][4], bl[2][4];
#pragma unroll
            for (int m2 = 0; m2 < 2; ++m2) {
                ldsm4(addrA(ua, 80, wm * 32 + m2 * 16, kk, lane),
                      ah[m2][0], ah[m2][1], ah[m2][2], ah[m2][3]);
                ldsm4(addrA(ua + 128 * 80, 80, wm * 32 + m2 * 16, kk, lane),
                      al[m2][0], al[m2][1], al[m2][2], al[m2][3]);
            }
#pragma unroll
            for (int q = 0; q < 2; ++q) {
                ldsm4(addrB(ub, 80, wn * 32 + q * 16, kk, lane),
                      bh[q][0], bh[q][1], bh[q][2], bh[q][3]);
                ldsm4(addrB(ub + 64 * 80, 80, wn * 32 + q * 16, kk, lane),
                      bl[q][0], bl[q][1], bl[q][2], bl[q][3]);
            }
#pragma unroll
            for (int m2 = 0; m2 < 2; ++m2)
#pragma unroll
                for (int o = 0; o < 4; ++o) {
                    int q = o >> 1, pp = (o & 1) * 2;
                    hmma(acc[m2][o], ah[m2][0], ah[m2][1], ah[m2][2], ah[m2][3],
                         bh[q][pp], bh[q][pp + 1]);
                    hmma(acc[m2][o], ah[m2][0], ah[m2][1], ah[m2][2], ah[m2][3],
                         bl[q][pp], bl[q][pp + 1]);
                    hmma(acc[m2][o], al[m2][0], al[m2][1], al[m2][2], al[m2][3],
                         bh[q][pp], bh[q][pp + 1]);
                }
        }
    }
    const int g = lane >> 2, t = lane & 3;
#pragma unroll
    for (int m2 = 0; m2 < 2; ++m2)
#pragma unroll
        for (int o = 0; o < 4; ++o) {
            int row = m0 + wm * 32 + m2 * 16 + g;
            int col = n0 + wn * 32 + o * 8 + 2 * t;
            *(float2*)&C[(size_t)row * N + col] = make_float2(acc[m2][o][0], acc[m2][o][1]);
            *(float2*)&C[(size_t)(row + 8) * N + col] = make_float2(acc[m2][o][2], acc[m2][o][3]);
        }
}

// ---------------- rope + permute + split ----------------
__global__ void rope_split(const float* __restrict__ fcos, const float* __restrict__ fsin) {
    const int NQ = L_SEQ * NH * 32;
    int idx = blockIdx.x * 256 + threadIdx.x;
    if (idx < NQ) {
        int p = idx & 31, hq = (idx >> 5) & 15, i = idx >> 9;
        float xr = g_t0[(size_t)i * DM + hq * 64 + 2 * p];
        float xi = g_t0[(size_t)i * DM + hq * 64 + 2 * p + 1];
        float c = fcos[i * 32 + p], s = fsin[i * 32 + p];
        float o0 = (xr * c - xi * s) * RSCALE, o1 = (xr * s + xi * c) * RSCALE;
        size_t o = ((size_t)hq * L_SEQ + i) * HD + 2 * p;
        split2(o0, g_qah[o], g_qal[o]);
        split2(o1, g_qah[o + 1], g_qal[o + 1]);
    } else if (idx < 2 * NQ) {
        int k = idx - NQ;
        int p = k & 31, hq = (k >> 5) & 15, i = k >> 9;
        float xr = g_t1[(size_t)i * DM + hq * 64 + 2 * p] * RSCALE;
        float xi = g_t1[(size_t)i * DM + hq * 64 + 2 * p + 1] * RSCALE;
        size_t o = ((size_t)hq * L_SEQ + i) * HD + 2 * p;
        split2(xr, g_qrh[o], g_qrl[o]);
        split2(xi, g_qrh[o + 1], g_qrl[o + 1]);
    } else if (idx < 2 * NQ + 65536) {
        int k = idx - 2 * NQ;
        int p = k & 31, i = k >> 5;
        float xr = g_kaf[i * HD + 2 * p], xi = g_kaf[i * HD + 2 * p + 1];
        float c = fcos[i * 32 + p], s = fsin[i * 32 + p];
        split2(xr * c - xi * s, g_kah[i * HD + 2 * p], g_kal[i * HD + 2 * p]);
        split2(xr * s + xi * c, g_kah[i * HD + 2 * p + 1], g_kal[i * HD + 2 * p + 1]);
    } else if (idx < 2 * NQ + 131072) {
        int k = idx - 2 * NQ - 65536;
        int p = k & 31, i = k >> 5;
        split2(g_krf[i * HD + 2 * p], g_krh[i * HD + 2 * p], g_krl[i * HD + 2 * p]);
        split2(g_krf[i * HD + 2 * p + 1], g_krh[i * HD + 2 * p + 1], g_krl[i * HD + 2 * p + 1]);
    } else if (idx < 2 * NQ + 262144) {
        int k = idx - 2 * NQ - 131072;
        int j = k & (L_SEQ - 1), d = k >> 11;
        split2(g_vf[(size_t)j * HD + d], g_vth[(size_t)d * L_SEQ + j], g_vtl[(size_t)d * L_SEQ + j]);
    }
}

// ---------------- fused attention ----------------
// cs/cr accumulate a 128x64 tile per jt; warp layout 4 wm x 2 wn; each warp 32 rows x 32 cols.
__device__ __forceinline__ void mma_qk(u32 aH, u32 aL, u32 bH, u32 bL,
                                       int wm, int wn, int lane, float cs[2][4][4]) {
#pragma unroll
    for (int ks = 0; ks < 4; ++ks) {
        int k0 = ks * 16;
        u32 ah[2][4], al[2][4], bh[2][4], bl[2][4];
#pragma unroll
        for (int m2 = 0; m2 < 2; ++m2) {
            ldsm4(addrA(aH, 144, wm * 32 + m2 * 16, k0, lane),
                  ah[m2][0], ah[m2][1], ah[m2][2], ah[m2][3]);
            ldsm4(addrA(aL, 144, wm * 32 + m2 * 16, k0, lane),
                  al[m2][0], al[m2][1], al[m2][2], al[m2][3]);
        }
#pragma unroll
        for (int q = 0; q < 2; ++q) {
            ldsm4(addrB(bH, 144, wn * 32 + q * 16, k0, lane),
                  bh[q][0], bh[q][1], bh[q][2], bh[q][3]);
            ldsm4(addrB(bL, 144, wn * 32 + q * 16, k0, lane),
                  bl[q][0], bl[q][1], bl[q][2], bl[q][3]);
        }
#pragma unroll
        for (int m2 = 0; m2 < 2; ++m2)
#pragma unroll
            for (int o = 0; o < 4; ++o) {
                int q = o >> 1, pp = (o & 1) * 2;
                hmma(cs[m2][o], ah[m2][0], ah[m2][1], ah[m2][2], ah[m2][3],
                     bh[q][pp], bh[q][pp + 1]);
                hmma(cs[m2][o], ah[m2][0], ah[m2][1], ah[m2][2], ah[m2][3],
                     bl[q][pp], bl[q][pp + 1]);
                hmma(cs[m2][o], al[m2][0], al[m2][1], al[m2][2], al[m2][3],
                     bh[q][pp], bh[q][pp + 1]);
            }
    }
}

__device__ __forceinline__ void stage_frag(float* stage, float c[2][4][4],
                                           int wm, int wn, int g, int t) {
#pragma unroll
    for (int m2 = 0; m2 < 2; ++m2)
#pragma unroll
        for (int o = 0; o < 4; ++o) {
            int row = wm * 32 + m2 * 16 + g;
            int col = wn * 32 + o * 8 + 2 * t;
            *(float2*)&stage[row * 68 + col] = make_float2(c[m2][o][0], c[m2][o][1]);
            *(float2*)&stage[(row + 8) * 68 + col] = make_float2(c[m2][o][2], c[m2][o][3]);
        }
}

__device__ __forceinline__ void copy_stage(const float* stage, float* dst,
                                           int i0, int jt, int tid) {
#pragma unroll
    for (int it = 0; it < 8; ++it) {
        int idx = it * 256 + tid;
        int r = idx >> 4, s = idx & 15;
        *(float4*)&dst[(size_t)(i0 + r) * L_SEQ + jt * 64 + s * 4] =
            *(const float4*)&stage[r * 68 + s * 4];
    }
}

__global__ __launch_bounds__(256, 1) void attn_mma(float* __restrict__ attn_out,
                                                   float* __restrict__ rel_out) {
    extern __shared__ char smraw[];
    bf16* sb = (bf16*)smraw;
    bf16 *qa_h = sb,          *qa_l = sb + 9216;
    bf16 *qr_h = sb + 18432,  *qr_l = sb + 27648;
    bf16 *ka_h = sb + 36864,  *ka_l = sb + 41472;
    bf16 *kr_h = sb + 46080,  *kr_l = sb + 50688;
    bf16 *vt_h = sb + 55296,  *vt_l = sb + 59904;
    float* stage = (float*)(sb + 64512);
    float* lsum  = stage + 128 * 68;
    float* linv  = lsum + 256;

    const int hq = blockIdx.y;
    const int ib = 15 - blockIdx.x;          // heavy blocks first
    const int i0 = ib * 128;
    const int tid = threadIdx.x, lane = tid & 31, warp = tid >> 5;
    const int wm = warp & 3, wn = warp >> 2;
    const int g = lane >> 2, t = lane & 3;
    const int jtmax = 2 * ib + 1;

    // load Q tiles (4 planes)
    {
        const bf16* srcs[4] = {g_qah + ((size_t)hq * L_SEQ + i0) * HD,
                               g_qal + ((size_t)hq * L_SEQ + i0) * HD,
                               g_qrh + ((size_t)hq * L_SEQ + i0) * HD,
                               g_qrl + ((size_t)hq * L_SEQ + i0) * HD};
        bf16* dsts[4] = {qa_h, qa_l, qr_h, qr_l};
#pragma unroll
        for (int a = 0; a < 4; ++a)
#pragma unroll
            for (int it = 0; it < 4; ++it) {
                int idx = it * 256 + tid;
                int r = idx >> 3, s = idx & 7;
                *(uint4*)&dsts[a][r * 72 + s * 8] =
                    *(const uint4*)&srcs[a][(size_t)r * HD + s * 8];
            }
    }
    u32 uqa_h = (u32)__cvta_generic_to_shared(qa_h);
    u32 uqa_l = (u32)__cvta_generic_to_shared(qa_l);
    u32 uqr_h = (u32)__cvta_generic_to_shared(qr_h);
    u32 uqr_l = (u32)__cvta_generic_to_shared(qr_l);
    u32 uka_h = (u32)__cvta_generic_to_shared(ka_h);
    u32 uka_l = (u32)__cvta_generic_to_shared(ka_l);
    u32 ukr_h = (u32)__cvta_generic_to_shared(kr_h);
    u32 ukr_l = (u32)__cvta_generic_to_shared(kr_l);
    u32 uvt_h = (u32)__cvta_generic_to_shared(vt_h);
    u32 uvt_l = (u32)__cvta_generic_to_shared(vt_l);

    // -------- pass 1: causal row sums of exp(scores) --------
    float esum[2][2] = {{0.f, 0.f}, {0.f, 0.f}};
    for (int jt = 0; jt <= jtmax; ++jt) {
        __syncthreads();
#pragma unroll
        for (int it = 0; it < 4; ++it) {
            int idx = it * 256 + tid;
            int pl = idx >> 9, rem = idx & 511, r = rem >> 3, s = rem & 7;
            bf16* d = pl ? ka_l : ka_h;
            const bf16* sc = pl ? g_kal : g_kah;
            *(uint4*)&d[r * 72 + s * 8] = *(const uint4*)&sc[(size_t)(jt * 64 + r) * HD + s * 8];
        }
        __syncthreads();
        float cs[2][4][4];
#pragma unroll
        for (int m2 = 0; m2 < 2; ++m2)
#pragma unroll
            for (int o = 0; o < 4; ++o)
#pragma unroll
                for (int k = 0; k < 4; ++k) cs[m2][o][k] = 0.f;
        mma_qk(uqa_h, uqa_l, uka_h, uka_l, wm, wn, lane, cs);

        if (jt < 2 * ib) {
#pragma unroll
            for (int m2 = 0; m2 < 2; ++m2)
#pragma unroll
                for (int o = 0; o < 4; ++o) {
                    esum[m2][0] += __expf(cs[m2][o][0]) + __expf(cs[m2][o][1]);
                    esum[m2][1] += __expf(cs[m2][o][2]) + __expf(cs[m2][o][3]);
                }
        } else {
#pragma unroll
            for (int m2 = 0; m2 < 2; ++m2)
#pragma unroll
                for (int o = 0; o < 4; ++o) {
                    int r0 = i0 + wm * 32 + m2 * 16 + g;
                    int cb = jt * 64 + wn * 32 + o * 8 + 2 * t;
                    if (cb     <= r0)     esum[m2][0] += __expf(cs[m2][o][0]);
                    if (cb + 1 <= r0)     esum[m2][0] += __expf(cs[m2][o][1]);
                    if (cb     <= r0 + 8) esum[m2][1] += __expf(cs[m2][o][2]);
                    if (cb + 1 <= r0 + 8) esum[m2][1] += __expf(cs[m2][o][3]);
                }
        }
    }
#pragma unroll
    for (int m2 = 0; m2 < 2; ++m2)
#pragma unroll
        for (int hf = 0; hf < 2; ++hf) {
            float v = esum[m2][hf];
            v += __shfl_xor_sync(0xffffffffu, v, 1);
            v += __shfl_xor_sync(0xffffffffu, v, 2);
            esum[m2][hf] = v;
        }
    __syncthreads();
    if (t == 0) {
#pragma unroll
        for (int m2 = 0; m2 < 2; ++m2) {
            lsum[wn * 128 + wm * 32 + m2 * 16 + g] = esum[m2][0];
            lsum[wn * 128 + wm * 32 + m2 * 16 + g + 8] = esum[m2][1];
        }
    }
    __syncthreads();
    if (tid < 128) linv[tid] = __fdividef(1.f, lsum[tid] + lsum[128 + tid]);
    __syncthreads();
    float li[2][2];
#pragma unroll
    for (int m2 = 0; m2 < 2; ++m2) {
        li[m2][0] = linv[wm * 32 + m2 * 16 + g];
        li[m2][1] = linv[wm * 32 + m2 * 16 + g + 8];
    }

    float co[2][8][4];
#pragma unroll
    for (int m2 = 0; m2 < 2; ++m2)
#pragma unroll
        for (int o = 0; o < 8; ++o)
#pragma unroll
            for (int k = 0; k < 4; ++k) co[m2][o][k] = 0.f;

    float* attnp = attn_out + (size_t)hq * L_SEQ * L_SEQ;
    float* relp  = rel_out  + (size_t)hq * L_SEQ * L_SEQ;

    // -------- pass 2 --------
    for (int jt = 0; jt < 32; ++jt) {
        const bool causal = (jt <= jtmax);
        __syncthreads();
#pragma unroll
        for (int it = 0; it < 4; ++it) {
            int idx = it * 256 + tid;
            int pl = idx >> 9, rem = idx & 511, r = rem >> 3, s = rem & 7;
            bf16* d = pl ? kr_l : kr_h;
            const bf16* sc = pl ? g_krl : g_krh;
            *(uint4*)&d[r * 72 + s * 8] = *(const uint4*)&sc[(size_t)(jt * 64 + r) * HD + s * 8];
        }
        if (causal) {
#pragma unroll
            for (int it = 0; it < 4; ++it) {
                int idx = it * 256 + tid;
                int pl = idx >> 9, rem = idx & 511, r = rem >> 3, s = rem & 7;
                bf16* d = pl ? ka_l : ka_h;
                const bf16* sc = pl ? g_kal : g_kah;
                *(uint4*)&d[r * 72 + s * 8] = *(const uint4*)&sc[(size_t)(jt * 64 + r) * HD + s * 8];
            }
#pragma unroll
            for (int it = 0; it < 4; ++it) {
                int idx = it * 256 + tid;
                int pl = idx >> 9, rem = idx & 511, r = rem >> 3, s = rem & 7;
                bf16* d = pl ? vt_l : vt_h;
                const bf16* sc = pl ? g_vtl : g_vth;
                *(uint4*)&d[r * 72 + s * 8] = *(const uint4*)&sc[(size_t)r * L_SEQ + jt * 64 + s * 8];
            }
        }
        __syncthreads();

        float cr[2][4][4];
#pragma unroll
        for (int m2 = 0; m2 < 2; ++m2)
#pragma unroll
            for (int o = 0; o < 4; ++o)
#pragma unroll
                for (int k = 0; k < 4; ++k) cr[m2][o][k] = 0.f;
        mma_qk(uqr_h, uqr_l, ukr_h, ukr_l, wm, wn, lane, cr);

        if (!causal) {
            stage_frag(stage, cr, wm, wn, g, t);
            __syncthreads();
            copy_stage(stage, relp, i0, jt, tid);
            float4 z = make_float4(0.f, 0.f, 0.f, 0.f);
#pragma unroll
            for (int it = 0; it < 8; ++it) {
                int idx = it * 256 + tid;
                int r = idx >> 4, s = idx & 15;
                *(float4*)&attnp[(size_t)(i0 + r) * L_SEQ + jt * 64 + s * 4] = z;
            }
            continue;
        }

        float csq[2][4][4];
#pragma unroll
        for (int m2 = 0; m2 < 2; ++m2)
#pragma unroll
            for (int o = 0; o < 4; ++o)
#pragma unroll
                for (int k = 0; k < 4; ++k) csq[m2][o][k] = 0.f;
        mma_qk(uqa_h, uqa_l, uka_h, uka_l, wm, wn, lane, csq);

        stage_frag(stage, cr, wm, wn, g, t);
        __syncthreads();
        copy_stage(stage, relp, i0, jt, tid);

        const bool dia = (jt >= 2 * ib);
#pragma unroll
        for (int m2 = 0; m2 < 2; ++m2)
#pragma unroll
            for (int o = 0; o < 4; ++o) {
                int r0 = i0 + wm * 32 + m2 * 16 + g;
                int cb = jt * 64 + wn * 32 + o * 8 + 2 * t;
                float p0 = __expf(csq[m2][o][0]) * li[m2][0];
                float p1 = __expf(csq[m2][o][1]) * li[m2][0];
                float p2 = __expf(csq[m2][o][2]) * li[m2][1];
                float p3 = __expf(csq[m2][o][3]) * li[m2][1];
                if (dia) {
                    if (cb     > r0)     p0 = 0.f;
                    if (cb + 1 > r0)     p1 = 0.f;
                    if (cb     > r0 + 8) p2 = 0.f;
                    if (cb + 1 > r0 + 8) p3 = 0.f;
                }
                csq[m2][o][0] = p0; csq[m2][o][1] = p1;
                csq[m2][o][2] = p2; csq[m2][o][3] = p3;
            }
        __syncthreads();                       // rel copy done before stage reuse
        stage_frag(stage, csq, wm, wn, g, t);
        __syncthreads();
        copy_stage(stage, attnp, i0, jt, tid);

        // PV: O += (P.R) @ V, k = warp's 32 j-cols
#pragma unroll
        for (int b = 0; b < 2; ++b) {
            u32 vh[4][4], vl[4][4];
#pragma unroll
            for (int q2 = 0; q2 < 4; ++q2) {
                ldsm4(addrB(uvt_h, 144, q2 * 16, wn * 32 + b * 16, lane),
                      vh[q2][0], vh[q2][1], vh[q2][2], vh[q2][3]);
                ldsm4(addrB(uvt_l, 144, q2 * 16, wn * 32 + b * 16, lane),
                      vl[q2][0], vl[q2][1], vl[q2][2], vl[q2][3]);
            }
#pragma unroll
            for (int m2 = 0; m2 < 2; ++m2) {
                float pr[8];
#pragma unroll
                for (int k = 0; k < 4; ++k) {
                    pr[k]     = csq[m2][2 * b][k]     * cr[m2][2 * b][k];
                    pr[4 + k] = csq[m2][2 * b + 1][k] * cr[m2][2 * b + 1][k];
                }
                u32 aH[4], aL[4];
                packsplit(pr[0], pr[1], aH[0], aL[0]);
                packsplit(pr[2], pr[3], aH[1], aL[1]);
                packsplit(pr[4], pr[5], aH[2], aL[2]);
                packsplit(pr[6], pr[7], aH[3], aL[3]);
#pragma unroll
                for (int q2 = 0; q2 < 4; ++q2)
#pragma unroll
                    for (int sub = 0; sub < 2; ++sub) {
                        int o = q2 * 2 + sub, pp = sub * 2;
                        hmma(co[m2][o], aH[0], aH[1], aH[2], aH[3],
                             vh[q2][pp], vh[q2][pp + 1]);
                        hmma(co[m2][o], aH[0], aH[1], aH[2], aH[3],
                             vl[q2][pp], vl[q2][pp + 1]);
                        hmma(co[m2][o], aL[0], aL[1], aL[2], aL[3],
                             vh[q2][pp], vh[q2][pp + 1]);
                    }
            }
        }
    }

    // -------- O reduction across wn and split-store --------
    __syncthreads();
    if (wn == 0) {
#pragma unroll
        for (int m2 = 0; m2 < 2; ++m2)
#pragma unroll
            for (int o = 0; o < 8; ++o) {
                int row = wm * 32 + m2 * 16 + g;
                int col = o * 8 + 2 * t;
                *(float2*)&stage[row * 68 + col] = make_float2(co[m2][o][0], co[m2][o][1]);
                *(float2*)&stage[(row + 8) * 68 + col] = make_float2(co[m2][o][2], co[m2][o][3]);
            }
    }
    __syncthreads();
    if (wn == 1) {
#pragma unroll
        for (int m2 = 0; m2 < 2; ++m2)
#pragma unroll
            for (int o = 0; o < 8; ++o) {
                int row = wm * 32 + m2 * 16 + g;
                int col = o * 8 + 2 * t;
                stage[row * 68 + col]           += co[m2][o][0];
                stage[row * 68 + col + 1]       += co[m2][o][1];
                stage[(row + 8) * 68 + col]     += co[m2][o][2];
                stage[(row + 8) * 68 + col + 1] += co[m2][o][3];
            }
    }
    __syncthreads();
#pragma unroll
    for (int it = 0; it < 32; ++it) {
        int idx = it * 256 + tid;
        int r = idx >> 6, d = idx & 63;
        float v = stage[r * 68 + d];
        bf16 hh, ll; split2(v, hh, ll);
        size_t off = (size_t)(i0 + r) * DM + hq * 64 + d;
        g_aoh[off] = hh; g_aol[off] = ll;
    }
}

// ---------------------------------- launch ----------------------------------
extern "C" void kernel_launch(void* const* d_in, const int* in_sizes, int n_in,
                              void* d_out, int out_size) {
    (void)in_sizes; (void)n_in; (void)out_size;
    const float* x    = (const float*)d_in[0];
    const float* sym  = (const float*)d_in[1];
    const float* fcos = (const float*)d_in[2];
    const float* fsin = (const float*)d_in[3];
    const float* wqa  = (const float*)d_in[4];
    const float* wka  = (const float*)d_in[5];
    const float* wqr  = (const float*)d_in[6];
    const float* wkr  = (const float*)d_in[7];
    const float* wv   = (const float*)d_in[8];
    const float* wo   = (const float*)d_in[9];

    float* out  = (float*)d_out;
    float* attn = out + (size_t)L_SEQ * DM;
    float* rel  = attn + (size_t)NH * L_SEQ * L_SEQ;

    void* p;
#define GS(var, sym_) cudaGetSymbolAddress(&p, sym_); bf16* var = (bf16*)p;
#define GF(var, sym_) cudaGetSymbolAddress(&p, sym_); float* var = (float*)p;
    GS(xh, g_xh)   GS(xl, g_xl)   GS(sh_, g_sh)  GS(sl_, g_sl)
    GS(wqah, g_wqah) GS(wqal, g_wqal) GS(wqrh, g_wqrh) GS(wqrl, g_wqrl)
    GS(woh, g_woh)   GS(wol, g_wol)
    GS(wkah, g_wkah) GS(wkal, g_wkal) GS(wkrh, g_wkrh) GS(wkrl, g_wkrl)
    GS(wvh, g_wvh)   GS(wvl, g_wvl)
    GS(aoh, g_aoh)   GS(aol, g_aol)
    GF(t0, g_t0) GF(t1, g_t1) GF(kaf, g_kaf) GF(krf, g_krf) GF(vf, g_vf)
#undef GS
#undef GF

    split_in<<<(2 * L_SEQ * DM) / 256, 256>>>(x, sym);
    tsplit_big<<<dim3(32, 32, 3), 256>>>(wqa, wqr, wo);
    tsplit_small<<<dim3(32, 2, 3), 256>>>(wka, wkr, wv);

    gemm_split<<<dim3(16, 16), 256>>>(xh, xl, wqah, wqal, t0, DM);
    gemm_split<<<dim3(16, 16), 256>>>(xh, xl, wqrh, wqrl, t1, DM);
    gemm_split<<<dim3(1, 16), 256>>>(xh, xl, wkah, wkal, kaf, HD);
    gemm_split<<<dim3(1, 16), 256>>>(xh, xl, wkrh, wkrl, krf, HD);
    gemm_split<<<dim3(1, 16), 256>>>(sh_, sl_, wvh, wvl, vf, HD);

    {
        int total = 2 * L_SEQ * NH * 32 + 262144;
        rope_split<<<(total + 255) / 256, 256>>>(fcos, fsin);
    }
    {
        size_t smem = 165376;
        cudaFuncSetAttribute(attn_mma, cudaFuncAttributeMaxDynamicSharedMemorySize, (int)smem);
        attn_mma<<<dim3(16, 16), 256, smem>>>(attn, rel);
    }
    gemm_split<<<dim3(16, 16), 256>>>(aoh, aol, woh, wol, out, DM);
}

// round 4
// speedup vs baseline: 2.9042x; 1.2730x over previous
#include <cuda_runtime.h>
#include <cuda_bf16.h>
#include <cstdint>
#include <cstddef>

#define L_SEQ 2048
#define DM    1024
#define NH    16
#define HD    64
#define RSCALE 0.125f
typedef __nv_bfloat16 bf16;
typedef unsigned int u32;

// ---------------- scratch ----------------
__device__ bf16 g_xh[L_SEQ*DM],  g_xl[L_SEQ*DM];
__device__ bf16 g_sh[L_SEQ*DM],  g_sl[L_SEQ*DM];
__device__ bf16 g_wqah[DM*DM], g_wqal[DM*DM];
__device__ bf16 g_wqrh[DM*DM], g_wqrl[DM*DM];
__device__ bf16 g_woh [DM*DM], g_wol [DM*DM];
__device__ bf16 g_wkah[HD*DM], g_wkal[HD*DM];
__device__ bf16 g_wkrh[HD*DM], g_wkrl[HD*DM];
__device__ bf16 g_wvh [HD*DM], g_wvl [HD*DM];
__device__ float g_t0[L_SEQ*DM], g_t1[L_SEQ*DM];
__device__ float g_kaf[L_SEQ*HD], g_krf[L_SEQ*HD], g_vf[L_SEQ*HD];
__device__ bf16 g_qah[NH*L_SEQ*HD], g_qal[NH*L_SEQ*HD];
__device__ bf16 g_qrh[NH*L_SEQ*HD], g_qrl[NH*L_SEQ*HD];
__device__ bf16 g_kah[L_SEQ*HD], g_kal[L_SEQ*HD];
__device__ bf16 g_krh[L_SEQ*HD], g_krl[L_SEQ*HD];
__device__ bf16 g_vth[HD*L_SEQ], g_vtl[HD*L_SEQ];
__device__ bf16 g_aoh[L_SEQ*DM], g_aol[L_SEQ*DM];

// ---------------- helpers ----------------
__device__ __forceinline__ void split2(float v, bf16& hi, bf16& lo) {
    hi = __float2bfloat16(v);
    lo = __float2bfloat16(v - __bfloat162float(hi));
}
__device__ __forceinline__ void packsplit(float a, float b, u32& ph, u32& pl) {
    float ah = __bfloat162float(__float2bfloat16(a));
    float bh = __bfloat162float(__float2bfloat16(b));
    __nv_bfloat162 hv = __floats2bfloat162_rn(ah, bh);
    __nv_bfloat162 lv = __floats2bfloat162_rn(a - ah, b - bh);
    ph = *reinterpret_cast<u32*>(&hv);
    pl = *reinterpret_cast<u32*>(&lv);
}
__device__ __forceinline__ void ldsm4(u32 addr, u32& r0, u32& r1, u32& r2, u32& r3) {
    asm volatile("ldmatrix.sync.aligned.m8n8.x4.shared.b16 {%0,%1,%2,%3}, [%4];"
                 : "=r"(r0), "=r"(r1), "=r"(r2), "=r"(r3) : "r"(addr));
}
__device__ __forceinline__ void hmma(float* c, u32 a0, u32 a1, u32 a2, u32 a3,
                                     u32 b0, u32 b1) {
    asm volatile("mma.sync.aligned.m16n8k16.row.col.f32.bf16.bf16.f32 "
                 "{%0,%1,%2,%3},{%4,%5,%6,%7},{%8,%9},{%0,%1,%2,%3};"
                 : "+f"(c[0]), "+f"(c[1]), "+f"(c[2]), "+f"(c[3])
                 : "r"(a0), "r"(a1), "r"(a2), "r"(a3), "r"(b0), "r"(b1));
}
__device__ __forceinline__ u32 addrA(u32 base, int ldb, int m0, int k0, int lane) {
    int g = lane & 7, grp = lane >> 3;
    return base + (u32)((m0 + g + (grp & 1) * 8) * ldb + (k0 + (grp >> 1) * 8) * 2);
}
__device__ __forceinline__ u32 addrB(u32 base, int ldb, int n0, int k0, int lane) {
    int g = lane & 7, grp = lane >> 3;
    return base + (u32)((n0 + g + (grp >> 1) * 8) * ldb + (k0 + (grp & 1) * 8) * 2);
}
__device__ __forceinline__ void cpasync16(u32 dst, const void* src) {
    asm volatile("cp.async.cg.shared.global [%0], [%1], 16;" :: "r"(dst), "l"(src));
}
__device__ __forceinline__ void cpcommit() { asm volatile("cp.async.commit_group;"); }
__device__ __forceinline__ void cpwait0() { asm volatile("cp.async.wait_group 0;"); }
__device__ __forceinline__ void cpwait1() { asm volatile("cp.async.wait_group 1;"); }

// ---------------- input split ----------------
__global__ void split_in(const float* __restrict__ x, const float* __restrict__ s) {
    int i = blockIdx.x * 256 + threadIdx.x;
    if (i < L_SEQ * DM) {
        split2(x[i], g_xh[i], g_xl[i]);
    } else {
        int k = i - L_SEQ * DM;
        if (k < L_SEQ * DM) split2(s[k], g_sh[k], g_sl[k]);
    }
}

// ---------------- weight transpose + split ----------------
__global__ void tsplit_big(const float* __restrict__ w0, const float* __restrict__ w1,
                           const float* __restrict__ w2) {
    __shared__ float t[32][33];
    int z = blockIdx.z;
    const float* src = (z == 0) ? w0 : (z == 1) ? w1 : w2;
    bf16* dh = (z == 0) ? g_wqah : (z == 1) ? g_wqrh : g_woh;
    bf16* dl = (z == 0) ? g_wqal : (z == 1) ? g_wqrl : g_wol;
    int k0 = blockIdx.x * 32, n0 = blockIdx.y * 32;
    int tx = threadIdx.x & 31, ty0 = threadIdx.x >> 5;
#pragma unroll
    for (int q = 0; q < 4; ++q) {
        int ty = ty0 * 4 + q;
        t[ty][tx] = src[(size_t)(k0 + ty) * DM + n0 + tx];
    }
    __syncthreads();
#pragma unroll
    for (int q = 0; q < 4; ++q) {
        int ty = ty0 * 4 + q;
        bf16 hh, ll; split2(t[tx][ty], hh, ll);
        size_t o = (size_t)(n0 + ty) * DM + k0 + tx;
        dh[o] = hh; dl[o] = ll;
    }
}
__global__ void tsplit_small(const float* __restrict__ w0, const float* __restrict__ w1,
                             const float* __restrict__ w2) {
    __shared__ float t[32][33];
    int z = blockIdx.z;
    const float* src = (z == 0) ? w0 : (z == 1) ? w1 : w2;
    bf16* dh = (z == 0) ? g_wkah : (z == 1) ? g_wkrh : g_wvh;
    bf16* dl = (z == 0) ? g_wkal : (z == 1) ? g_wkrl : g_wvl;
    int k0 = blockIdx.x * 32, n0 = blockIdx.y * 32;
    int tx = threadIdx.x & 31, ty0 = threadIdx.x >> 5;
#pragma unroll
    for (int q = 0; q < 4; ++q) {
        int ty = ty0 * 4 + q;
        t[ty][tx] = src[(size_t)(k0 + ty) * HD + n0 + tx];
    }
    __syncthreads();
#pragma unroll
    for (int q = 0; q < 4; ++q) {
        int ty = ty0 * 4 + q;
        bf16 hh, ll; split2(t[tx][ty], hh, ll);
        size_t o = (size_t)(n0 + ty) * DM + k0 + tx;
        dh[o] = hh; dl[o] = ll;
    }
}

// ---------------- big GEMM: cp.async double-buffered, BM=128 BN=64 BK=32 ----------------
__global__ __launch_bounds__(256, 2) void gemm_big(const bf16* __restrict__ Ah,
                                                   const bf16* __restrict__ Al,
                                                   const bf16* __restrict__ Bh,
                                                   const bf16* __restrict__ Bl,
                                                   float* __restrict__ C, int N) {
    extern __shared__ bf16 dsm[];
    const int tid = threadIdx.x, lane = tid & 31, warp = tid >> 5;
    const int wm = warp & 3, wn = warp >> 2;
    const int m0 = blockIdx.y * 128, n0 = blockIdx.x * 64;
    u32 ua = (u32)__cvta_generic_to_shared(dsm);     // A: 2 st x 2 pl x 128x40
    u32 ub = ua + 40960u;                            // B: 2 st x 2 pl x 64x40

    float acc[2][4][4];
#pragma unroll
    for (int m2 = 0; m2 < 2; ++m2)
#pragma unroll
        for (int o = 0; o < 4; ++o)
#pragma unroll
            for (int k = 0; k < 4; ++k) acc[m2][o][k] = 0.f;

    auto issue = [&](int k0, int st) {
#pragma unroll
        for (int it = 0; it < 4; ++it) {
            int idx = it * 256 + tid;
            int pl = idx >> 9, rem = idx & 511, r = rem >> 2, s = rem & 3;
            const bf16* src = pl ? Al : Ah;
            cpasync16(ua + (u32)(st * 2 + pl) * 10240u + r * 80 + s * 16,
                      src + (size_t)(m0 + r) * DM + k0 + s * 8);
        }
#pragma unroll
        for (int it = 0; it < 2; ++it) {
            int idx = it * 256 + tid;
            int pl = idx >> 8, rem = idx & 255, r = rem >> 2, s = rem & 3;
            const bf16* src = pl ? Bl : Bh;
            cpasync16(ub + (u32)(st * 2 + pl) * 5120u + r * 80 + s * 16,
                      src + (size_t)(n0 + r) * DM + k0 + s * 8);
        }
        cpcommit();
    };

    issue(0, 0);
    const int NK = DM / 32;
    for (int kt = 0; kt < NK; ++kt) {
        if (kt + 1 < NK) { issue((kt + 1) * 32, (kt + 1) & 1); cpwait1(); }
        else cpwait0();
        __syncthreads();
        int st = kt & 1;
        u32 aH = ua + (u32)(st * 2) * 10240u, aL = aH + 10240u;
        u32 bH = ub + (u32)(st * 2) * 5120u,  bL = bH + 5120u;
#pragma unroll
        for (int ks = 0; ks < 2; ++ks) {
            int kk = ks * 16;
            u32 ah[2][4], al[2][4], bh[2][4], bl[2][4];
#pragma unroll
            for (int m2 = 0; m2 < 2; ++m2) {
                ldsm4(addrA(aH, 80, wm * 32 + m2 * 16, kk, lane),
                      ah[m2][0], ah[m2][1], ah[m2][2], ah[m2][3]);
                ldsm4(addrA(aL, 80, wm * 32 + m2 * 16, kk, lane),
                      al[m2][0], al[m2][1], al[m2][2], al[m2][3]);
            }
#pragma unroll
            for (int q = 0; q < 2; ++q) {
                ldsm4(addrB(bH, 80, wn * 32 + q * 16, kk, lane),
                      bh[q][0], bh[q][1], bh[q][2], bh[q][3]);
                ldsm4(addrB(bL, 80, wn * 32 + q * 16, kk, lane),
                      bl[q][0], bl[q][1], bl[q][2], bl[q][3]);
            }
#pragma unroll
            for (int m2 = 0; m2 < 2; ++m2)
#pragma unroll
                for (int o = 0; o < 4; ++o) {
                    int q = o >> 1, pp = (o & 1) * 2;
                    hmma(acc[m2][o], ah[m2][0], ah[m2][1], ah[m2][2], ah[m2][3],
                         bh[q][pp], bh[q][pp + 1]);
                    hmma(acc[m2][o], ah[m2][0], ah[m2][1], ah[m2][2], ah[m2][3],
                         bl[q][pp], bl[q][pp + 1]);
                    hmma(acc[m2][o], al[m2][0], al[m2][1], al[m2][2], al[m2][3],
                         bh[q][pp], bh[q][pp + 1]);
                }
        }
        __syncthreads();
    }
    const int g = lane >> 2, t = lane & 3;
#pragma unroll
    for (int m2 = 0; m2 < 2; ++m2)
#pragma unroll
        for (int o = 0; o < 4; ++o) {
            int row = m0 + wm * 32 + m2 * 16 + g;
            int col = n0 + wn * 32 + o * 8 + 2 * t;
            *(float2*)&C[(size_t)row * N + col] = make_float2(acc[m2][o][0], acc[m2][o][1]);
            *(float2*)&C[(size_t)(row + 8) * N + col] = make_float2(acc[m2][o][2], acc[m2][o][3]);
        }
}

// ---------------- 3 small projections fused: BM=64, grid (32,3) ----------------
__global__ __launch_bounds__(256, 2) void proj3() {
    __shared__ bf16 sA[2 * 2 * 64 * 40];
    __shared__ bf16 sB[2 * 2 * 64 * 40];
    const int z = blockIdx.y;
    const bf16* Ah = (z == 2) ? g_sh : g_xh;
    const bf16* Al = (z == 2) ? g_sl : g_xl;
    const bf16* Bh = (z == 0) ? g_wkah : (z == 1) ? g_wkrh : g_wvh;
    const bf16* Bl = (z == 0) ? g_wkal : (z == 1) ? g_wkrl : g_wvl;
    float* C = (z == 0) ? g_kaf : (z == 1) ? g_krf : g_vf;

    const int tid = threadIdx.x, lane = tid & 31, warp = tid >> 5;
    const int wm = warp & 3, wn = warp >> 2;
    const int m0 = blockIdx.x * 64;
    u32 ua = (u32)__cvta_generic_to_shared(sA);
    u32 ub = (u32)__cvta_generic_to_shared(sB);

    float acc[4][4];
#pragma unroll
    for (int o = 0; o < 4; ++o)
#pragma unroll
        for (int k = 0; k < 4; ++k) acc[o][k] = 0.f;

    auto issue = [&](int k0, int st) {
#pragma unroll
        for (int it = 0; it < 2; ++it) {
            int idx = it * 256 + tid;
            int pl = idx >> 8, rem = idx & 255, r = rem >> 2, s = rem & 3;
            const bf16* src = pl ? Al : Ah;
            cpasync16(ua + (u32)(st * 2 + pl) * 5120u + r * 80 + s * 16,
                      src + (size_t)(m0 + r) * DM + k0 + s * 8);
        }
#pragma unroll
        for (int it = 0; it < 2; ++it) {
            int idx = it * 256 + tid;
            int pl = idx >> 8, rem = idx & 255, r = rem >> 2, s = rem & 3;
            const bf16* src = pl ? Bl : Bh;
            cpasync16(ub + (u32)(st * 2 + pl) * 5120u + r * 80 + s * 16,
                      src + (size_t)r * DM + k0 + s * 8);
        }
        cpcommit();
    };

    issue(0, 0);
    const int NK = DM / 32;
    for (int kt = 0; kt < NK; ++kt) {
        if (kt + 1 < NK) { issue((kt + 1) * 32, (kt + 1) & 1); cpwait1(); }
        else cpwait0();
        __syncthreads();
        int st = kt & 1;
        u32 aH = ua + (u32)(st * 2) * 5120u, aL = aH + 5120u;
        u32 bH = ub + (u32)(st * 2) * 5120u, bL = bH + 5120u;
#pragma unroll
        for (int ks = 0; ks < 2; ++ks) {
            int kk = ks * 16;
            u32 ah[4], al[4], bh[2][4], bl[2][4];
            ldsm4(addrA(aH, 80, wm * 16, kk, lane), ah[0], ah[1], ah[2], ah[3]);
            ldsm4(addrA(aL, 80, wm * 16, kk, lane), al[0], al[1], al[2], al[3]);
#pragma unroll
            for (int q = 0; q < 2; ++q) {
                ldsm4(addrB(bH, 80, wn * 32 + q * 16, kk, lane),
                      bh[q][0], bh[q][1], bh[q][2], bh[q][3]);
                ldsm4(addrB(bL, 80, wn * 32 + q * 16, kk, lane),
                      bl[q][0], bl[q][1], bl[q][2], bl[q][3]);
            }
#pragma unroll
            for (int o = 0; o < 4; ++o) {
                int q = o >> 1, pp = (o & 1) * 2;
                hmma(acc[o], ah[0], ah[1], ah[2], ah[3], bh[q][pp], bh[q][pp + 1]);
                hmma(acc[o], ah[0], ah[1], ah[2], ah[3], bl[q][pp], bl[q][pp + 1]);
                hmma(acc[o], al[0], al[1], al[2], al[3], bh[q][pp], bh[q][pp + 1]);
            }
        }
        __syncthreads();
    }
    const int g = lane >> 2, t = lane & 3;
#pragma unroll
    for (int o = 0; o < 4; ++o) {
        int row = m0 + wm * 16 + g;
        int col = wn * 32 + o * 8 + 2 * t;
        *(float2*)&C[(size_t)row * HD + col] = make_float2(acc[o][0], acc[o][1]);
        *(float2*)&C[(size_t)(row + 8) * HD + col] = make_float2(acc[o][2], acc[o][3]);
    }
}

// ---------------- rope + permute + split ----------------
__global__ void rope_split(const float* __restrict__ fcos, const float* __restrict__ fsin) {
    const int NQ = L_SEQ * NH * 32;
    int idx = blockIdx.x * 256 + threadIdx.x;
    if (idx < NQ) {
        int p = idx & 31, hq = (idx >> 5) & 15, i = idx >> 9;
        float xr = g_t0[(size_t)i * DM + hq * 64 + 2 * p];
        float xi = g_t0[(size_t)i * DM + hq * 64 + 2 * p + 1];
        float c = fcos[i * 32 + p], s = fsin[i * 32 + p];
        float o0 = (xr * c - xi * s) * RSCALE, o1 = (xr * s + xi * c) * RSCALE;
        size_t o = ((size_t)hq * L_SEQ + i) * HD + 2 * p;
        split2(o0, g_qah[o], g_qal[o]);
        split2(o1, g_qah[o + 1], g_qal[o + 1]);
    } else if (idx < 2 * NQ) {
        int k = idx - NQ;
        int p = k & 31, hq = (k >> 5) & 15, i = k >> 9;
        float xr = g_t1[(size_t)i * DM + hq * 64 + 2 * p] * RSCALE;
        float xi = g_t1[(size_t)i * DM + hq * 64 + 2 * p + 1] * RSCALE;
        size_t o = ((size_t)hq * L_SEQ + i) * HD + 2 * p;
        split2(xr, g_qrh[o], g_qrl[o]);
        split2(xi, g_qrh[o + 1], g_qrl[o + 1]);
    } else if (idx < 2 * NQ + 65536) {
        int k = idx - 2 * NQ;
        int p = k & 31, i = k >> 5;
        float xr = g_kaf[i * HD + 2 * p], xi = g_kaf[i * HD + 2 * p + 1];
        float c = fcos[i * 32 + p], s = fsin[i * 32 + p];
        split2(xr * c - xi * s, g_kah[i * HD + 2 * p], g_kal[i * HD + 2 * p]);
        split2(xr * s + xi * c, g_kah[i * HD + 2 * p + 1], g_kal[i * HD + 2 * p + 1]);
    } else if (idx < 2 * NQ + 131072) {
        int k = idx - 2 * NQ - 65536;
        int p = k & 31, i = k >> 5;
        split2(g_krf[i * HD + 2 * p], g_krh[i * HD + 2 * p], g_krl[i * HD + 2 * p]);
        split2(g_krf[i * HD + 2 * p + 1], g_krh[i * HD + 2 * p + 1], g_krl[i * HD + 2 * p + 1]);
    } else if (idx < 2 * NQ + 262144) {
        int k = idx - 2 * NQ - 131072;
        int j = k & (L_SEQ - 1), d = k >> 11;
        split2(g_vf[(size_t)j * HD + d], g_vth[(size_t)d * L_SEQ + j], g_vtl[(size_t)d * L_SEQ + j]);
    }
}

// ---------------- attention ----------------
__device__ __forceinline__ void mma_qk(u32 aH, u32 aL, u32 bH, u32 bL,
                                       int wm, int wn, int lane, float cs[2][4][4]) {
#pragma unroll
    for (int ks = 0; ks < 4; ++ks) {
        int k0 = ks * 16;
        u32 ah[2][4], al[2][4], bh[2][4], bl[2][4];
#pragma unroll
        for (int m2 = 0; m2 < 2; ++m2) {
            ldsm4(addrA(aH, 144, wm * 32 + m2 * 16, k0, lane),
                  ah[m2][0], ah[m2][1], ah[m2][2], ah[m2][3]);
            ldsm4(addrA(aL, 144, wm * 32 + m2 * 16, k0, lane),
                  al[m2][0], al[m2][1], al[m2][2], al[m2][3]);
        }
#pragma unroll
        for (int q = 0; q < 2; ++q) {
            ldsm4(addrB(bH, 144, wn * 32 + q * 16, k0, lane),
                  bh[q][0], bh[q][1], bh[q][2], bh[q][3]);
            ldsm4(addrB(bL, 144, wn * 32 + q * 16, k0, lane),
                  bl[q][0], bl[q][1], bl[q][2], bl[q][3]);
        }
#pragma unroll
        for (int m2 = 0; m2 < 2; ++m2)
#pragma unroll
            for (int o = 0; o < 4; ++o) {
                int q = o >> 1, pp = (o & 1) * 2;
                hmma(cs[m2][o], ah[m2][0], ah[m2][1], ah[m2][2], ah[m2][3],
                     bh[q][pp], bh[q][pp + 1]);
                hmma(cs[m2][o], ah[m2][0], ah[m2][1], ah[m2][2], ah[m2][3],
                     bl[q][pp], bl[q][pp + 1]);
                hmma(cs[m2][o], al[m2][0], al[m2][1], al[m2][2], al[m2][3],
                     bh[q][pp], bh[q][pp + 1]);
            }
    }
}

// direct fragment -> gmem store of a 128x64 tile
__device__ __forceinline__ void store_frag_g(float* dst, float c[2][4][4],
                                             int wm, int wn, int g, int t) {
#pragma unroll
    for (int m2 = 0; m2 < 2; ++m2)
#pragma unroll
        for (int o = 0; o < 4; ++o) {
            int row = wm * 32 + m2 * 16 + g;
            int col = wn * 32 + o * 8 + 2 * t;
            *(float2*)&dst[(size_t)row * L_SEQ + col] = make_float2(c[m2][o][0], c[m2][o][1]);
            *(float2*)&dst[(size_t)(row + 8) * L_SEQ + col] = make_float2(c[m2][o][2], c[m2][o][3]);
        }
}

__global__ __launch_bounds__(256, 1) void attn_mma(float* __restrict__ attn_out,
                                                   float* __restrict__ rel_out) {
    extern __shared__ char smraw[];
    u32 usm = (u32)__cvta_generic_to_shared(smraw);
    float* lsum = (float*)(smraw + 184320);
    float* linv = lsum + 256;
    float* osc  = (float*)(smraw + 73728);   // reuse ring for O reduction

    const int hq = blockIdx.y;
    const int ib = 15 - blockIdx.x;          // heavy blocks first
    const int i0 = ib * 128;
    const int tid = threadIdx.x, lane = tid & 31, warp = tid >> 5;
    const int wm = warp & 3, wn = warp >> 2;
    const int g = lane >> 2, t = lane & 3;
    const int jtmax = 2 * ib + 1;

    // Q planes: a=0..3 -> qa_h, qa_l, qr_h, qr_l at usm + a*18432 (stride 144B)
    {
        const bf16* srcs[4] = {g_qah + ((size_t)hq * L_SEQ + i0) * HD,
                               g_qal + ((size_t)hq * L_SEQ + i0) * HD,
                               g_qrh + ((size_t)hq * L_SEQ + i0) * HD,
                               g_qrl + ((size_t)hq * L_SEQ + i0) * HD};
#pragma unroll
        for (int a = 0; a < 4; ++a)
#pragma unroll
            for (int it = 0; it < 4; ++it) {
                int idx = it * 256 + tid;
                int r = idx >> 3, s = idx & 7;
                *(uint4*)(smraw + a * 18432 + r * 144 + s * 16) =
                    *(const uint4*)&srcs[a][(size_t)r * HD + s * 8];
            }
    }
    const u32 uqa_h = usm, uqa_l = usm + 18432u;
    const u32 uqr_h = usm + 36864u, uqr_l = usm + 55296u;
    auto ring = [&](int st, int pl) -> u32 {
        return usm + 73728u + (u32)st * 55296u + (u32)pl * 9216u;
    };

    auto issue_ka = [&](int jt, int st) {
#pragma unroll
        for (int it = 0; it < 4; ++it) {
            int idx = it * 256 + tid;
            int pl = idx >> 9, rem = idx & 511, r = rem >> 3, s = rem & 7;
            const bf16* src = pl ? g_kal : g_kah;
            cpasync16(ring(st, pl) + r * 144 + s * 16,
                      src + (size_t)(jt * 64 + r) * HD + s * 8);
        }
        cpcommit();
    };
    auto issue_p2 = [&](int jt, int st, bool causal) {
#pragma unroll
        for (int it = 0; it < 4; ++it) {
            int idx = it * 256 + tid;
            int pl = idx >> 9, rem = idx & 511, r = rem >> 3, s = rem & 7;
            const bf16* src = pl ? g_krl : g_krh;
            cpasync16(ring(st, 2 + pl) + r * 144 + s * 16,
                      src + (size_t)(jt * 64 + r) * HD + s * 8);
        }
        if (causal) {
#pragma unroll
            for (int it = 0; it < 4; ++it) {
                int idx = it * 256 + tid;
                int pl = idx >> 9, rem = idx & 511, r = rem >> 3, s = rem & 7;
                const bf16* src = pl ? g_kal : g_kah;
                cpasync16(ring(st, pl) + r * 144 + s * 16,
                          src + (size_t)(jt * 64 + r) * HD + s * 8);
            }
#pragma unroll
            for (int it = 0; it < 4; ++it) {
                int idx = it * 256 + tid;
                int pl = idx >> 9, rem = idx & 511, r = rem >> 3, s = rem & 7;
                const bf16* src = pl ? g_vtl : g_vth;
                cpasync16(ring(st, 4 + pl) + r * 144 + s * 16,
                          src + (size_t)r * L_SEQ + jt * 64 + s * 8);
            }
        }
        cpcommit();
    };

    // -------- pass 1: causal row sums of exp(scores) --------
    float esum[2][2] = {{0.f, 0.f}, {0.f, 0.f}};
    issue_ka(0, 0);
    for (int jt = 0; jt <= jtmax; ++jt) {
        if (jt < jtmax) { issue_ka(jt + 1, (jt + 1) & 1); cpwait1(); }
        else cpwait0();
        __syncthreads();
        int st = jt & 1;
        float cs[2][4][4];
#pragma unroll
        for (int m2 = 0; m2 < 2; ++m2)
#pragma unroll
            for (int o = 0; o < 4; ++o)
#pragma unroll
                for (int k = 0; k < 4; ++k) cs[m2][o][k] = 0.f;
        mma_qk(uqa_h, uqa_l, ring(st, 0), ring(st, 1), wm, wn, lane, cs);

        if (jt < 2 * ib) {
#pragma unroll
            for (int m2 = 0; m2 < 2; ++m2)
#pragma unroll
                for (int o = 0; o < 4; ++o) {
                    esum[m2][0] += __expf(cs[m2][o][0]) + __expf(cs[m2][o][1]);
                    esum[m2][1] += __expf(cs[m2][o][2]) + __expf(cs[m2][o][3]);
                }
        } else {
#pragma unroll
            for (int m2 = 0; m2 < 2; ++m2)
#pragma unroll
                for (int o = 0; o < 4; ++o) {
                    int r0 = i0 + wm * 32 + m2 * 16 + g;
                    int cb = jt * 64 + wn * 32 + o * 8 + 2 * t;
                    if (cb     <= r0)     esum[m2][0] += __expf(cs[m2][o][0]);
                    if (cb + 1 <= r0)     esum[m2][0] += __expf(cs[m2][o][1]);
                    if (cb     <= r0 + 8) esum[m2][1] += __expf(cs[m2][o][2]);
                    if (cb + 1 <= r0 + 8) esum[m2][1] += __expf(cs[m2][o][3]);
                }
        }
        __syncthreads();
    }
#pragma unroll
    for (int m2 = 0; m2 < 2; ++m2)
#pragma unroll
        for (int hf = 0; hf < 2; ++hf) {
            float v = esum[m2][hf];
            v += __shfl_xor_sync(0xffffffffu, v, 1);
            v += __shfl_xor_sync(0xffffffffu, v, 2);
            esum[m2][hf] = v;
        }
    if (t == 0) {
#pragma unroll
        for (int m2 = 0; m2 < 2; ++m2) {
            lsum[wn * 128 + wm * 32 + m2 * 16 + g] = esum[m2][0];
            lsum[wn * 128 + wm * 32 + m2 * 16 + g + 8] = esum[m2][1];
        }
    }
    __syncthreads();
    if (tid < 128) linv[tid] = __fdividef(1.f, lsum[tid] + lsum[128 + tid]);
    __syncthreads();
    float li[2][2];
#pragma unroll
    for (int m2 = 0; m2 < 2; ++m2) {
        li[m2][0] = linv[wm * 32 + m2 * 16 + g];
        li[m2][1] = linv[wm * 32 + m2 * 16 + g + 8];
    }

    float co[2][8][4];
#pragma unroll
    for (int m2 = 0; m2 < 2; ++m2)
#pragma unroll
        for (int o = 0; o < 8; ++o)
#pragma unroll
            for (int k = 0; k < 4; ++k) co[m2][o][k] = 0.f;

    float* attnp = attn_out + (size_t)hq * L_SEQ * L_SEQ + (size_t)i0 * L_SEQ;
    float* relp  = rel_out  + (size_t)hq * L_SEQ * L_SEQ + (size_t)i0 * L_SEQ;

    // -------- pass 2 --------
    issue_p2(0, 0, true);
    for (int jt = 0; jt < 32; ++jt) {
        const bool causal = (jt <= jtmax);
        if (jt < 31) { issue_p2(jt + 1, (jt + 1) & 1, (jt + 1) <= jtmax); cpwait1(); }
        else cpwait0();
        __syncthreads();
        int st = jt & 1;

        float cr[2][4][4];
#pragma unroll
        for (int m2 = 0; m2 < 2; ++m2)
#pragma unroll
            for (int o = 0; o < 4; ++o)
#pragma unroll
                for (int k = 0; k < 4; ++k) cr[m2][o][k] = 0.f;
        mma_qk(uqr_h, uqr_l, ring(st, 2), ring(st, 3), wm, wn, lane, cr);
        store_frag_g(relp + jt * 64, cr, wm, wn, g, t);

        if (!causal) {
            float4 z = make_float4(0.f, 0.f, 0.f, 0.f);
#pragma unroll
            for (int it = 0; it < 8; ++it) {
                int idx = it * 256 + tid;
                int r = idx >> 4, s = idx & 15;
                *(float4*)&attnp[(size_t)r * L_SEQ + jt * 64 + s * 4] = z;
            }
            __syncthreads();
            continue;
        }

        float csq[2][4][4];
#pragma unroll
        for (int m2 = 0; m2 < 2; ++m2)
#pragma unroll
            for (int o = 0; o < 4; ++o)
#pragma unroll
                for (int k = 0; k < 4; ++k) csq[m2][o][k] = 0.f;
        mma_qk(uqa_h, uqa_l, ring(st, 0), ring(st, 1), wm, wn, lane, csq);

        const bool dia = (jt >= 2 * ib);
#pragma unroll
        for (int m2 = 0; m2 < 2; ++m2)
#pragma unroll
            for (int o = 0; o < 4; ++o) {
                int r0 = i0 + wm * 32 + m2 * 16 + g;
                int cb = jt * 64 + wn * 32 + o * 8 + 2 * t;
                float p0 = __expf(csq[m2][o][0]) * li[m2][0];
                float p1 = __expf(csq[m2][o][1]) * li[m2][0];
                float p2 = __expf(csq[m2][o][2]) * li[m2][1];
                float p3 = __expf(csq[m2][o][3]) * li[m2][1];
                if (dia) {
                    if (cb     > r0)     p0 = 0.f;
                    if (cb + 1 > r0)     p1 = 0.f;
                    if (cb     > r0 + 8) p2 = 0.f;
                    if (cb + 1 > r0 + 8) p3 = 0.f;
                }
                csq[m2][o][0] = p0; csq[m2][o][1] = p1;
                csq[m2][o][2] = p2; csq[m2][o][3] = p3;
            }
        store_frag_g(attnp + jt * 64, csq, wm, wn, g, t);

        // PV: O += (P.R) @ V over this warp's 32 j-cols
#pragma unroll
        for (int b = 0; b < 2; ++b) {
            u32 vh[4][4], vl[4][4];
#pragma unroll
            for (int q2 = 0; q2 < 4; ++q2) {
                ldsm4(addrB(ring(st, 4), 144, q2 * 16, wn * 32 + b * 16, lane),
                      vh[q2][0], vh[q2][1], vh[q2][2], vh[q2][3]);
                ldsm4(addrB(ring(st, 5), 144, q2 * 16, wn * 32 + b * 16, lane),
                      vl[q2][0], vl[q2][1], vl[q2][2], vl[q2][3]);
            }
#pragma unroll
            for (int m2 = 0; m2 < 2; ++m2) {
                float pr[8];
#pragma unroll
                for (int k = 0; k < 4; ++k) {
                    pr[k]     = csq[m2][2 * b][k]     * cr[m2][2 * b][k];
                    pr[4 + k] = csq[m2][2 * b + 1][k] * cr[m2][2 * b + 1][k];
                }
                u32 aH[4], aL[4];
                packsplit(pr[0], pr[1], aH[0], aL[0]);
                packsplit(pr[2], pr[3], aH[1], aL[1]);
                packsplit(pr[4], pr[5], aH[2], aL[2]);
                packsplit(pr[6], pr[7], aH[3], aL[3]);
#pragma unroll
                for (int q2 = 0; q2 < 4; ++q2)
#pragma unroll
                    for (int sub = 0; sub < 2; ++sub) {
                        int o = q2 * 2 + sub, pp = sub * 2;
                        hmma(co[m2][o], aH[0], aH[1], aH[2], aH[3],
                             vh[q2][pp], vh[q2][pp + 1]);
                        hmma(co[m2][o], aH[0], aH[1], aH[2], aH[3],
                             vl[q2][pp], vl[q2][pp + 1]);
                        hmma(co[m2][o], aL[0], aL[1], aL[2], aL[3],
                             vh[q2][pp], vh[q2][pp + 1]);
                    }
            }
        }
        __syncthreads();
    }

    // -------- O reduction across wn (reuse ring as float scratch) --------
    if (wn == 0) {
#pragma unroll
        for (int m2 = 0; m2 < 2; ++m2)
#pragma unroll
            for (int o = 0; o < 8; ++o) {
                int row = wm * 32 + m2 * 16 + g;
                int col = o * 8 + 2 * t;
                *(float2*)&osc[row * 68 + col] = make_float2(co[m2][o][0], co[m2][o][1]);
                *(float2*)&osc[(row + 8) * 68 + col] = make_float2(co[m2][o][2], co[m2][o][3]);
            }
    }
    __syncthreads();
    if (wn == 1) {
#pragma unroll
        for (int m2 = 0; m2 < 2; ++m2)
#pragma unroll
            for (int o = 0; o < 8; ++o) {
                int row = wm * 32 + m2 * 16 + g;
                int col = o * 8 + 2 * t;
                osc[row * 68 + col]           += co[m2][o][0];
                osc[row * 68 + col + 1]       += co[m2][o][1];
                osc[(row + 8) * 68 + col]     += co[m2][o][2];
                osc[(row + 8) * 68 + col + 1] += co[m2][o][3];
            }
    }
    __syncthreads();
#pragma unroll
    for (int it = 0; it < 32; ++it) {
        int idx = it * 256 + tid;
        int r = idx >> 6, d = idx & 63;
        float v = osc[r * 68 + d];
        bf16 hh, ll; split2(v, hh, ll);
        size_t off = (size_t)(i0 + r) * DM + hq * 64 + d;
        g_aoh[off] = hh; g_aol[off] = ll;
    }
}

// ---------------------------------- launch ----------------------------------
extern "C" void kernel_launch(void* const* d_in, const int* in_sizes, int n_in,
                              void* d_out, int out_size) {
    (void)in_sizes; (void)n_in; (void)out_size;
    const float* x    = (const float*)d_in[0];
    const float* sym  = (const float*)d_in[1];
    const float* fcos = (const float*)d_in[2];
    const float* fsin = (const float*)d_in[3];
    const float* wqa  = (const float*)d_in[4];
    const float* wka  = (const float*)d_in[5];
    const float* wqr  = (const float*)d_in[6];
    const float* wkr  = (const float*)d_in[7];
    const float* wv   = (const float*)d_in[8];
    const float* wo   = (const float*)d_in[9];

    float* out  = (float*)d_out;
    float* attn = out + (size_t)L_SEQ * DM;
    float* rel  = attn + (size_t)NH * L_SEQ * L_SEQ;

    void* p;
#define GS(var, sym_) cudaGetSymbolAddress(&p, sym_); bf16* var = (bf16*)p;
#define GF(var, sym_) cudaGetSymbolAddress(&p, sym_); float* var = (float*)p;
    GS(xh, g_xh)   GS(xl, g_xl)
    GS(wqah, g_wqah) GS(wqal, g_wqal) GS(wqrh, g_wqrh) GS(wqrl, g_wqrl)
    GS(woh, g_woh)   GS(wol, g_wol)
    GS(aoh, g_aoh)   GS(aol, g_aol)
    GF(t0, g_t0) GF(t1, g_t1)
#undef GS
#undef GF

    static bool attrs_set = false;
    if (!attrs_set) {
        cudaFuncSetAttribute(gemm_big, cudaFuncAttributeMaxDynamicSharedMemorySize, 61440);
        cudaFuncSetAttribute(attn_mma, cudaFuncAttributeMaxDynamicSharedMemorySize, 185856);
        attrs_set = true;
    }

    split_in<<<(2 * L_SEQ * DM) / 256, 256>>>(x, sym);
    tsplit_big<<<dim3(32, 32, 3), 256>>>(wqa, wqr, wo);
    tsplit_small<<<dim3(32, 2, 3), 256>>>(wka, wkr, wv);

    gemm_big<<<dim3(16, 16), 256, 61440>>>(xh, xl, wqah, wqal, t0, DM);
    gemm_big<<<dim3(16, 16), 256, 61440>>>(xh, xl, wqrh, wqrl, t1, DM);
    proj3<<<dim3(32, 3), 256>>>();

    {
        int total = 2 * L_SEQ * NH * 32 + 262144;
        rope_split<<<(total + 255) / 256, 256>>>(fcos, fsin);
    }
    attn_mma<<<dim3(16, 16), 256, 185856>>>(attn, rel);
    gemm_big<<<dim3(16, 16), 256, 61440>>>(aoh, aol, woh, wol, out, DM);
}

// round 6
// speedup vs baseline: 2.9914x; 1.0300x over previous
#include <cuda_runtime.h>
#include <cuda_bf16.h>
#include <cstdint>
#include <cstddef>

#define L_SEQ 2048
#define DM    1024
#define NH    16
#define HD    64
#define RSCALE 0.125f
typedef __nv_bfloat16 bf16;
typedef unsigned int u32;

// ---------------- scratch ----------------
__device__ bf16 g_xh[L_SEQ*DM],  g_xl[L_SEQ*DM];
__device__ bf16 g_sh[L_SEQ*DM],  g_sl[L_SEQ*DM];
__device__ bf16 g_wqah[DM*DM], g_wqal[DM*DM];
__device__ bf16 g_wqrh[DM*DM], g_wqrl[DM*DM];
__device__ bf16 g_woh [DM*DM], g_wol [DM*DM];
__device__ bf16 g_wkah[HD*DM], g_wkal[HD*DM];
__device__ bf16 g_wkrh[HD*DM], g_wkrl[HD*DM];
__device__ bf16 g_wvh [HD*DM], g_wvl [HD*DM];
__device__ float g_t0[L_SEQ*DM], g_t1[L_SEQ*DM];
__device__ float g_kaf[L_SEQ*HD], g_krf[L_SEQ*HD], g_vf[L_SEQ*HD];
__device__ bf16 g_qah[NH*L_SEQ*HD], g_qal[NH*L_SEQ*HD];
__device__ bf16 g_qrh[NH*L_SEQ*HD], g_qrl[NH*L_SEQ*HD];
__device__ bf16 g_kah[L_SEQ*HD], g_kal[L_SEQ*HD];
__device__ bf16 g_krh[L_SEQ*HD], g_krl[L_SEQ*HD];
__device__ bf16 g_vth[HD*L_SEQ], g_vtl[HD*L_SEQ];
__device__ bf16 g_aoh[L_SEQ*DM], g_aol[L_SEQ*DM];
__device__ float g_linv[NH*L_SEQ];

// ---------------- helpers ----------------
__device__ __forceinline__ void split2(float v, bf16& hi, bf16& lo) {
    hi = __float2bfloat16(v);
    lo = __float2bfloat16(v - __bfloat162float(hi));
}
__device__ __forceinline__ void packsplit(float a, float b, u32& ph, u32& pl) {
    float ah = __bfloat162float(__float2bfloat16(a));
    float bh = __bfloat162float(__float2bfloat16(b));
    __nv_bfloat162 hv = __floats2bfloat162_rn(ah, bh);
    __nv_bfloat162 lv = __floats2bfloat162_rn(a - ah, b - bh);
    ph = *reinterpret_cast<u32*>(&hv);
    pl = *reinterpret_cast<u32*>(&lv);
}
__device__ __forceinline__ void ldsm4(u32 addr, u32& r0, u32& r1, u32& r2, u32& r3) {
    asm volatile("ldmatrix.sync.aligned.m8n8.x4.shared.b16 {%0,%1,%2,%3}, [%4];"
                 : "=r"(r0), "=r"(r1), "=r"(r2), "=r"(r3) : "r"(addr));
}
__device__ __forceinline__ void hmma(float* c, u32 a0, u32 a1, u32 a2, u32 a3,
                                     u32 b0, u32 b1) {
    asm volatile("mma.sync.aligned.m16n8k16.row.col.f32.bf16.bf16.f32 "
                 "{%0,%1,%2,%3},{%4,%5,%6,%7},{%8,%9},{%0,%1,%2,%3};"
                 : "+f"(c[0]), "+f"(c[1]), "+f"(c[2]), "+f"(c[3])
                 : "r"(a0), "r"(a1), "r"(a2), "r"(a3), "r"(b0), "r"(b1));
}
__device__ __forceinline__ u32 addrA(u32 base, int ldb, int m0, int k0, int lane) {
    int g = lane & 7, grp = lane >> 3;
    return base + (u32)((m0 + g + (grp & 1) * 8) * ldb + (k0 + (grp >> 1) * 8) * 2);
}
__device__ __forceinline__ u32 addrB(u32 base, int ldb, int n0, int k0, int lane) {
    int g = lane & 7, grp = lane >> 3;
    return base + (u32)((n0 + g + (grp >> 1) * 8) * ldb + (k0 + (grp & 1) * 8) * 2);
}
__device__ __forceinline__ void cpasync16(u32 dst, const void* src) {
    asm volatile("cp.async.cg.shared.global [%0], [%1], 16;" :: "r"(dst), "l"(src));
}
__device__ __forceinline__ void cpcommit() { asm volatile("cp.async.commit_group;"); }
__device__ __forceinline__ void cpwait0() { asm volatile("cp.async.wait_group 0;"); }
__device__ __forceinline__ void cpwait1() { asm volatile("cp.async.wait_group 1;"); }

// ---------------- input split ----------------
__global__ void split_in(const float* __restrict__ x, const float* __restrict__ s) {
    int i = blockIdx.x * 256 + threadIdx.x;
    if (i < L_SEQ * DM) {
        split2(x[i], g_xh[i], g_xl[i]);
    } else {
        int k = i - L_SEQ * DM;
        if (k < L_SEQ * DM) split2(s[k], g_sh[k], g_sl[k]);
    }
}

// ---------------- weight transpose + split ----------------
__global__ void tsplit_big(const float* __restrict__ w0, const float* __restrict__ w1,
                           const float* __restrict__ w2) {
    __shared__ float t[32][33];
    int z = blockIdx.z;
    const float* src = (z == 0) ? w0 : (z == 1) ? w1 : w2;
    bf16* dh = (z == 0) ? g_wqah : (z == 1) ? g_wqrh : g_woh;
    bf16* dl = (z == 0) ? g_wqal : (z == 1) ? g_wqrl : g_wol;
    int k0 = blockIdx.x * 32, n0 = blockIdx.y * 32;
    int tx = threadIdx.x & 31, ty0 = threadIdx.x >> 5;
#pragma unroll
    for (int q = 0; q < 4; ++q) {
        int ty = ty0 * 4 + q;
        t[ty][tx] = src[(size_t)(k0 + ty) * DM + n0 + tx];
    }
    __syncthreads();
#pragma unroll
    for (int q = 0; q < 4; ++q) {
        int ty = ty0 * 4 + q;
        bf16 hh, ll; split2(t[tx][ty], hh, ll);
        size_t o = (size_t)(n0 + ty) * DM + k0 + tx;
        dh[o] = hh; dl[o] = ll;
    }
}
__global__ void tsplit_small(const float* __restrict__ w0, const float* __restrict__ w1,
                             const float* __restrict__ w2) {
    __shared__ float t[32][33];
    int z = blockIdx.z;
    const float* src = (z == 0) ? w0 : (z == 1) ? w1 : w2;
    bf16* dh = (z == 0) ? g_wkah : (z == 1) ? g_wkrh : g_wvh;
    bf16* dl = (z == 0) ? g_wkal : (z == 1) ? g_wkrl : g_wvl;
    int k0 = blockIdx.x * 32, n0 = blockIdx.y * 32;
    int tx = threadIdx.x & 31, ty0 = threadIdx.x >> 5;
#pragma unroll
    for (int q = 0; q < 4; ++q) {
        int ty = ty0 * 4 + q;
        t[ty][tx] = src[(size_t)(k0 + ty) * HD + n0 + tx];
    }
    __syncthreads();
#pragma unroll
    for (int q = 0; q < 4; ++q) {
        int ty = ty0 * 4 + q;
        bf16 hh, ll; split2(t[tx][ty], hh, ll);
        size_t o = (size_t)(n0 + ty) * DM + k0 + tx;
        dh[o] = hh; dl[o] = ll;
    }
}

// ---------------- big GEMM: BM=128 BN=128 BK=32, 3-stage cp.async ----------------
// stage layout (40960 B): Ah@0, Al@10240, Bh@20480, Bl@30720; row stride 80 B.
__global__ __launch_bounds__(256, 1) void gemm_big(const bf16* __restrict__ Ah,
                                                   const bf16* __restrict__ Al,
                                                   const bf16* __restrict__ Bh,
                                                   const bf16* __restrict__ Bl,
                                                   float* __restrict__ C) {
    extern __shared__ bf16 dsm[];
    const int tid = threadIdx.x, lane = tid & 31, warp = tid >> 5;
    const int wm = warp & 3, wn = warp >> 2;
    const int m0 = blockIdx.y * 128, n0 = blockIdx.x * 128;
    u32 ub = (u32)__cvta_generic_to_shared(dsm);

    float acc[2][8][4];
#pragma unroll
    for (int m2 = 0; m2 < 2; ++m2)
#pragma unroll
        for (int o = 0; o < 8; ++o)
#pragma unroll
            for (int k = 0; k < 4; ++k) acc[m2][o][k] = 0.f;

    auto issue = [&](int k0, int st) {
        u32 base = ub + (u32)st * 40960u;
#pragma unroll
        for (int it = 0; it < 4; ++it) {
            int idx = it * 256 + tid;
            int pl = idx >> 9, rem = idx & 511, r = rem >> 2, s = rem & 3;
            const bf16* src = pl ? Al : Ah;
            cpasync16(base + (u32)pl * 10240u + r * 80 + s * 16,
                      src + (size_t)(m0 + r) * DM + k0 + s * 8);
        }
#pragma unroll
        for (int it = 0; it < 4; ++it) {
            int idx = it * 256 + tid;
            int pl = idx >> 9, rem = idx & 511, r = rem >> 2, s = rem & 3;
            const bf16* src = pl ? Bl : Bh;
            cpasync16(base + 20480u + (u32)pl * 10240u + r * 80 + s * 16,
                      src + (size_t)(n0 + r) * DM + k0 + s * 8);
        }
        cpcommit();
    };

    const int NK = DM / 32;
    issue(0, 0);
    issue(32, 1);
    for (int kt = 0; kt < NK; ++kt) {
        if (kt == NK - 1) cpwait0(); else cpwait1();
        __syncthreads();
        u32 base = ub + (u32)(kt % 3) * 40960u;
        u32 aH = base, aL = base + 10240u, bH = base + 20480u, bL = base + 30720u;
#pragma unroll
        for (int ks = 0; ks < 2; ++ks) {
            int kk = ks * 16;
            u32 ah[2][4], al[2][4], bh[4][4], bl[4][4];
#pragma unroll
            for (int m2 = 0; m2 < 2; ++m2) {
                ldsm4(addrA(aH, 80, wm * 32 + m2 * 16, kk, lane),
                      ah[m2][0], ah[m2][1], ah[m2][2], ah[m2][3]);
                ldsm4(addrA(aL, 80, wm * 32 + m2 * 16, kk, lane),
                      al[m2][0], al[m2][1], al[m2][2], al[m2][3]);
            }
#pragma unroll
            for (int q = 0; q < 4; ++q) {
                ldsm4(addrB(bH, 80, wn * 64 + q * 16, kk, lane),
                      bh[q][0], bh[q][1], bh[q][2], bh[q][3]);
                ldsm4(addrB(bL, 80, wn * 64 + q * 16, kk, lane),
                      bl[q][0], bl[q][1], bl[q][2], bl[q][3]);
            }
#pragma unroll
            for (int m2 = 0; m2 < 2; ++m2)
#pragma unroll
                for (int o = 0; o < 8; ++o) {
                    int q = o >> 1, pp = (o & 1) * 2;
                    hmma(acc[m2][o], ah[m2][0], ah[m2][1], ah[m2][2], ah[m2][3],
                         bh[q][pp], bh[q][pp + 1]);
                    hmma(acc[m2][o], ah[m2][0], ah[m2][1], ah[m2][2], ah[m2][3],
                         bl[q][pp], bl[q][pp + 1]);
                    hmma(acc[m2][o], al[m2][0], al[m2][1], al[m2][2], al[m2][3],
                         bh[q][pp], bh[q][pp + 1]);
                }
        }
        __syncthreads();
        if (kt + 2 < NK) issue((kt + 2) * 32, (kt + 2) % 3);
    }
    const int g = lane >> 2, t = lane & 3;
#pragma unroll
    for (int m2 = 0; m2 < 2; ++m2)
#pragma unroll
        for (int o = 0; o < 8; ++o) {
            int row = m0 + wm * 32 + m2 * 16 + g;
            int col = n0 + wn * 64 + o * 8 + 2 * t;
            *(float2*)&C[(size_t)row * DM + col] = make_float2(acc[m2][o][0], acc[m2][o][1]);
            *(float2*)&C[(size_t)(row + 8) * DM + col] = make_float2(acc[m2][o][2], acc[m2][o][3]);
        }
}

// ---------------- 3 small projections fused: BM=64, grid (32,3) ----------------
__global__ __launch_bounds__(256, 2) void proj3() {
    __shared__ bf16 sA[2 * 2 * 64 * 40];
    __shared__ bf16 sB[2 * 2 * 64 * 40];
    const int z = blockIdx.y;
    const bf16* Ah = (z == 2) ? g_sh : g_xh;
    const bf16* Al = (z == 2) ? g_sl : g_xl;
    const bf16* Bh = (z == 0) ? g_wkah : (z == 1) ? g_wkrh : g_wvh;
    const bf16* Bl = (z == 0) ? g_wkal : (z == 1) ? g_wkrl : g_wvl;
    float* C = (z == 0) ? g_kaf : (z == 1) ? g_krf : g_vf;

    const int tid = threadIdx.x, lane = tid & 31, warp = tid >> 5;
    const int wm = warp & 3, wn = warp >> 2;
    const int m0 = blockIdx.x * 64;
    u32 ua = (u32)__cvta_generic_to_shared(sA);
    u32 ub = (u32)__cvta_generic_to_shared(sB);

    float acc[4][4];
#pragma unroll
    for (int o = 0; o < 4; ++o)
#pragma unroll
        for (int k = 0; k < 4; ++k) acc[o][k] = 0.f;

    auto issue = [&](int k0, int st) {
#pragma unroll
        for (int it = 0; it < 2; ++it) {
            int idx = it * 256 + tid;
            int pl = idx >> 8, rem = idx & 255, r = rem >> 2, s = rem & 3;
            const bf16* src = pl ? Al : Ah;
            cpasync16(ua + (u32)(st * 2 + pl) * 5120u + r * 80 + s * 16,
                      src + (size_t)(m0 + r) * DM + k0 + s * 8);
        }
#pragma unroll
        for (int it = 0; it < 2; ++it) {
            int idx = it * 256 + tid;
            int pl = idx >> 8, rem = idx & 255, r = rem >> 2, s = rem & 3;
            const bf16* src = pl ? Bl : Bh;
            cpasync16(ub + (u32)(st * 2 + pl) * 5120u + r * 80 + s * 16,
                      src + (size_t)r * DM + k0 + s * 8);
        }
        cpcommit();
    };

    issue(0, 0);
    const int NK = DM / 32;
    for (int kt = 0; kt < NK; ++kt) {
        if (kt + 1 < NK) { issue((kt + 1) * 32, (kt + 1) & 1); cpwait1(); }
        else cpwait0();
        __syncthreads();
        int st = kt & 1;
        u32 aH = ua + (u32)(st * 2) * 5120u, aL = aH + 5120u;
        u32 bH = ub + (u32)(st * 2) * 5120u, bL = bH + 5120u;
#pragma unroll
        for (int ks = 0; ks < 2; ++ks) {
            int kk = ks * 16;
            u32 ah[4], al[4], bh[2][4], bl[2][4];
            ldsm4(addrA(aH, 80, wm * 16, kk, lane), ah[0], ah[1], ah[2], ah[3]);
            ldsm4(addrA(aL, 80, wm * 16, kk, lane), al[0], al[1], al[2], al[3]);
#pragma unroll
            for (int q = 0; q < 2; ++q) {
                ldsm4(addrB(bH, 80, wn * 32 + q * 16, kk, lane),
                      bh[q][0], bh[q][1], bh[q][2], bh[q][3]);
                ldsm4(addrB(bL, 80, wn * 32 + q * 16, kk, lane),
                      bl[q][0], bl[q][1], bl[q][2], bl[q][3]);
            }
#pragma unroll
            for (int o = 0; o < 4; ++o) {
                int q = o >> 1, pp = (o & 1) * 2;
                hmma(acc[o], ah[0], ah[1], ah[2], ah[3], bh[q][pp], bh[q][pp + 1]);
                hmma(acc[o], ah[0], ah[1], ah[2], ah[3], bl[q][pp], bl[q][pp + 1]);
                hmma(acc[o], al[0], al[1], al[2], al[3], bh[q][pp], bh[q][pp + 1]);
            }
        }
        __syncthreads();
    }
    const int g = lane >> 2, t = lane & 3;
#pragma unroll
    for (int o = 0; o < 4; ++o) {
        int row = m0 + wm * 16 + g;
        int col = wn * 32 + o * 8 + 2 * t;
        *(float2*)&C[(size_t)row * HD + col] = make_float2(acc[o][0], acc[o][1]);
        *(float2*)&C[(size_t)(row + 8) * HD + col] = make_float2(acc[o][2], acc[o][3]);
    }
}

// ---------------- rope + permute + split ----------------
__global__ void rope_split(const float* __restrict__ fcos, const float* __restrict__ fsin) {
    const int NQ = L_SEQ * NH * 32;
    int idx = blockIdx.x * 256 + threadIdx.x;
    if (idx < NQ) {
        int p = idx & 31, hq = (idx >> 5) & 15, i = idx >> 9;
        float xr = g_t0[(size_t)i * DM + hq * 64 + 2 * p];
        float xi = g_t0[(size_t)i * DM + hq * 64 + 2 * p + 1];
        float c = fcos[i * 32 + p], s = fsin[i * 32 + p];
        float o0 = (xr * c - xi * s) * RSCALE, o1 = (xr * s + xi * c) * RSCALE;
        size_t o = ((size_t)hq * L_SEQ + i) * HD + 2 * p;
        split2(o0, g_qah[o], g_qal[o]);
        split2(o1, g_qah[o + 1], g_qal[o + 1]);
    } else if (idx < 2 * NQ) {
        int k = idx - NQ;
        int p = k & 31, hq = (k >> 5) & 15, i = k >> 9;
        float xr = g_t1[(size_t)i * DM + hq * 64 + 2 * p] * RSCALE;
        float xi = g_t1[(size_t)i * DM + hq * 64 + 2 * p + 1] * RSCALE;
        size_t o = ((size_t)hq * L_SEQ + i) * HD + 2 * p;
        split2(xr, g_qrh[o], g_qrl[o]);
        split2(xi, g_qrh[o + 1], g_qrl[o + 1]);
    } else if (idx < 2 * NQ + 65536) {
        int k = idx - 2 * NQ;
        int p = k & 31, i = k >> 5;
        float xr = g_kaf[i * HD + 2 * p], xi = g_kaf[i * HD + 2 * p + 1];
        float c = fcos[i * 32 + p], s = fsin[i * 32 + p];
        split2(xr * c - xi * s, g_kah[i * HD + 2 * p], g_kal[i * HD + 2 * p]);
        split2(xr * s + xi * c, g_kah[i * HD + 2 * p + 1], g_kal[i * HD + 2 * p + 1]);
    } else if (idx < 2 * NQ + 131072) {
        int k = idx - 2 * NQ - 65536;
        int p = k & 31, i = k >> 5;
        split2(g_krf[i * HD + 2 * p], g_krh[i * HD + 2 * p], g_krl[i * HD + 2 * p]);
        split2(g_krf[i * HD + 2 * p + 1], g_krh[i * HD + 2 * p + 1], g_krl[i * HD + 2 * p + 1]);
    } else if (idx < 2 * NQ + 262144) {
        int k = idx - 2 * NQ - 131072;
        int j = k & (L_SEQ - 1), d = k >> 11;
        split2(g_vf[(size_t)j * HD + d], g_vth[(size_t)d * L_SEQ + j], g_vtl[(size_t)d * L_SEQ + j]);
    }
}

// ---------------- attention: single pass, unnormalized exp, deferred 1/l ----------------
__device__ __forceinline__ void mma_qk(u32 aH, u32 aL, u32 bH, u32 bL,
                                       int wm, int wn, int lane, float cs[2][4][4]) {
#pragma unroll
    for (int ks = 0; ks < 4; ++ks) {
        int k0 = ks * 16;
        u32 ah[2][4], al[2][4], bh[2][4], bl[2][4];
#pragma unroll
        for (int m2 = 0; m2 < 2; ++m2) {
            ldsm4(addrA(aH, 144, wm * 32 + m2 * 16, k0, lane),
                  ah[m2][0], ah[m2][1], ah[m2][2], ah[m2][3]);
            ldsm4(addrA(aL, 144, wm * 32 + m2 * 16, k0, lane),
                  al[m2][0], al[m2][1], al[m2][2], al[m2][3]);
        }
#pragma unroll
        for (int q = 0; q < 2; ++q) {
            ldsm4(addrB(bH, 144, wn * 32 + q * 16, k0, lane),
                  bh[q][0], bh[q][1], bh[q][2], bh[q][3]);
            ldsm4(addrB(bL, 144, wn * 32 + q * 16, k0, lane),
                  bl[q][0], bl[q][1], bl[q][2], bl[q][3]);
        }
#pragma unroll
        for (int m2 = 0; m2 < 2; ++m2)
#pragma unroll
            for (int o = 0; o < 4; ++o) {
                int q = o >> 1, pp = (o & 1) * 2;
                hmma(cs[m2][o], ah[m2][0], ah[m2][1], ah[m2][2], ah[m2][3],
                     bh[q][pp], bh[q][pp + 1]);
                hmma(cs[m2][o], ah[m2][0], ah[m2][1], ah[m2][2], ah[m2][3],
                     bl[q][pp], bl[q][pp + 1]);
                hmma(cs[m2][o], al[m2][0], al[m2][1], al[m2][2], al[m2][3],
                     bh[q][pp], bh[q][pp + 1]);
            }
    }
}

__device__ __forceinline__ void store_frag_g(float* dst, float c[2][4][4],
                                             int wm, int wn, int g, int t) {
#pragma unroll
    for (int m2 = 0; m2 < 2; ++m2)
#pragma unroll
        for (int o = 0; o < 4; ++o) {
            int row = wm * 32 + m2 * 16 + g;
            int col = wn * 32 + o * 8 + 2 * t;
            *(float2*)&dst[(size_t)row * L_SEQ + col] = make_float2(c[m2][o][0], c[m2][o][1]);
            *(float2*)&dst[(size_t)(row + 8) * L_SEQ + col] = make_float2(c[m2][o][2], c[m2][o][3]);
        }
}

__global__ __launch_bounds__(256, 1) void attn_mma(float* __restrict__ attn_out,
                                                   float* __restrict__ rel_out) {
    extern __shared__ char smraw[];
    u32 usm = (u32)__cvta_generic_to_shared(smraw);
    float* lsum = (float*)(smraw + 184320);
    float* linv = lsum + 256;
    float* osc  = (float*)(smraw + 73728);

    const int hq = blockIdx.y;
    const int ib = 15 - blockIdx.x;
    const int i0 = ib * 128;
    const int tid = threadIdx.x, lane = tid & 31, warp = tid >> 5;
    const int wm = warp & 3, wn = warp >> 2;
    const int g = lane >> 2, t = lane & 3;
    const int jtmax = 2 * ib + 1;

    {
        const bf16* srcs[4] = {g_qah + ((size_t)hq * L_SEQ + i0) * HD,
                               g_qal + ((size_t)hq * L_SEQ + i0) * HD,
                               g_qrh + ((size_t)hq * L_SEQ + i0) * HD,
                               g_qrl + ((size_t)hq * L_SEQ + i0) * HD};
#pragma unroll
        for (int a = 0; a < 4; ++a)
#pragma unroll
            for (int it = 0; it < 4; ++it) {
                int idx = it * 256 + tid;
                int r = idx >> 3, s = idx & 7;
                *(uint4*)(smraw + a * 18432 + r * 144 + s * 16) =
                    *(const uint4*)&srcs[a][(size_t)r * HD + s * 8];
            }
    }
    const u32 uqa_h = usm, uqa_l = usm + 18432u;
    const u32 uqr_h = usm + 36864u, uqr_l = usm + 55296u;
    auto ring = [&](int st, int pl) -> u32 {
        return usm + 73728u + (u32)st * 55296u + (u32)pl * 9216u;
    };

    auto issue_tiles = [&](int jt, int st, bool causal) {
#pragma unroll
        for (int it = 0; it < 4; ++it) {
            int idx = it * 256 + tid;
            int pl = idx >> 9, rem = idx & 511, r = rem >> 3, s = rem & 7;
            const bf16* src = pl ? g_krl : g_krh;
            cpasync16(ring(st, 2 + pl) + r * 144 + s * 16,
                      src + (size_t)(jt * 64 + r) * HD + s * 8);
        }
        if (causal) {
#pragma unroll
            for (int it = 0; it < 4; ++it) {
                int idx = it * 256 + tid;
                int pl = idx >> 9, rem = idx & 511, r = rem >> 3, s = rem & 7;
                const bf16* src = pl ? g_kal : g_kah;
                cpasync16(ring(st, pl) + r * 144 + s * 16,
                          src + (size_t)(jt * 64 + r) * HD + s * 8);
            }
#pragma unroll
            for (int it = 0; it < 4; ++it) {
                int idx = it * 256 + tid;
                int pl = idx >> 9, rem = idx & 511, r = rem >> 3, s = rem & 7;
                const bf16* src = pl ? g_vtl : g_vth;
                cpasync16(ring(st, 4 + pl) + r * 144 + s * 16,
                          src + (size_t)r * L_SEQ + jt * 64 + s * 8);
            }
        }
        cpcommit();
    };

    float esum[2][2] = {{0.f, 0.f}, {0.f, 0.f}};
    float co[2][8][4];
#pragma unroll
    for (int m2 = 0; m2 < 2; ++m2)
#pragma unroll
        for (int o = 0; o < 8; ++o)
#pragma unroll
            for (int k = 0; k < 4; ++k) co[m2][o][k] = 0.f;

    float* attnp = attn_out + (size_t)hq * L_SEQ * L_SEQ + (size_t)i0 * L_SEQ;
    float* relp  = rel_out  + (size_t)hq * L_SEQ * L_SEQ + (size_t)i0 * L_SEQ;

    issue_tiles(0, 0, true);
    for (int jt = 0; jt < 32; ++jt) {
        const bool causal = (jt <= jtmax);
        if (jt < 31) { issue_tiles(jt + 1, (jt + 1) & 1, (jt + 1) <= jtmax); cpwait1(); }
        else cpwait0();
        __syncthreads();
        int st = jt & 1;

        float cr[2][4][4];
#pragma unroll
        for (int m2 = 0; m2 < 2; ++m2)
#pragma unroll
            for (int o = 0; o < 4; ++o)
#pragma unroll
                for (int k = 0; k < 4; ++k) cr[m2][o][k] = 0.f;
        mma_qk(uqr_h, uqr_l, ring(st, 2), ring(st, 3), wm, wn, lane, cr);
        store_frag_g(relp + jt * 64, cr, wm, wn, g, t);

        if (!causal) {
            float4 z = make_float4(0.f, 0.f, 0.f, 0.f);
#pragma unroll
            for (int it = 0; it < 8; ++it) {
                int idx = it * 256 + tid;
                int r = idx >> 4, s = idx & 15;
                *(float4*)&attnp[(size_t)r * L_SEQ + jt * 64 + s * 4] = z;
            }
            __syncthreads();
            continue;
        }

        float csq[2][4][4];
#pragma unroll
        for (int m2 = 0; m2 < 2; ++m2)
#pragma unroll
            for (int o = 0; o < 4; ++o)
#pragma unroll
                for (int k = 0; k < 4; ++k) csq[m2][o][k] = 0.f;
        mma_qk(uqa_h, uqa_l, ring(st, 0), ring(st, 1), wm, wn, lane, csq);

        const bool dia = (jt >= 2 * ib);
#pragma unroll
        for (int m2 = 0; m2 < 2; ++m2)
#pragma unroll
            for (int o = 0; o < 4; ++o) {
                int r0 = i0 + wm * 32 + m2 * 16 + g;
                int cb = jt * 64 + wn * 32 + o * 8 + 2 * t;
                float p0 = __expf(csq[m2][o][0]);
                float p1 = __expf(csq[m2][o][1]);
                float p2 = __expf(csq[m2][o][2]);
                float p3 = __expf(csq[m2][o][3]);
                if (dia) {
                    if (cb     > r0)     p0 = 0.f;
                    if (cb + 1 > r0)     p1 = 0.f;
                    if (cb     > r0 + 8) p2 = 0.f;
                    if (cb + 1 > r0 + 8) p3 = 0.f;
                }
                esum[m2][0] += p0 + p1;
                esum[m2][1] += p2 + p3;
                csq[m2][o][0] = p0; csq[m2][o][1] = p1;
                csq[m2][o][2] = p2; csq[m2][o][3] = p3;
            }
        store_frag_g(attnp + jt * 64, csq, wm, wn, g, t);

        // O += (E.R) @ V over this warp's 32 j-cols (unnormalized)
#pragma unroll
        for (int b = 0; b < 2; ++b) {
            u32 vh[4][4], vl[4][4];
#pragma unroll
            for (int q2 = 0; q2 < 4; ++q2) {
                ldsm4(addrB(ring(st, 4), 144, q2 * 16, wn * 32 + b * 16, lane),
                      vh[q2][0], vh[q2][1], vh[q2][2], vh[q2][3]);
                ldsm4(addrB(ring(st, 5), 144, q2 * 16, wn * 32 + b * 16, lane),
                      vl[q2][0], vl[q2][1], vl[q2][2], vl[q2][3]);
            }
#pragma unroll
            for (int m2 = 0; m2 < 2; ++m2) {
                float pr[8];
#pragma unroll
                for (int k = 0; k < 4; ++k) {
                    pr[k]     = csq[m2][2 * b][k]     * cr[m2][2 * b][k];
                    pr[4 + k] = csq[m2][2 * b + 1][k] * cr[m2][2 * b + 1][k];
                }
                u32 aH[4], aL[4];
                packsplit(pr[0], pr[1], aH[0], aL[0]);
                packsplit(pr[2], pr[3], aH[1], aL[1]);
                packsplit(pr[4], pr[5], aH[2], aL[2]);
                packsplit(pr[6], pr[7], aH[3], aL[3]);
#pragma unroll
                for (int q2 = 0; q2 < 4; ++q2)
#pragma unroll
                    for (int sub = 0; sub < 2; ++sub) {
                        int o = q2 * 2 + sub, pp = sub * 2;
                        hmma(co[m2][o], aH[0], aH[1], aH[2], aH[3],
                             vh[q2][pp], vh[q2][pp + 1]);
                        hmma(co[m2][o], aH[0], aH[1], aH[2], aH[3],
                             vl[q2][pp], vl[q2][pp + 1]);
                        hmma(co[m2][o], aL[0], aL[1], aL[2], aL[3],
                             vh[q2][pp], vh[q2][pp + 1]);
                    }
            }
        }
        __syncthreads();
    }

    // -------- reduce row sums, compute 1/l, publish, scale O --------
#pragma unroll
    for (int m2 = 0; m2 < 2; ++m2)
#pragma unroll
        for (int hf = 0; hf < 2; ++hf) {
            float v = esum[m2][hf];
            v += __shfl_xor_sync(0xffffffffu, v, 1);
            v += __shfl_xor_sync(0xffffffffu, v, 2);
            esum[m2][hf] = v;
        }
    if (t == 0) {
#pragma unroll
        for (int m2 = 0; m2 < 2; ++m2) {
            lsum[wn * 128 + wm * 32 + m2 * 16 + g] = esum[m2][0];
            lsum[wn * 128 + wm * 32 + m2 * 16 + g + 8] = esum[m2][1];
        }
    }
    __syncthreads();
    if (tid < 128) {
        float v = __fdividef(1.f, lsum[tid] + lsum[128 + tid]);
        linv[tid] = v;
        g_linv[hq * L_SEQ + i0 + tid] = v;
    }
    __syncthreads();

    if (wn == 0) {
#pragma unroll
        for (int m2 = 0; m2 < 2; ++m2)
#pragma unroll
            for (int o = 0; o < 8; ++o) {
                int row = wm * 32 + m2 * 16 + g;
                int col = o * 8 + 2 * t;
                *(float2*)&osc[row * 68 + col] = make_float2(co[m2][o][0], co[m2][o][1]);
                *(float2*)&osc[(row + 8) * 68 + col] = make_float2(co[m2][o][2], co[m2][o][3]);
            }
    }
    __syncthreads();
    if (wn == 1) {
#pragma unroll
        for (int m2 = 0; m2 < 2; ++m2)
#pragma unroll
            for (int o = 0; o < 8; ++o) {
                int row = wm * 32 + m2 * 16 + g;
                int col = o * 8 + 2 * t;
                osc[row * 68 + col]           += co[m2][o][0];
                osc[row * 68 + col + 1]       += co[m2][o][1];
                osc[(row + 8) * 68 + col]     += co[m2][o][2];
                osc[(row + 8) * 68 + col + 1] += co[m2][o][3];
            }
    }
    __syncthreads();
#pragma unroll
    for (int it = 0; it < 32; ++it) {
        int idx = it * 256 + tid;
        int r = idx >> 6, d = idx & 63;
        float v = osc[r * 68 + d] * linv[r];
        bf16 hh, ll; split2(v, hh, ll);
        size_t off = (size_t)(i0 + r) * DM + hq * 64 + d;
        g_aoh[off] = hh; g_aol[off] = ll;
    }
}

// ---------------- rescale causal attn region by 1/l ----------------
__global__ __launch_bounds__(256) void rescale_attn(float* __restrict__ attn) {
    const int i = blockIdx.x, hq = blockIdx.y;
    const float s = g_linv[hq * L_SEQ + i];
    float* row = attn + ((size_t)hq * L_SEQ + i) * L_SEQ;
    const int W = (((i >> 6) + 1) << 6);   // causal tile width (zeros beyond diag are fine)
    for (int c = threadIdx.x * 4; c < W; c += 256 * 4) {
        float4 v = *(float4*)&row[c];
        v.x *= s; v.y *= s; v.z *= s; v.w *= s;
        *(float4*)&row[c] = v;
    }
}

// ---------------------------------- launch ----------------------------------
extern "C" void kernel_launch(void* const* d_in, const int* in_sizes, int n_in,
                              void* d_out, int out_size) {
    (void)in_sizes; (void)n_in; (void)out_size;
    const float* x    = (const float*)d_in[0];
    const float* sym  = (const float*)d_in[1];
    const float* fcos = (const float*)d_in[2];
    const float* fsin = (const float*)d_in[3];
    const float* wqa  = (const float*)d_in[4];
    const float* wka  = (const float*)d_in[5];
    const float* wqr  = (const float*)d_in[6];
    const float* wkr  = (const float*)d_in[7];
    const float* wv   = (const float*)d_in[8];
    const float* wo   = (const float*)d_in[9];

    float* out  = (float*)d_out;
    float* attn = out + (size_t)L_SEQ * DM;
    float* rel  = attn + (size_t)NH * L_SEQ * L_SEQ;

    void* p;
#define GS(var, sym_) cudaGetSymbolAddress(&p, sym_); bf16* var = (bf16*)p;
#define GF(var, sym_) cudaGetSymbolAddress(&p, sym_); float* var = (float*)p;
    GS(xh, g_xh)   GS(xl, g_xl)
    GS(wqah, g_wqah) GS(wqal, g_wqal) GS(wqrh, g_wqrh) GS(wqrl, g_wqrl)
    GS(woh, g_woh)   GS(wol, g_wol)
    GS(aoh, g_aoh)   GS(aol, g_aol)
    GF(t0, g_t0) GF(t1, g_t1)
#undef GS
#undef GF

    static bool attrs_set = false;
    if (!attrs_set) {
        cudaFuncSetAttribute(gemm_big, cudaFuncAttributeMaxDynamicSharedMemorySize, 122880);
        cudaFuncSetAttribute(attn_mma, cudaFuncAttributeMaxDynamicSharedMemorySize, 185856);
        attrs_set = true;
    }

    split_in<<<(2 * L_SEQ * DM) / 256, 256>>>(x, sym);
    tsplit_big<<<dim3(32, 32, 3), 256>>>(wqa, wqr, wo);
    tsplit_small<<<dim3(32, 2, 3), 256>>>(wka, wkr, wv);

    gemm_big<<<dim3(8, 16), 256, 122880>>>(xh, xl, wqah, wqal, t0);
    gemm_big<<<dim3(8, 16), 256, 122880>>>(xh, xl, wqrh, wqrl, t1);
    proj3<<<dim3(32, 3), 256>>>();

    {
        int total = 2 * L_SEQ * NH * 32 + 262144;
        rope_split<<<(total + 255) / 256, 256>>>(fcos, fsin);
    }
    attn_mma<<<dim3(16, 16), 256, 185856>>>(attn, rel);
    rescale_attn<<<dim3(L_SEQ, NH), 256>>>(attn);
    gemm_big<<<dim3(8, 16), 256, 122880>>>(aoh, aol, woh, wol, out);
}

// round 7
// speedup vs baseline: 3.1210x; 1.0433x over previous
#include <cuda_runtime.h>
#include <cuda_bf16.h>
#include <cstdint>
#include <cstddef>

#define L_SEQ 2048
#define DM    1024
#define NH    16
#define HD    64
#define RSCALE 0.125f
typedef __nv_bfloat16 bf16;
typedef unsigned int u32;

// ---------------- scratch ----------------
__device__ bf16 g_xh[L_SEQ*DM],  g_xl[L_SEQ*DM];
__device__ bf16 g_sh[L_SEQ*DM],  g_sl[L_SEQ*DM];
__device__ bf16 g_wqah[DM*DM], g_wqal[DM*DM];
__device__ bf16 g_wqrh[DM*DM], g_wqrl[DM*DM];
__device__ bf16 g_woh [DM*DM], g_wol [DM*DM];
__device__ bf16 g_wkah[HD*DM], g_wkal[HD*DM];
__device__ bf16 g_wkrh[HD*DM], g_wkrl[HD*DM];
__device__ bf16 g_wvh [HD*DM], g_wvl [HD*DM];
__device__ float g_t0[L_SEQ*DM], g_t1[L_SEQ*DM];
__device__ float g_kaf[L_SEQ*HD], g_krf[L_SEQ*HD], g_vf[L_SEQ*HD];
__device__ bf16 g_qah[NH*L_SEQ*HD], g_qal[NH*L_SEQ*HD];
__device__ bf16 g_qrh[NH*L_SEQ*HD], g_qrl[NH*L_SEQ*HD];
__device__ bf16 g_kah[L_SEQ*HD], g_kal[L_SEQ*HD];
__device__ bf16 g_krh[L_SEQ*HD], g_krl[L_SEQ*HD];
__device__ bf16 g_vth[HD*L_SEQ], g_vtl[HD*L_SEQ];
__device__ bf16 g_aoh[L_SEQ*DM], g_aol[L_SEQ*DM];
__device__ float g_linv[NH*L_SEQ];

// ---------------- helpers ----------------
__device__ __forceinline__ void split2(float v, bf16& hi, bf16& lo) {
    hi = __float2bfloat16(v);
    lo = __float2bfloat16(v - __bfloat162float(hi));
}
__device__ __forceinline__ void packsplit(float a, float b, u32& ph, u32& pl) {
    float ah = __bfloat162float(__float2bfloat16(a));
    float bh = __bfloat162float(__float2bfloat16(b));
    __nv_bfloat162 hv = __floats2bfloat162_rn(ah, bh);
    __nv_bfloat162 lv = __floats2bfloat162_rn(a - ah, b - bh);
    ph = *reinterpret_cast<u32*>(&hv);
    pl = *reinterpret_cast<u32*>(&lv);
}
__device__ __forceinline__ void ldsm4(u32 addr, u32& r0, u32& r1, u32& r2, u32& r3) {
    asm volatile("ldmatrix.sync.aligned.m8n8.x4.shared.b16 {%0,%1,%2,%3}, [%4];"
                 : "=r"(r0), "=r"(r1), "=r"(r2), "=r"(r3) : "r"(addr));
}
__device__ __forceinline__ void hmma(float* c, u32 a0, u32 a1, u32 a2, u32 a3,
                                     u32 b0, u32 b1) {
    asm volatile("mma.sync.aligned.m16n8k16.row.col.f32.bf16.bf16.f32 "
                 "{%0,%1,%2,%3},{%4,%5,%6,%7},{%8,%9},{%0,%1,%2,%3};"
                 : "+f"(c[0]), "+f"(c[1]), "+f"(c[2]), "+f"(c[3])
                 : "r"(a0), "r"(a1), "r"(a2), "r"(a3), "r"(b0), "r"(b1));
}
__device__ __forceinline__ u32 addrA(u32 base, int ldb, int m0, int k0, int lane) {
    int g = lane & 7, grp = lane >> 3;
    return base + (u32)((m0 + g + (grp & 1) * 8) * ldb + (k0 + (grp >> 1) * 8) * 2);
}
__device__ __forceinline__ u32 addrB(u32 base, int ldb, int n0, int k0, int lane) {
    int g = lane & 7, grp = lane >> 3;
    return base + (u32)((n0 + g + (grp >> 1) * 8) * ldb + (k0 + (grp & 1) * 8) * 2);
}
__device__ __forceinline__ void cpasync16(u32 dst, const void* src) {
    asm volatile("cp.async.cg.shared.global [%0], [%1], 16;" :: "r"(dst), "l"(src));
}
__device__ __forceinline__ void cpcommit() { asm volatile("cp.async.commit_group;"); }
__device__ __forceinline__ void cpwait0() { asm volatile("cp.async.wait_group 0;"); }
__device__ __forceinline__ void cpwait1() { asm volatile("cp.async.wait_group 1;"); }

// ---------------- input split ----------------
__global__ void split_in(const float* __restrict__ x, const float* __restrict__ s) {
    int i = blockIdx.x * 256 + threadIdx.x;
    if (i < L_SEQ * DM) {
        split2(x[i], g_xh[i], g_xl[i]);
    } else {
        int k = i - L_SEQ * DM;
        if (k < L_SEQ * DM) split2(s[k], g_sh[k], g_sl[k]);
    }
}

// ---------------- weight transpose + split ----------------
__global__ void tsplit_big(const float* __restrict__ w0, const float* __restrict__ w1,
                           const float* __restrict__ w2) {
    __shared__ float t[32][33];
    int z = blockIdx.z;
    const float* src = (z == 0) ? w0 : (z == 1) ? w1 : w2;
    bf16* dh = (z == 0) ? g_wqah : (z == 1) ? g_wqrh : g_woh;
    bf16* dl = (z == 0) ? g_wqal : (z == 1) ? g_wqrl : g_wol;
    int k0 = blockIdx.x * 32, n0 = blockIdx.y * 32;
    int tx = threadIdx.x & 31, ty0 = threadIdx.x >> 5;
#pragma unroll
    for (int q = 0; q < 4; ++q) {
        int ty = ty0 * 4 + q;
        t[ty][tx] = src[(size_t)(k0 + ty) * DM + n0 + tx];
    }
    __syncthreads();
#pragma unroll
    for (int q = 0; q < 4; ++q) {
        int ty = ty0 * 4 + q;
        bf16 hh, ll; split2(t[tx][ty], hh, ll);
        size_t o = (size_t)(n0 + ty) * DM + k0 + tx;
        dh[o] = hh; dl[o] = ll;
    }
}
__global__ void tsplit_small(const float* __restrict__ w0, const float* __restrict__ w1,
                             const float* __restrict__ w2) {
    __shared__ float t[32][33];
    int z = blockIdx.z;
    const float* src = (z == 0) ? w0 : (z == 1) ? w1 : w2;
    bf16* dh = (z == 0) ? g_wkah : (z == 1) ? g_wkrh : g_wvh;
    bf16* dl = (z == 0) ? g_wkal : (z == 1) ? g_wkrl : g_wvl;
    int k0 = blockIdx.x * 32, n0 = blockIdx.y * 32;
    int tx = threadIdx.x & 31, ty0 = threadIdx.x >> 5;
#pragma unroll
    for (int q = 0; q < 4; ++q) {
        int ty = ty0 * 4 + q;
        t[ty][tx] = src[(size_t)(k0 + ty) * HD + n0 + tx];
    }
    __syncthreads();
#pragma unroll
    for (int q = 0; q < 4; ++q) {
        int ty = ty0 * 4 + q;
        bf16 hh, ll; split2(t[tx][ty], hh, ll);
        size_t o = (size_t)(n0 + ty) * DM + k0 + tx;
        dh[o] = hh; dl[o] = ll;
    }
}

// ---------------- big GEMM: 512 thr, BM=128 BN=128 BK=32, 3-stage, 1 sync/iter -------
__global__ __launch_bounds__(512, 1) void gemm_big(const bf16* __restrict__ Ah,
                                                   const bf16* __restrict__ Al,
                                                   const bf16* __restrict__ Bh,
                                                   const bf16* __restrict__ Bl,
                                                   float* __restrict__ C) {
    extern __shared__ bf16 dsm[];
    const int tid = threadIdx.x, lane = tid & 31, warp = tid >> 5;
    const int wm = warp & 3, wn = warp >> 2;       // 4 x 4 warps, 32x32 each
    const int m0 = blockIdx.y * 128, n0 = blockIdx.x * 128;
    u32 ub = (u32)__cvta_generic_to_shared(dsm);

    float acc[2][4][4];
#pragma unroll
    for (int m2 = 0; m2 < 2; ++m2)
#pragma unroll
        for (int o = 0; o < 4; ++o)
#pragma unroll
            for (int k = 0; k < 4; ++k) acc[m2][o][k] = 0.f;

    auto issue = [&](int k0, int st) {
        u32 base = ub + (u32)st * 40960u;
#pragma unroll
        for (int it = 0; it < 2; ++it) {
            int idx = it * 512 + tid;
            int pl = idx >> 9, rem = idx & 511, r = rem >> 2, s = rem & 3;
            const bf16* src = pl ? Al : Ah;
            cpasync16(base + (u32)pl * 10240u + r * 80 + s * 16,
                      src + (size_t)(m0 + r) * DM + k0 + s * 8);
        }
#pragma unroll
        for (int it = 0; it < 2; ++it) {
            int idx = it * 512 + tid;
            int pl = idx >> 9, rem = idx & 511, r = rem >> 2, s = rem & 3;
            const bf16* src = pl ? Bl : Bh;
            cpasync16(base + 20480u + (u32)pl * 10240u + r * 80 + s * 16,
                      src + (size_t)(n0 + r) * DM + k0 + s * 8);
        }
        cpcommit();
    };

    const int NK = DM / 32;
    issue(0, 0);
    issue(32, 1);
    for (int kt = 0; kt < NK; ++kt) {
        if (kt == NK - 1) cpwait0(); else cpwait1();
        __syncthreads();
        if (kt + 2 < NK) issue((kt + 2) * 32, (kt + 2) % 3);
        u32 base = ub + (u32)(kt % 3) * 40960u;
        u32 aH = base, aL = base + 10240u, bH = base + 20480u, bL = base + 30720u;
#pragma unroll
        for (int ks = 0; ks < 2; ++ks) {
            int kk = ks * 16;
            u32 ah[2][4], al[2][4], bh[2][4], bl[2][4];
#pragma unroll
            for (int m2 = 0; m2 < 2; ++m2) {
                ldsm4(addrA(aH, 80, wm * 32 + m2 * 16, kk, lane),
                      ah[m2][0], ah[m2][1], ah[m2][2], ah[m2][3]);
                ldsm4(addrA(aL, 80, wm * 32 + m2 * 16, kk, lane),
                      al[m2][0], al[m2][1], al[m2][2], al[m2][3]);
            }
#pragma unroll
            for (int q = 0; q < 2; ++q) {
                ldsm4(addrB(bH, 80, wn * 32 + q * 16, kk, lane),
                      bh[q][0], bh[q][1], bh[q][2], bh[q][3]);
                ldsm4(addrB(bL, 80, wn * 32 + q * 16, kk, lane),
                      bl[q][0], bl[q][1], bl[q][2], bl[q][3]);
            }
#pragma unroll
            for (int m2 = 0; m2 < 2; ++m2)
#pragma unroll
                for (int o = 0; o < 4; ++o) {
                    int q = o >> 1, pp = (o & 1) * 2;
                    hmma(acc[m2][o], ah[m2][0], ah[m2][1], ah[m2][2], ah[m2][3],
                         bh[q][pp], bh[q][pp + 1]);
                    hmma(acc[m2][o], ah[m2][0], ah[m2][1], ah[m2][2], ah[m2][3],
                         bl[q][pp], bl[q][pp + 1]);
                    hmma(acc[m2][o], al[m2][0], al[m2][1], al[m2][2], al[m2][3],
                         bh[q][pp], bh[q][pp + 1]);
                }
        }
    }
    const int g = lane >> 2, t = lane & 3;
#pragma unroll
    for (int m2 = 0; m2 < 2; ++m2)
#pragma unroll
        for (int o = 0; o < 4; ++o) {
            int row = m0 + wm * 32 + m2 * 16 + g;
            int col = n0 + wn * 32 + o * 8 + 2 * t;
            *(float2*)&C[(size_t)row * DM + col] = make_float2(acc[m2][o][0], acc[m2][o][1]);
            *(float2*)&C[(size_t)(row + 8) * DM + col] = make_float2(acc[m2][o][2], acc[m2][o][3]);
        }
}

// ---------------- 3 small projections fused: BM=64, grid (32,3) ----------------
__global__ __launch_bounds__(256, 2) void proj3() {
    __shared__ bf16 sA[2 * 2 * 64 * 40];
    __shared__ bf16 sB[2 * 2 * 64 * 40];
    const int z = blockIdx.y;
    const bf16* Ah = (z == 2) ? g_sh : g_xh;
    const bf16* Al = (z == 2) ? g_sl : g_xl;
    const bf16* Bh = (z == 0) ? g_wkah : (z == 1) ? g_wkrh : g_wvh;
    const bf16* Bl = (z == 0) ? g_wkal : (z == 1) ? g_wkrl : g_wvl;
    float* C = (z == 0) ? g_kaf : (z == 1) ? g_krf : g_vf;

    const int tid = threadIdx.x, lane = tid & 31, warp = tid >> 5;
    const int wm = warp & 3, wn = warp >> 2;
    const int m0 = blockIdx.x * 64;
    u32 ua = (u32)__cvta_generic_to_shared(sA);
    u32 ub = (u32)__cvta_generic_to_shared(sB);

    float acc[4][4];
#pragma unroll
    for (int o = 0; o < 4; ++o)
#pragma unroll
        for (int k = 0; k < 4; ++k) acc[o][k] = 0.f;

    auto issue = [&](int k0, int st) {
#pragma unroll
        for (int it = 0; it < 2; ++it) {
            int idx = it * 256 + tid;
            int pl = idx >> 8, rem = idx & 255, r = rem >> 2, s = rem & 3;
            const bf16* src = pl ? Al : Ah;
            cpasync16(ua + (u32)(st * 2 + pl) * 5120u + r * 80 + s * 16,
                      src + (size_t)(m0 + r) * DM + k0 + s * 8);
        }
#pragma unroll
        for (int it = 0; it < 2; ++it) {
            int idx = it * 256 + tid;
            int pl = idx >> 8, rem = idx & 255, r = rem >> 2, s = rem & 3;
            const bf16* src = pl ? Bl : Bh;
            cpasync16(ub + (u32)(st * 2 + pl) * 5120u + r * 80 + s * 16,
                      src + (size_t)r * DM + k0 + s * 8);
        }
        cpcommit();
    };

    issue(0, 0);
    const int NK = DM / 32;
    for (int kt = 0; kt < NK; ++kt) {
        if (kt + 1 < NK) { issue((kt + 1) * 32, (kt + 1) & 1); cpwait1(); }
        else cpwait0();
        __syncthreads();
        int st = kt & 1;
        u32 aH = ua + (u32)(st * 2) * 5120u, aL = aH + 5120u;
        u32 bH = ub + (u32)(st * 2) * 5120u, bL = bH + 5120u;
#pragma unroll
        for (int ks = 0; ks < 2; ++ks) {
            int kk = ks * 16;
            u32 ah[4], al[4], bh[2][4], bl[2][4];
            ldsm4(addrA(aH, 80, wm * 16, kk, lane), ah[0], ah[1], ah[2], ah[3]);
            ldsm4(addrA(aL, 80, wm * 16, kk, lane), al[0], al[1], al[2], al[3]);
#pragma unroll
            for (int q = 0; q < 2; ++q) {
                ldsm4(addrB(bH, 80, wn * 32 + q * 16, kk, lane),
                      bh[q][0], bh[q][1], bh[q][2], bh[q][3]);
                ldsm4(addrB(bL, 80, wn * 32 + q * 16, kk, lane),
                      bl[q][0], bl[q][1], bl[q][2], bl[q][3]);
            }
#pragma unroll
            for (int o = 0; o < 4; ++o) {
                int q = o >> 1, pp = (o & 1) * 2;
                hmma(acc[o], ah[0], ah[1], ah[2], ah[3], bh[q][pp], bh[q][pp + 1]);
                hmma(acc[o], ah[0], ah[1], ah[2], ah[3], bl[q][pp], bl[q][pp + 1]);
                hmma(acc[o], al[0], al[1], al[2], al[3], bh[q][pp], bh[q][pp + 1]);
            }
        }
        __syncthreads();
    }
    const int g = lane >> 2, t = lane & 3;
#pragma unroll
    for (int o = 0; o < 4; ++o) {
        int row = m0 + wm * 16 + g;
        int col = wn * 32 + o * 8 + 2 * t;
        *(float2*)&C[(size_t)row * HD + col] = make_float2(acc[o][0], acc[o][1]);
        *(float2*)&C[(size_t)(row + 8) * HD + col] = make_float2(acc[o][2], acc[o][3]);
    }
}

// ---------------- rope + permute + split ----------------
__global__ void rope_split(const float* __restrict__ fcos, const float* __restrict__ fsin) {
    const int NQ = L_SEQ * NH * 32;
    int idx = blockIdx.x * 256 + threadIdx.x;
    if (idx < NQ) {
        int p = idx & 31, hq = (idx >> 5) & 15, i = idx >> 9;
        float xr = g_t0[(size_t)i * DM + hq * 64 + 2 * p];
        float xi = g_t0[(size_t)i * DM + hq * 64 + 2 * p + 1];
        float c = fcos[i * 32 + p], s = fsin[i * 32 + p];
        float o0 = (xr * c - xi * s) * RSCALE, o1 = (xr * s + xi * c) * RSCALE;
        size_t o = ((size_t)hq * L_SEQ + i) * HD + 2 * p;
        split2(o0, g_qah[o], g_qal[o]);
        split2(o1, g_qah[o + 1], g_qal[o + 1]);
    } else if (idx < 2 * NQ) {
        int k = idx - NQ;
        int p = k & 31, hq = (k >> 5) & 15, i = k >> 9;
        float xr = g_t1[(size_t)i * DM + hq * 64 + 2 * p] * RSCALE;
        float xi = g_t1[(size_t)i * DM + hq * 64 + 2 * p + 1] * RSCALE;
        size_t o = ((size_t)hq * L_SEQ + i) * HD + 2 * p;
        split2(xr, g_qrh[o], g_qrl[o]);
        split2(xi, g_qrh[o + 1], g_qrl[o + 1]);
    } else if (idx < 2 * NQ + 65536) {
        int k = idx - 2 * NQ;
        int p = k & 31, i = k >> 5;
        float xr = g_kaf[i * HD + 2 * p], xi = g_kaf[i * HD + 2 * p + 1];
        float c = fcos[i * 32 + p], s = fsin[i * 32 + p];
        split2(xr * c - xi * s, g_kah[i * HD + 2 * p], g_kal[i * HD + 2 * p]);
        split2(xr * s + xi * c, g_kah[i * HD + 2 * p + 1], g_kal[i * HD + 2 * p + 1]);
    } else if (idx < 2 * NQ + 131072) {
        int k = idx - 2 * NQ - 65536;
        int p = k & 31, i = k >> 5;
        split2(g_krf[i * HD + 2 * p], g_krh[i * HD + 2 * p], g_krl[i * HD + 2 * p]);
        split2(g_krf[i * HD + 2 * p + 1], g_krh[i * HD + 2 * p + 1], g_krl[i * HD + 2 * p + 1]);
    } else if (idx < 2 * NQ + 262144) {
        int k = idx - 2 * NQ - 131072;
        int j = k & (L_SEQ - 1), d = k >> 11;
        split2(g_vf[(size_t)j * HD + d], g_vth[(size_t)d * L_SEQ + j], g_vtl[(size_t)d * L_SEQ + j]);
    }
}

// ---------------- attention: 512 thr, warp = 16 rows x 32 cols ----------------
__device__ __forceinline__ void mma_qk16(u32 aH, u32 aL, u32 bH, u32 bL,
                                         int wm, int wn, int lane, float cs[4][4]) {
#pragma unroll
    for (int ks = 0; ks < 4; ++ks) {
        int k0 = ks * 16;
        u32 ah[4], al[4], bh[2][4], bl[2][4];
        ldsm4(addrA(aH, 144, wm * 16, k0, lane), ah[0], ah[1], ah[2], ah[3]);
        ldsm4(addrA(aL, 144, wm * 16, k0, lane), al[0], al[1], al[2], al[3]);
#pragma unroll
        for (int q = 0; q < 2; ++q) {
            ldsm4(addrB(bH, 144, wn * 32 + q * 16, k0, lane),
                  bh[q][0], bh[q][1], bh[q][2], bh[q][3]);
            ldsm4(addrB(bL, 144, wn * 32 + q * 16, k0, lane),
                  bl[q][0], bl[q][1], bl[q][2], bl[q][3]);
        }
#pragma unroll
        for (int o = 0; o < 4; ++o) {
            int q = o >> 1, pp = (o & 1) * 2;
            hmma(cs[o], ah[0], ah[1], ah[2], ah[3], bh[q][pp], bh[q][pp + 1]);
            hmma(cs[o], ah[0], ah[1], ah[2], ah[3], bl[q][pp], bl[q][pp + 1]);
            hmma(cs[o], al[0], al[1], al[2], al[3], bh[q][pp], bh[q][pp + 1]);
        }
    }
}

__device__ __forceinline__ void store_frag16(float* dst, float c[4][4],
                                             int wm, int wn, int g, int t) {
#pragma unroll
    for (int o = 0; o < 4; ++o) {
        int row = wm * 16 + g;
        int col = wn * 32 + o * 8 + 2 * t;
        *(float2*)&dst[(size_t)row * L_SEQ + col] = make_float2(c[o][0], c[o][1]);
        *(float2*)&dst[(size_t)(row + 8) * L_SEQ + col] = make_float2(c[o][2], c[o][3]);
    }
}

__global__ __launch_bounds__(512, 1) void attn_mma(float* __restrict__ attn_out,
                                                   float* __restrict__ rel_out) {
    extern __shared__ char smraw[];
    u32 usm = (u32)__cvta_generic_to_shared(smraw);
    float* lsum = (float*)(smraw + 184320);
    float* linv = lsum + 256;
    float* osc  = (float*)(smraw + 73728);   // ring reuse after loop

    const int hq = blockIdx.y;
    const int ib = 15 - blockIdx.x;          // heavy blocks first
    const int i0 = ib * 128;
    const int tid = threadIdx.x, lane = tid & 31, warp = tid >> 5;
    const int wm = warp >> 1, wn = warp & 1;  // 8 x 2 warps, 16x32 each
    const int g = lane >> 2, t = lane & 3;
    const int jtmax = 2 * ib + 1;

    // Q planes: a=0..3 -> qa_h, qa_l, qr_h, qr_l at usm + a*18432 (stride 144B)
    {
        const bf16* srcs[4] = {g_qah + ((size_t)hq * L_SEQ + i0) * HD,
                               g_qal + ((size_t)hq * L_SEQ + i0) * HD,
                               g_qrh + ((size_t)hq * L_SEQ + i0) * HD,
                               g_qrl + ((size_t)hq * L_SEQ + i0) * HD};
#pragma unroll
        for (int a = 0; a < 4; ++a)
#pragma unroll
            for (int it = 0; it < 2; ++it) {
                int idx = it * 512 + tid;
                int r = idx >> 3, s = idx & 7;
                *(uint4*)(smraw + a * 18432 + r * 144 + s * 16) =
                    *(const uint4*)&srcs[a][(size_t)r * HD + s * 8];
            }
    }
    const u32 uqa_h = usm, uqa_l = usm + 18432u;
    const u32 uqr_h = usm + 36864u, uqr_l = usm + 55296u;
    auto ring = [&](int st, int pl) -> u32 {
        return usm + 73728u + (u32)st * 55296u + (u32)pl * 9216u;
    };

    auto issue_tiles = [&](int jt, int st, bool causal) {
#pragma unroll
        for (int it = 0; it < 2; ++it) {
            int idx = it * 512 + tid;
            int pl = idx >> 9, rem = idx & 511, r = rem >> 3, s = rem & 7;
            const bf16* src = pl ? g_krl : g_krh;
            cpasync16(ring(st, 2 + pl) + r * 144 + s * 16,
                      src + (size_t)(jt * 64 + r) * HD + s * 8);
        }
        if (causal) {
#pragma unroll
            for (int it = 0; it < 2; ++it) {
                int idx = it * 512 + tid;
                int pl = idx >> 9, rem = idx & 511, r = rem >> 3, s = rem & 7;
                const bf16* src = pl ? g_kal : g_kah;
                cpasync16(ring(st, pl) + r * 144 + s * 16,
                          src + (size_t)(jt * 64 + r) * HD + s * 8);
            }
#pragma unroll
            for (int it = 0; it < 2; ++it) {
                int idx = it * 512 + tid;
                int pl = idx >> 9, rem = idx & 511, r = rem >> 3, s = rem & 7;
                const bf16* src = pl ? g_vtl : g_vth;
                cpasync16(ring(st, 4 + pl) + r * 144 + s * 16,
                          src + (size_t)r * L_SEQ + jt * 64 + s * 8);
            }
        }
        cpcommit();
    };

    float esum[2] = {0.f, 0.f};
    float co[8][4];
#pragma unroll
    for (int o = 0; o < 8; ++o)
#pragma unroll
        for (int k = 0; k < 4; ++k) co[o][k] = 0.f;

    float* attnp = attn_out + (size_t)hq * L_SEQ * L_SEQ + (size_t)i0 * L_SEQ;
    float* relp  = rel_out  + (size_t)hq * L_SEQ * L_SEQ + (size_t)i0 * L_SEQ;

    issue_tiles(0, 0, true);
    for (int jt = 0; jt < 32; ++jt) {
        const bool causal = (jt <= jtmax);
        cpwait0();
        __syncthreads();
        if (jt < 31) issue_tiles(jt + 1, (jt + 1) & 1, (jt + 1) <= jtmax);
        int st = jt & 1;

        float cr[4][4];
#pragma unroll
        for (int o = 0; o < 4; ++o)
#pragma unroll
            for (int k = 0; k < 4; ++k) cr[o][k] = 0.f;
        mma_qk16(uqr_h, uqr_l, ring(st, 2), ring(st, 3), wm, wn, lane, cr);
        store_frag16(relp + jt * 64, cr, wm, wn, g, t);

        if (!causal) {
            float4 z = make_float4(0.f, 0.f, 0.f, 0.f);
#pragma unroll
            for (int it = 0; it < 4; ++it) {
                int idx = it * 512 + tid;
                int r = idx >> 4, s = idx & 15;
                *(float4*)&attnp[(size_t)r * L_SEQ + jt * 64 + s * 4] = z;
            }
            continue;
        }

        float csq[4][4];
#pragma unroll
        for (int o = 0; o < 4; ++o)
#pragma unroll
            for (int k = 0; k < 4; ++k) csq[o][k] = 0.f;
        mma_qk16(uqa_h, uqa_l, ring(st, 0), ring(st, 1), wm, wn, lane, csq);

        const bool dia = (jt >= 2 * ib);
        const int r0 = i0 + wm * 16 + g;
#pragma unroll
        for (int o = 0; o < 4; ++o) {
            int cb = jt * 64 + wn * 32 + o * 8 + 2 * t;
            float p0 = __expf(csq[o][0]);
            float p1 = __expf(csq[o][1]);
            float p2 = __expf(csq[o][2]);
            float p3 = __expf(csq[o][3]);
            if (dia) {
                if (cb     > r0)     p0 = 0.f;
                if (cb + 1 > r0)     p1 = 0.f;
                if (cb     > r0 + 8) p2 = 0.f;
                if (cb + 1 > r0 + 8) p3 = 0.f;
            }
            esum[0] += p0 + p1;
            esum[1] += p2 + p3;
            csq[o][0] = p0; csq[o][1] = p1; csq[o][2] = p2; csq[o][3] = p3;
        }
        store_frag16(attnp + jt * 64, csq, wm, wn, g, t);

        // O += (E.R) @ V over this warp's 32 j-cols (unnormalized)
#pragma unroll
        for (int b = 0; b < 2; ++b) {
            float pr[8];
#pragma unroll
            for (int k = 0; k < 4; ++k) {
                pr[k]     = csq[2 * b][k]     * cr[2 * b][k];
                pr[4 + k] = csq[2 * b + 1][k] * cr[2 * b + 1][k];
            }
            u32 aH[4], aL[4];
            packsplit(pr[0], pr[1], aH[0], aL[0]);
            packsplit(pr[2], pr[3], aH[1], aL[1]);
            packsplit(pr[4], pr[5], aH[2], aL[2]);
            packsplit(pr[6], pr[7], aH[3], aL[3]);
#pragma unroll
            for (int q2 = 0; q2 < 4; ++q2) {
                u32 vh[4], vl[4];
                ldsm4(addrB(ring(st, 4), 144, q2 * 16, wn * 32 + b * 16, lane),
                      vh[0], vh[1], vh[2], vh[3]);
                ldsm4(addrB(ring(st, 5), 144, q2 * 16, wn * 32 + b * 16, lane),
                      vl[0], vl[1], vl[2], vl[3]);
#pragma unroll
                for (int sub = 0; sub < 2; ++sub) {
                    int o = q2 * 2 + sub, pp = sub * 2;
                    hmma(co[o], aH[0], aH[1], aH[2], aH[3], vh[pp], vh[pp + 1]);
                    hmma(co[o], aH[0], aH[1], aH[2], aH[3], vl[pp], vl[pp + 1]);
                    hmma(co[o], aL[0], aL[1], aL[2], aL[3], vh[pp], vh[pp + 1]);
                }
            }
        }
    }

    // -------- reduce row sums, compute 1/l --------
#pragma unroll
    for (int hf = 0; hf < 2; ++hf) {
        float v = esum[hf];
        v += __shfl_xor_sync(0xffffffffu, v, 1);
        v += __shfl_xor_sync(0xffffffffu, v, 2);
        esum[hf] = v;
    }
    __syncthreads();                 // all warps done with ring before osc reuse
    if (t == 0) {
        lsum[wn * 128 + wm * 16 + g] = esum[0];
        lsum[wn * 128 + wm * 16 + g + 8] = esum[1];
    }
    __syncthreads();
    if (tid < 128) {
        float v = __fdividef(1.f, lsum[tid] + lsum[128 + tid]);
        linv[tid] = v;
        g_linv[hq * L_SEQ + i0 + tid] = v;
    }

    // -------- O reduction across wn (osc = ring region) --------
    if (wn == 0) {
#pragma unroll
        for (int o = 0; o < 8; ++o) {
            int row = wm * 16 + g;
            int col = o * 8 + 2 * t;
            *(float2*)&osc[row * 68 + col] = make_float2(co[o][0], co[o][1]);
            *(float2*)&osc[(row + 8) * 68 + col] = make_float2(co[o][2], co[o][3]);
        }
    }
    __syncthreads();
    if (wn == 1) {
#pragma unroll
        for (int o = 0; o < 8; ++o) {
            int row = wm * 16 + g;
            int col = o * 8 + 2 * t;
            osc[row * 68 + col]           += co[o][0];
            osc[row * 68 + col + 1]       += co[o][1];
            osc[(row + 8) * 68 + col]     += co[o][2];
            osc[(row + 8) * 68 + col + 1] += co[o][3];
        }
    }
    __syncthreads();
#pragma unroll
    for (int it = 0; it < 16; ++it) {
        int idx = it * 512 + tid;
        int r = idx >> 6, d = idx & 63;
        float v = osc[r * 68 + d] * linv[r];
        bf16 hh, ll; split2(v, hh, ll);
        size_t off = (size_t)(i0 + r) * DM + hq * 64 + d;
        g_aoh[off] = hh; g_aol[off] = ll;
    }
}

// ---------------- rescale causal attn region by 1/l ----------------
__global__ __launch_bounds__(256) void rescale_attn(float* __restrict__ attn) {
    const int i = blockIdx.x, hq = blockIdx.y;
    const float s = g_linv[hq * L_SEQ + i];
    float* row = attn + ((size_t)hq * L_SEQ + i) * L_SEQ;
    const int W = (((i >> 6) + 1) << 6);
    for (int c = threadIdx.x * 4; c < W; c += 256 * 4) {
        float4 v = *(float4*)&row[c];
        v.x *= s; v.y *= s; v.z *= s; v.w *= s;
        *(float4*)&row[c] = v;
    }
}

// ---------------------------------- launch ----------------------------------
extern "C" void kernel_launch(void* const* d_in, const int* in_sizes, int n_in,
                              void* d_out, int out_size) {
    (void)in_sizes; (void)n_in; (void)out_size;
    const float* x    = (const float*)d_in[0];
    const float* sym  = (const float*)d_in[1];
    const float* fcos = (const float*)d_in[2];
    const float* fsin = (const float*)d_in[3];
    const float* wqa  = (const float*)d_in[4];
    const float* wka  = (const float*)d_in[5];
    const float* wqr  = (const float*)d_in[6];
    const float* wkr  = (const float*)d_in[7];
    const float* wv   = (const float*)d_in[8];
    const float* wo   = (const float*)d_in[9];

    float* out  = (float*)d_out;
    float* attn = out + (size_t)L_SEQ * DM;
    float* rel  = attn + (size_t)NH * L_SEQ * L_SEQ;

    void* p;
#define GS(var, sym_) cudaGetSymbolAddress(&p, sym_); bf16* var = (bf16*)p;
#define GF(var, sym_) cudaGetSymbolAddress(&p, sym_); float* var = (float*)p;
    GS(xh, g_xh)   GS(xl, g_xl)
    GS(wqah, g_wqah) GS(wqal, g_wqal) GS(wqrh, g_wqrh) GS(wqrl, g_wqrl)
    GS(woh, g_woh)   GS(wol, g_wol)
    GS(aoh, g_aoh)   GS(aol, g_aol)
    GF(t0, g_t0) GF(t1, g_t1)
#undef GS
#undef GF

    static bool attrs_set = false;
    if (!attrs_set) {
        cudaFuncSetAttribute(gemm_big, cudaFuncAttributeMaxDynamicSharedMemorySize, 122880);
        cudaFuncSetAttribute(attn_mma, cudaFuncAttributeMaxDynamicSharedMemorySize, 185856);
        attrs_set = true;
    }

    split_in<<<(2 * L_SEQ * DM) / 256, 256>>>(x, sym);
    tsplit_big<<<dim3(32, 32, 3), 256>>>(wqa, wqr, wo);
    tsplit_small<<<dim3(32, 2, 3), 256>>>(wka, wkr, wv);

    gemm_big<<<dim3(8, 16), 512, 122880>>>(xh, xl, wqah, wqal, t0);
    gemm_big<<<dim3(8, 16), 512, 122880>>>(xh, xl, wqrh, wqrl, t1);
    proj3<<<dim3(32, 3), 256>>>();

    {
        int total = 2 * L_SEQ * NH * 32 + 262144;
        rope_split<<<(total + 255) / 256, 256>>>(fcos, fsin);
    }
    attn_mma<<<dim3(16, 16), 512, 185856>>>(attn, rel);
    rescale_attn<<<dim3(L_SEQ, NH), 256>>>(attn);
    gemm_big<<<dim3(8, 16), 512, 122880>>>(aoh, aol, woh, wol, out);
}

// round 8
// speedup vs baseline: 3.1267x; 1.0018x over previous
#include <cuda_runtime.h>
#include <cuda_bf16.h>
#include <cstdint>
#include <cstddef>

#define L_SEQ 2048
#define DM    1024
#define NH    16
#define HD    64
#define RSCALE 0.125f
typedef __nv_bfloat16 bf16;
typedef unsigned int u32;

// ---------------- scratch ----------------
__device__ bf16 g_xh[L_SEQ*DM],  g_xl[L_SEQ*DM];
__device__ bf16 g_sh[L_SEQ*DM],  g_sl[L_SEQ*DM];
__device__ bf16 g_wqah[DM*DM], g_wqal[DM*DM];
__device__ bf16 g_wqrh[DM*DM], g_wqrl[DM*DM];
__device__ bf16 g_woh [DM*DM], g_wol [DM*DM];
__device__ bf16 g_wkah[HD*DM], g_wkal[HD*DM];
__device__ bf16 g_wkrh[HD*DM], g_wkrl[HD*DM];
__device__ bf16 g_wvh [HD*DM], g_wvl [HD*DM];
__device__ float g_t0[L_SEQ*DM], g_t1[L_SEQ*DM];
__device__ float g_kaf[L_SEQ*HD], g_krf[L_SEQ*HD], g_vf[L_SEQ*HD];
__device__ bf16 g_qah[NH*L_SEQ*HD], g_qal[NH*L_SEQ*HD];
__device__ bf16 g_qrh[NH*L_SEQ*HD], g_qrl[NH*L_SEQ*HD];
__device__ bf16 g_kah[L_SEQ*HD], g_kal[L_SEQ*HD];
__device__ bf16 g_krh[L_SEQ*HD], g_krl[L_SEQ*HD];
__device__ bf16 g_vth[HD*L_SEQ], g_vtl[HD*L_SEQ];
__device__ bf16 g_aoh[L_SEQ*DM], g_aol[L_SEQ*DM];
__device__ float g_linv[NH*L_SEQ];

// ---------------- helpers ----------------
__device__ __forceinline__ void split2(float v, bf16& hi, bf16& lo) {
    hi = __float2bfloat16(v);
    lo = __float2bfloat16(v - __bfloat162float(hi));
}
__device__ __forceinline__ void packsplit(float a, float b, u32& ph, u32& pl) {
    float ah = __bfloat162float(__float2bfloat16(a));
    float bh = __bfloat162float(__float2bfloat16(b));
    __nv_bfloat162 hv = __floats2bfloat162_rn(ah, bh);
    __nv_bfloat162 lv = __floats2bfloat162_rn(a - ah, b - bh);
    ph = *reinterpret_cast<u32*>(&hv);
    pl = *reinterpret_cast<u32*>(&lv);
}
__device__ __forceinline__ void ldsm4(u32 addr, u32& r0, u32& r1, u32& r2, u32& r3) {
    asm volatile("ldmatrix.sync.aligned.m8n8.x4.shared.b16 {%0,%1,%2,%3}, [%4];"
                 : "=r"(r0), "=r"(r1), "=r"(r2), "=r"(r3) : "r"(addr));
}
__device__ __forceinline__ void hmma(float* c, u32 a0, u32 a1, u32 a2, u32 a3,
                                     u32 b0, u32 b1) {
    asm volatile("mma.sync.aligned.m16n8k16.row.col.f32.bf16.bf16.f32 "
                 "{%0,%1,%2,%3},{%4,%5,%6,%7},{%8,%9},{%0,%1,%2,%3};"
                 : "+f"(c[0]), "+f"(c[1]), "+f"(c[2]), "+f"(c[3])
                 : "r"(a0), "r"(a1), "r"(a2), "r"(a3), "r"(b0), "r"(b1));
}
__device__ __forceinline__ u32 addrA(u32 base, int ldb, int m0, int k0, int lane) {
    int g = lane & 7, grp = lane >> 3;
    return base + (u32)((m0 + g + (grp & 1) * 8) * ldb + (k0 + (grp >> 1) * 8) * 2);
}
__device__ __forceinline__ u32 addrB(u32 base, int ldb, int n0, int k0, int lane) {
    int g = lane & 7, grp = lane >> 3;
    return base + (u32)((n0 + g + (grp >> 1) * 8) * ldb + (k0 + (grp & 1) * 8) * 2);
}
__device__ __forceinline__ void cpasync16(u32 dst, const void* src) {
    asm volatile("cp.async.cg.shared.global [%0], [%1], 16;" :: "r"(dst), "l"(src));
}
__device__ __forceinline__ void cpcommit() { asm volatile("cp.async.commit_group;"); }
__device__ __forceinline__ void cpwait0() { asm volatile("cp.async.wait_group 0;"); }
__device__ __forceinline__ void cpwait1() { asm volatile("cp.async.wait_group 1;"); }

// ---------------- input split ----------------
__global__ void split_in(const float* __restrict__ x, const float* __restrict__ s) {
    int i = blockIdx.x * 256 + threadIdx.x;
    if (i < L_SEQ * DM) {
        split2(x[i], g_xh[i], g_xl[i]);
    } else {
        int k = i - L_SEQ * DM;
        if (k < L_SEQ * DM) split2(s[k], g_sh[k], g_sl[k]);
    }
}

// ---------------- weight transpose + split ----------------
__global__ void tsplit_big(const float* __restrict__ w0, const float* __restrict__ w1,
                           const float* __restrict__ w2) {
    __shared__ float t[32][33];
    int z = blockIdx.z;
    const float* src = (z == 0) ? w0 : (z == 1) ? w1 : w2;
    bf16* dh = (z == 0) ? g_wqah : (z == 1) ? g_wqrh : g_woh;
    bf16* dl = (z == 0) ? g_wqal : (z == 1) ? g_wqrl : g_wol;
    int k0 = blockIdx.x * 32, n0 = blockIdx.y * 32;
    int tx = threadIdx.x & 31, ty0 = threadIdx.x >> 5;
#pragma unroll
    for (int q = 0; q < 4; ++q) {
        int ty = ty0 * 4 + q;
        t[ty][tx] = src[(size_t)(k0 + ty) * DM + n0 + tx];
    }
    __syncthreads();
#pragma unroll
    for (int q = 0; q < 4; ++q) {
        int ty = ty0 * 4 + q;
        bf16 hh, ll; split2(t[tx][ty], hh, ll);
        size_t o = (size_t)(n0 + ty) * DM + k0 + tx;
        dh[o] = hh; dl[o] = ll;
    }
}
__global__ void tsplit_small(const float* __restrict__ w0, const float* __restrict__ w1,
                             const float* __restrict__ w2) {
    __shared__ float t[32][33];
    int z = blockIdx.z;
    const float* src = (z == 0) ? w0 : (z == 1) ? w1 : w2;
    bf16* dh = (z == 0) ? g_wkah : (z == 1) ? g_wkrh : g_wvh;
    bf16* dl = (z == 0) ? g_wkal : (z == 1) ? g_wkrl : g_wvl;
    int k0 = blockIdx.x * 32, n0 = blockIdx.y * 32;
    int tx = threadIdx.x & 31, ty0 = threadIdx.x >> 5;
#pragma unroll
    for (int q = 0; q < 4; ++q) {
        int ty = ty0 * 4 + q;
        t[ty][tx] = src[(size_t)(k0 + ty) * HD + n0 + tx];
    }
    __syncthreads();
#pragma unroll
    for (int q = 0; q < 4; ++q) {
        int ty = ty0 * 4 + q;
        bf16 hh, ll; split2(t[tx][ty], hh, ll);
        size_t o = (size_t)(n0 + ty) * DM + k0 + tx;
        dh[o] = hh; dl[o] = ll;
    }
}

// ---------------- big GEMM: BM=128 BN=64 BK=32, 3-stage, 2 CTA/SM, grid.z fused ------
// stage = 30720 B: Ah@0, Al@10240, Bh@20480, Bl@25600; row stride 80 B.
__global__ __launch_bounds__(256, 2) void gemm_big(
    const bf16* __restrict__ Ah,  const bf16* __restrict__ Al,
    const bf16* __restrict__ Bh0, const bf16* __restrict__ Bl0, float* __restrict__ C0,
    const bf16* __restrict__ Bh1, const bf16* __restrict__ Bl1, float* __restrict__ C1) {
    extern __shared__ bf16 dsm[];
    const bf16* Bh = blockIdx.z ? Bh1 : Bh0;
    const bf16* Bl = blockIdx.z ? Bl1 : Bl0;
    float* C = blockIdx.z ? C1 : C0;
    const int tid = threadIdx.x, lane = tid & 31, warp = tid >> 5;
    const int wm = warp & 3, wn = warp >> 2;       // 4 x 2 warps, 32x32 each
    const int m0 = blockIdx.y * 128, n0 = blockIdx.x * 64;
    u32 ub = (u32)__cvta_generic_to_shared(dsm);

    float acc[2][4][4];
#pragma unroll
    for (int m2 = 0; m2 < 2; ++m2)
#pragma unroll
        for (int o = 0; o < 4; ++o)
#pragma unroll
            for (int k = 0; k < 4; ++k) acc[m2][o][k] = 0.f;

    auto issue = [&](int k0, int st) {
        u32 base = ub + (u32)st * 30720u;
#pragma unroll
        for (int it = 0; it < 4; ++it) {
            int idx = it * 256 + tid;
            int pl = idx >> 9, rem = idx & 511, r = rem >> 2, s = rem & 3;
            const bf16* src = pl ? Al : Ah;
            cpasync16(base + (u32)pl * 10240u + r * 80 + s * 16,
                      src + (size_t)(m0 + r) * DM + k0 + s * 8);
        }
#pragma unroll
        for (int it = 0; it < 2; ++it) {
            int idx = it * 256 + tid;
            int pl = idx >> 8, rem = idx & 255, r = rem >> 2, s = rem & 3;
            const bf16* src = pl ? Bl : Bh;
            cpasync16(base + 20480u + (u32)pl * 5120u + r * 80 + s * 16,
                      src + (size_t)(n0 + r) * DM + k0 + s * 8);
        }
        cpcommit();
    };

    const int NK = DM / 32;
    issue(0, 0);
    issue(32, 1);
    for (int kt = 0; kt < NK; ++kt) {
        if (kt == NK - 1) cpwait0(); else cpwait1();
        __syncthreads();
        if (kt + 2 < NK) issue((kt + 2) * 32, (kt + 2) % 3);
        u32 base = ub + (u32)(kt % 3) * 30720u;
        u32 aH = base, aL = base + 10240u, bH = base + 20480u, bL = base + 25600u;
#pragma unroll
        for (int ks = 0; ks < 2; ++ks) {
            int kk = ks * 16;
            u32 ah[2][4], al[2][4], bh[2][4], bl[2][4];
#pragma unroll
            for (int m2 = 0; m2 < 2; ++m2) {
                ldsm4(addrA(aH, 80, wm * 32 + m2 * 16, kk, lane),
                      ah[m2][0], ah[m2][1], ah[m2][2], ah[m2][3]);
                ldsm4(addrA(aL, 80, wm * 32 + m2 * 16, kk, lane),
                      al[m2][0], al[m2][1], al[m2][2], al[m2][3]);
            }
#pragma unroll
            for (int q = 0; q < 2; ++q) {
                ldsm4(addrB(bH, 80, wn * 32 + q * 16, kk, lane),
                      bh[q][0], bh[q][1], bh[q][2], bh[q][3]);
                ldsm4(addrB(bL, 80, wn * 32 + q * 16, kk, lane),
                      bl[q][0], bl[q][1], bl[q][2], bl[q][3]);
            }
#pragma unroll
            for (int m2 = 0; m2 < 2; ++m2)
#pragma unroll
                for (int o = 0; o < 4; ++o) {
                    int q = o >> 1, pp = (o & 1) * 2;
                    hmma(acc[m2][o], ah[m2][0], ah[m2][1], ah[m2][2], ah[m2][3],
                         bh[q][pp], bh[q][pp + 1]);
                    hmma(acc[m2][o], ah[m2][0], ah[m2][1], ah[m2][2], ah[m2][3],
                         bl[q][pp], bl[q][pp + 1]);
                    hmma(acc[m2][o], al[m2][0], al[m2][1], al[m2][2], al[m2][3],
                         bh[q][pp], bh[q][pp + 1]);
                }
        }
    }
    const int g = lane >> 2, t = lane & 3;
#pragma unroll
    for (int m2 = 0; m2 < 2; ++m2)
#pragma unroll
        for (int o = 0; o < 4; ++o) {
            int row = m0 + wm * 32 + m2 * 16 + g;
            int col = n0 + wn * 32 + o * 8 + 2 * t;
            *(float2*)&C[(size_t)row * DM + col] = make_float2(acc[m2][o][0], acc[m2][o][1]);
            *(float2*)&C[(size_t)(row + 8) * DM + col] = make_float2(acc[m2][o][2], acc[m2][o][3]);
        }
}

// ---------------- 3 small projections fused: BM=64, grid (32,3) ----------------
__global__ __launch_bounds__(256, 2) void proj3() {
    __shared__ bf16 sA[2 * 2 * 64 * 40];
    __shared__ bf16 sB[2 * 2 * 64 * 40];
    const int z = blockIdx.y;
    const bf16* Ah = (z == 2) ? g_sh : g_xh;
    const bf16* Al = (z == 2) ? g_sl : g_xl;
    const bf16* Bh = (z == 0) ? g_wkah : (z == 1) ? g_wkrh : g_wvh;
    const bf16* Bl = (z == 0) ? g_wkal : (z == 1) ? g_wkrl : g_wvl;
    float* C = (z == 0) ? g_kaf : (z == 1) ? g_krf : g_vf;

    const int tid = threadIdx.x, lane = tid & 31, warp = tid >> 5;
    const int wm = warp & 3, wn = warp >> 2;
    const int m0 = blockIdx.x * 64;
    u32 ua = (u32)__cvta_generic_to_shared(sA);
    u32 ub = (u32)__cvta_generic_to_shared(sB);

    float acc[4][4];
#pragma unroll
    for (int o = 0; o < 4; ++o)
#pragma unroll
        for (int k = 0; k < 4; ++k) acc[o][k] = 0.f;

    auto issue = [&](int k0, int st) {
#pragma unroll
        for (int it = 0; it < 2; ++it) {
            int idx = it * 256 + tid;
            int pl = idx >> 8, rem = idx & 255, r = rem >> 2, s = rem & 3;
            const bf16* src = pl ? Al : Ah;
            cpasync16(ua + (u32)(st * 2 + pl) * 5120u + r * 80 + s * 16,
                      src + (size_t)(m0 + r) * DM + k0 + s * 8);
        }
#pragma unroll
        for (int it = 0; it < 2; ++it) {
            int idx = it * 256 + tid;
            int pl = idx >> 8, rem = idx & 255, r = rem >> 2, s = rem & 3;
            const bf16* src = pl ? Bl : Bh;
            cpasync16(ub + (u32)(st * 2 + pl) * 5120u + r * 80 + s * 16,
                      src + (size_t)r * DM + k0 + s * 8);
        }
        cpcommit();
    };

    issue(0, 0);
    const int NK = DM / 32;
    for (int kt = 0; kt < NK; ++kt) {
        if (kt + 1 < NK) { issue((kt + 1) * 32, (kt + 1) & 1); cpwait1(); }
        else cpwait0();
        __syncthreads();
        int st = kt & 1;
        u32 aH = ua + (u32)(st * 2) * 5120u, aL = aH + 5120u;
        u32 bH = ub + (u32)(st * 2) * 5120u, bL = bH + 5120u;
#pragma unroll
        for (int ks = 0; ks < 2; ++ks) {
            int kk = ks * 16;
            u32 ah[4], al[4], bh[2][4], bl[2][4];
            ldsm4(addrA(aH, 80, wm * 16, kk, lane), ah[0], ah[1], ah[2], ah[3]);
            ldsm4(addrA(aL, 80, wm * 16, kk, lane), al[0], al[1], al[2], al[3]);
#pragma unroll
            for (int q = 0; q < 2; ++q) {
                ldsm4(addrB(bH, 80, wn * 32 + q * 16, kk, lane),
                      bh[q][0], bh[q][1], bh[q][2], bh[q][3]);
                ldsm4(addrB(bL, 80, wn * 32 + q * 16, kk, lane),
                      bl[q][0], bl[q][1], bl[q][2], bl[q][3]);
            }
#pragma unroll
            for (int o = 0; o < 4; ++o) {
                int q = o >> 1, pp = (o & 1) * 2;
                hmma(acc[o], ah[0], ah[1], ah[2], ah[3], bh[q][pp], bh[q][pp + 1]);
                hmma(acc[o], ah[0], ah[1], ah[2], ah[3], bl[q][pp], bl[q][pp + 1]);
                hmma(acc[o], al[0], al[1], al[2], al[3], bh[q][pp], bh[q][pp + 1]);
            }
        }
        __syncthreads();
    }
    const int g = lane >> 2, t = lane & 3;
#pragma unroll
    for (int o = 0; o < 4; ++o) {
        int row = m0 + wm * 16 + g;
        int col = wn * 32 + o * 8 + 2 * t;
        *(float2*)&C[(size_t)row * HD + col] = make_float2(acc[o][0], acc[o][1]);
        *(float2*)&C[(size_t)(row + 8) * HD + col] = make_float2(acc[o][2], acc[o][3]);
    }
}

// ---------------- rope + permute + split ----------------
__global__ void rope_split(const float* __restrict__ fcos, const float* __restrict__ fsin) {
    const int NQ = L_SEQ * NH * 32;
    int idx = blockIdx.x * 256 + threadIdx.x;
    if (idx < NQ) {
        int p = idx & 31, hq = (idx >> 5) & 15, i = idx >> 9;
        float xr = g_t0[(size_t)i * DM + hq * 64 + 2 * p];
        float xi = g_t0[(size_t)i * DM + hq * 64 + 2 * p + 1];
        float c = fcos[i * 32 + p], s = fsin[i * 32 + p];
        float o0 = (xr * c - xi * s) * RSCALE, o1 = (xr * s + xi * c) * RSCALE;
        size_t o = ((size_t)hq * L_SEQ + i) * HD + 2 * p;
        split2(o0, g_qah[o], g_qal[o]);
        split2(o1, g_qah[o + 1], g_qal[o + 1]);
    } else if (idx < 2 * NQ) {
        int k = idx - NQ;
        int p = k & 31, hq = (k >> 5) & 15, i = k >> 9;
        float xr = g_t1[(size_t)i * DM + hq * 64 + 2 * p] * RSCALE;
        float xi = g_t1[(size_t)i * DM + hq * 64 + 2 * p + 1] * RSCALE;
        size_t o = ((size_t)hq * L_SEQ + i) * HD + 2 * p;
        split2(xr, g_qrh[o], g_qrl[o]);
        split2(xi, g_qrh[o + 1], g_qrl[o + 1]);
    } else if (idx < 2 * NQ + 65536) {
        int k = idx - 2 * NQ;
        int p = k & 31, i = k >> 5;
        float xr = g_kaf[i * HD + 2 * p], xi = g_kaf[i * HD + 2 * p + 1];
        float c = fcos[i * 32 + p], s = fsin[i * 32 + p];
        split2(xr * c - xi * s, g_kah[i * HD + 2 * p], g_kal[i * HD + 2 * p]);
        split2(xr * s + xi * c, g_kah[i * HD + 2 * p + 1], g_kal[i * HD + 2 * p + 1]);
    } else if (idx < 2 * NQ + 131072) {
        int k = idx - 2 * NQ - 65536;
        int p = k & 31, i = k >> 5;
        split2(g_krf[i * HD + 2 * p], g_krh[i * HD + 2 * p], g_krl[i * HD + 2 * p]);
        split2(g_krf[i * HD + 2 * p + 1], g_krh[i * HD + 2 * p + 1], g_krl[i * HD + 2 * p + 1]);
    } else if (idx < 2 * NQ + 262144) {
        int k = idx - 2 * NQ - 131072;
        int j = k & (L_SEQ - 1), d = k >> 11;
        split2(g_vf[(size_t)j * HD + d], g_vth[(size_t)d * L_SEQ + j], g_vtl[(size_t)d * L_SEQ + j]);
    }
}

// ---------------- attention: 512 thr, warp = 16 rows x 32 cols ----------------
__device__ __forceinline__ void mma_qk16(u32 aH, u32 aL, u32 bH, u32 bL,
                                         int wm, int wn, int lane, float cs[4][4]) {
#pragma unroll
    for (int ks = 0; ks < 4; ++ks) {
        int k0 = ks * 16;
        u32 ah[4], al[4], bh[2][4], bl[2][4];
        ldsm4(addrA(aH, 144, wm * 16, k0, lane), ah[0], ah[1], ah[2], ah[3]);
        ldsm4(addrA(aL, 144, wm * 16, k0, lane), al[0], al[1], al[2], al[3]);
#pragma unroll
        for (int q = 0; q < 2; ++q) {
            ldsm4(addrB(bH, 144, wn * 32 + q * 16, k0, lane),
                  bh[q][0], bh[q][1], bh[q][2], bh[q][3]);
            ldsm4(addrB(bL, 144, wn * 32 + q * 16, k0, lane),
                  bl[q][0], bl[q][1], bl[q][2], bl[q][3]);
        }
#pragma unroll
        for (int o = 0; o < 4; ++o) {
            int q = o >> 1, pp = (o & 1) * 2;
            hmma(cs[o], ah[0], ah[1], ah[2], ah[3], bh[q][pp], bh[q][pp + 1]);
            hmma(cs[o], ah[0], ah[1], ah[2], ah[3], bl[q][pp], bl[q][pp + 1]);
            hmma(cs[o], al[0], al[1], al[2], al[3], bh[q][pp], bh[q][pp + 1]);
        }
    }
}

__device__ __forceinline__ void store_frag16(float* dst, float c[4][4],
                                             int wm, int wn, int g, int t) {
#pragma unroll
    for (int o = 0; o < 4; ++o) {
        int row = wm * 16 + g;
        int col = wn * 32 + o * 8 + 2 * t;
        *(float2*)&dst[(size_t)row * L_SEQ + col] = make_float2(c[o][0], c[o][1]);
        *(float2*)&dst[(size_t)(row + 8) * L_SEQ + col] = make_float2(c[o][2], c[o][3]);
    }
}

__global__ __launch_bounds__(512, 1) void attn_mma(float* __restrict__ attn_out,
                                                   float* __restrict__ rel_out) {
    extern __shared__ char smraw[];
    u32 usm = (u32)__cvta_generic_to_shared(smraw);
    float* lsum = (float*)(smraw + 184320);
    float* linv = lsum + 256;
    float* osc  = (float*)(smraw + 73728);

    const int hq = blockIdx.y;
    const int ib = 15 - blockIdx.x;
    const int i0 = ib * 128;
    const int tid = threadIdx.x, lane = tid & 31, warp = tid >> 5;
    const int wm = warp >> 1, wn = warp & 1;
    const int g = lane >> 2, t = lane & 3;
    const int jtmax = 2 * ib + 1;

    {
        const bf16* srcs[4] = {g_qah + ((size_t)hq * L_SEQ + i0) * HD,
                               g_qal + ((size_t)hq * L_SEQ + i0) * HD,
                               g_qrh + ((size_t)hq * L_SEQ + i0) * HD,
                               g_qrl + ((size_t)hq * L_SEQ + i0) * HD};
#pragma unroll
        for (int a = 0; a < 4; ++a)
#pragma unroll
            for (int it = 0; it < 2; ++it) {
                int idx = it * 512 + tid;
                int r = idx >> 3, s = idx & 7;
                *(uint4*)(smraw + a * 18432 + r * 144 + s * 16) =
                    *(const uint4*)&srcs[a][(size_t)r * HD + s * 8];
            }
    }
    const u32 uqa_h = usm, uqa_l = usm + 18432u;
    const u32 uqr_h = usm + 36864u, uqr_l = usm + 55296u;
    auto ring = [&](int st, int pl) -> u32 {
        return usm + 73728u + (u32)st * 55296u + (u32)pl * 9216u;
    };

    auto issue_tiles = [&](int jt, int st, bool causal) {
#pragma unroll
        for (int it = 0; it < 2; ++it) {
            int idx = it * 512 + tid;
            int pl = idx >> 9, rem = idx & 511, r = rem >> 3, s = rem & 7;
            const bf16* src = pl ? g_krl : g_krh;
            cpasync16(ring(st, 2 + pl) + r * 144 + s * 16,
                      src + (size_t)(jt * 64 + r) * HD + s * 8);
        }
        if (causal) {
#pragma unroll
            for (int it = 0; it < 2; ++it) {
                int idx = it * 512 + tid;
                int pl = idx >> 9, rem = idx & 511, r = rem >> 3, s = rem & 7;
                const bf16* src = pl ? g_kal : g_kah;
                cpasync16(ring(st, pl) + r * 144 + s * 16,
                          src + (size_t)(jt * 64 + r) * HD + s * 8);
            }
#pragma unroll
            for (int it = 0; it < 2; ++it) {
                int idx = it * 512 + tid;
                int pl = idx >> 9, rem = idx & 511, r = rem >> 3, s = rem & 7;
                const bf16* src = pl ? g_vtl : g_vth;
                cpasync16(ring(st, 4 + pl) + r * 144 + s * 16,
                          src + (size_t)r * L_SEQ + jt * 64 + s * 8);
            }
        }
        cpcommit();
    };

    float esum[2] = {0.f, 0.f};
    float co[8][4];
#pragma unroll
    for (int o = 0; o < 8; ++o)
#pragma unroll
        for (int k = 0; k < 4; ++k) co[o][k] = 0.f;

    float* attnp = attn_out + (size_t)hq * L_SEQ * L_SEQ + (size_t)i0 * L_SEQ;
    float* relp  = rel_out  + (size_t)hq * L_SEQ * L_SEQ + (size_t)i0 * L_SEQ;

    issue_tiles(0, 0, true);
    for (int jt = 0; jt < 32; ++jt) {
        const bool causal = (jt <= jtmax);
        cpwait0();
        __syncthreads();
        if (jt < 31) issue_tiles(jt + 1, (jt + 1) & 1, (jt + 1) <= jtmax);
        int st = jt & 1;

        float cr[4][4];
#pragma unroll
        for (int o = 0; o < 4; ++o)
#pragma unroll
            for (int k = 0; k < 4; ++k) cr[o][k] = 0.f;
        mma_qk16(uqr_h, uqr_l, ring(st, 2), ring(st, 3), wm, wn, lane, cr);
        store_frag16(relp + jt * 64, cr, wm, wn, g, t);

        if (!causal) {
            float4 z = make_float4(0.f, 0.f, 0.f, 0.f);
#pragma unroll
            for (int it = 0; it < 4; ++it) {
                int idx = it * 512 + tid;
                int r = idx >> 4, s = idx & 15;
                *(float4*)&attnp[(size_t)r * L_SEQ + jt * 64 + s * 4] = z;
            }
            continue;
        }

        float csq[4][4];
#pragma unroll
        for (int o = 0; o < 4; ++o)
#pragma unroll
            for (int k = 0; k < 4; ++k) csq[o][k] = 0.f;
        mma_qk16(uqa_h, uqa_l, ring(st, 0), ring(st, 1), wm, wn, lane, csq);

        const bool dia = (jt >= 2 * ib);
        const int r0 = i0 + wm * 16 + g;
#pragma unroll
        for (int o = 0; o < 4; ++o) {
            int cb = jt * 64 + wn * 32 + o * 8 + 2 * t;
            float p0 = __expf(csq[o][0]);
            float p1 = __expf(csq[o][1]);
            float p2 = __expf(csq[o][2]);
            float p3 = __expf(csq[o][3]);
            if (dia) {
                if (cb     > r0)     p0 = 0.f;
                if (cb + 1 > r0)     p1 = 0.f;
                if (cb     > r0 + 8) p2 = 0.f;
                if (cb + 1 > r0 + 8) p3 = 0.f;
            }
            esum[0] += p0 + p1;
            esum[1] += p2 + p3;
            csq[o][0] = p0; csq[o][1] = p1; csq[o][2] = p2; csq[o][3] = p3;
        }
        store_frag16(attnp + jt * 64, csq, wm, wn, g, t);

#pragma unroll
        for (int b = 0; b < 2; ++b) {
            float pr[8];
#pragma unroll
            for (int k = 0; k < 4; ++k) {
                pr[k]     = csq[2 * b][k]     * cr[2 * b][k];
                pr[4 + k] = csq[2 * b + 1][k] * cr[2 * b + 1][k];
            }
            u32 aH[4], aL[4];
            packsplit(pr[0], pr[1], aH[0], aL[0]);
            packsplit(pr[2], pr[3], aH[1], aL[1]);
            packsplit(pr[4], pr[5], aH[2], aL[2]);
            packsplit(pr[6], pr[7], aH[3], aL[3]);
#pragma unroll
            for (int q2 = 0; q2 < 4; ++q2) {
                u32 vh[4], vl[4];
                ldsm4(addrB(ring(st, 4), 144, q2 * 16, wn * 32 + b * 16, lane),
                      vh[0], vh[1], vh[2], vh[3]);
                ldsm4(addrB(ring(st, 5), 144, q2 * 16, wn * 32 + b * 16, lane),
                      vl[0], vl[1], vl[2], vl[3]);
#pragma unroll
                for (int sub = 0; sub < 2; ++sub) {
                    int o = q2 * 2 + sub, pp = sub * 2;
                    hmma(co[o], aH[0], aH[1], aH[2], aH[3], vh[pp], vh[pp + 1]);
                    hmma(co[o], aH[0], aH[1], aH[2], aH[3], vl[pp], vl[pp + 1]);
                    hmma(co[o], aL[0], aL[1], aL[2], aL[3], vh[pp], vh[pp + 1]);
                }
            }
        }
    }

#pragma unroll
    for (int hf = 0; hf < 2; ++hf) {
        float v = esum[hf];
        v += __shfl_xor_sync(0xffffffffu, v, 1);
        v += __shfl_xor_sync(0xffffffffu, v, 2);
        esum[hf] = v;
    }
    __syncthreads();
    if (t == 0) {
        lsum[wn * 128 + wm * 16 + g] = esum[0];
        lsum[wn * 128 + wm * 16 + g + 8] = esum[1];
    }
    __syncthreads();
    if (tid < 128) {
        float v = __fdividef(1.f, lsum[tid] + lsum[128 + tid]);
        linv[tid] = v;
        g_linv[hq * L_SEQ + i0 + tid] = v;
    }

    if (wn == 0) {
#pragma unroll
        for (int o = 0; o < 8; ++o) {
            int row = wm * 16 + g;
            int col = o * 8 + 2 * t;
            *(float2*)&osc[row * 68 + col] = make_float2(co[o][0], co[o][1]);
            *(float2*)&osc[(row + 8) * 68 + col] = make_float2(co[o][2], co[o][3]);
        }
    }
    __syncthreads();
    if (wn == 1) {
#pragma unroll
        for (int o = 0; o < 8; ++o) {
            int row = wm * 16 + g;
            int col = o * 8 + 2 * t;
            osc[row * 68 + col]           += co[o][0];
            osc[row * 68 + col + 1]       += co[o][1];
            osc[(row + 8) * 68 + col]     += co[o][2];
            osc[(row + 8) * 68 + col + 1] += co[o][3];
        }
    }
    __syncthreads();
#pragma unroll
    for (int it = 0; it < 16; ++it) {
        int idx = it * 512 + tid;
        int r = idx >> 6, d = idx & 63;
        float v = osc[r * 68 + d] * linv[r];
        bf16 hh, ll; split2(v, hh, ll);
        size_t off = (size_t)(i0 + r) * DM + hq * 64 + d;
        g_aoh[off] = hh; g_aol[off] = ll;
    }
}

// ---------------- rescale causal attn region by 1/l ----------------
__global__ __launch_bounds__(256) void rescale_attn(float* __restrict__ attn) {
    const int i = blockIdx.x, hq = blockIdx.y;
    const float s = g_linv[hq * L_SEQ + i];
    float* row = attn + ((size_t)hq * L_SEQ + i) * L_SEQ;
    const int W = (((i >> 6) + 1) << 6);
    for (int c = threadIdx.x * 4; c < W; c += 256 * 4) {
        float4 v = *(float4*)&row[c];
        v.x *= s; v.y *= s; v.z *= s; v.w *= s;
        *(float4*)&row[c] = v;
    }
}

// ---------------------------------- launch ----------------------------------
extern "C" void kernel_launch(void* const* d_in, const int* in_sizes, int n_in,
                              void* d_out, int out_size) {
    (void)in_sizes; (void)n_in; (void)out_size;
    const float* x    = (const float*)d_in[0];
    const float* sym  = (const float*)d_in[1];
    const float* fcos = (const float*)d_in[2];
    const float* fsin = (const float*)d_in[3];
    const float* wqa  = (const float*)d_in[4];
    const float* wka  = (const float*)d_in[5];
    const float* wqr  = (const float*)d_in[6];
    const float* wkr  = (const float*)d_in[7];
    const float* wv   = (const float*)d_in[8];
    const float* wo   = (const float*)d_in[9];

    float* out  = (float*)d_out;
    float* attn = out + (size_t)L_SEQ * DM;
    float* rel  = attn + (size_t)NH * L_SEQ * L_SEQ;

    void* p;
#define GS(var, sym_) cudaGetSymbolAddress(&p, sym_); bf16* var = (bf16*)p;
#define GF(var, sym_) cudaGetSymbolAddress(&p, sym_); float* var = (float*)p;
    GS(xh, g_xh)   GS(xl, g_xl)
    GS(wqah, g_wqah) GS(wqal, g_wqal) GS(wqrh, g_wqrh) GS(wqrl, g_wqrl)
    GS(woh, g_woh)   GS(wol, g_wol)
    GS(aoh, g_aoh)   GS(aol, g_aol)
    GF(t0, g_t0) GF(t1, g_t1)
#undef GS
#undef GF

    static cudaStream_t s2 = nullptr;
    static cudaEvent_t evC = nullptr, evD = nullptr;
    if (!s2) {
        cudaStreamCreateWithFlags(&s2, cudaStreamNonBlocking);
        cudaEventCreateWithFlags(&evC, cudaEventDisableTiming);
        cudaEventCreateWithFlags(&evD, cudaEventDisableTiming);
        cudaFuncSetAttribute(gemm_big, cudaFuncAttributeMaxDynamicSharedMemorySize, 92160);
        cudaFuncSetAttribute(attn_mma, cudaFuncAttributeMaxDynamicSharedMemorySize, 185856);
    }

    split_in<<<(2 * L_SEQ * DM) / 256, 256>>>(x, sym);
    tsplit_big<<<dim3(32, 32, 3), 256>>>(wqa, wqr, wo);
    tsplit_small<<<dim3(32, 2, 3), 256>>>(wka, wkr, wv);

    // both big projections fused in one launch (grid.z selects weights/output)
    gemm_big<<<dim3(16, 16, 2), 256, 92160>>>(xh, xl, wqah, wqal, t0, wqrh, wqrl, t1);
    proj3<<<dim3(32, 3), 256>>>();

    {
        int total = 2 * L_SEQ * NH * 32 + 262144;
        rope_split<<<(total + 255) / 256, 256>>>(fcos, fsin);
    }
    attn_mma<<<dim3(16, 16), 512, 185856>>>(attn, rel);

    // fork: rescale on side stream, wo-projection on main stream (disjoint buffers)
    cudaEventRecord(evC, 0);
    cudaStreamWaitEvent(s2, evC, 0);
    rescale_attn<<<dim3(L_SEQ, NH), 256, 0, s2>>>(attn);
    cudaEventRecord(evD, s2);

    gemm_big<<<dim3(16, 16, 1), 256, 92160>>>(aoh, aol, woh, wol, out, woh, wol, out);
    cudaStreamWaitEvent(0, evD, 0);
}

// round 9
// speedup vs baseline: 3.2044x; 1.0249x over previous
#include <cuda_runtime.h>
#include <cuda_bf16.h>
#include <cstdint>
#include <cstddef>

#define L_SEQ 2048
#define DM    1024
#define NH    16
#define HD    64
#define RSCALE 0.125f
typedef __nv_bfloat16 bf16;
typedef unsigned int u32;

// ---------------- scratch ----------------
__device__ bf16 g_xh[L_SEQ*DM],  g_xl[L_SEQ*DM];
__device__ bf16 g_sh[L_SEQ*DM],  g_sl[L_SEQ*DM];
__device__ bf16 g_wqah[DM*DM], g_wqal[DM*DM];
__device__ bf16 g_wqrh[DM*DM], g_wqrl[DM*DM];
__device__ bf16 g_woh [DM*DM], g_wol [DM*DM];
__device__ bf16 g_wkah[HD*DM], g_wkal[HD*DM];
__device__ bf16 g_wkrh[HD*DM], g_wkrl[HD*DM];
__device__ bf16 g_wvh [HD*DM], g_wvl [HD*DM];
__device__ float g_t0[L_SEQ*DM], g_t1[L_SEQ*DM];
__device__ float g_kaf[L_SEQ*HD], g_krf[L_SEQ*HD], g_vf[L_SEQ*HD];
__device__ bf16 g_qah[NH*L_SEQ*HD], g_qal[NH*L_SEQ*HD];
__device__ bf16 g_qrh[NH*L_SEQ*HD], g_qrl[NH*L_SEQ*HD];
__device__ bf16 g_kah[L_SEQ*HD], g_kal[L_SEQ*HD];
__device__ bf16 g_krh[L_SEQ*HD], g_krl[L_SEQ*HD];
__device__ bf16 g_vth[HD*L_SEQ], g_vtl[HD*L_SEQ];
__device__ bf16 g_aoh[L_SEQ*DM], g_aol[L_SEQ*DM];
__device__ float g_linv[NH*L_SEQ];

// ---------------- helpers ----------------
__device__ __forceinline__ void split2(float v, bf16& hi, bf16& lo) {
    hi = __float2bfloat16(v);
    lo = __float2bfloat16(v - __bfloat162float(hi));
}
__device__ __forceinline__ void packsplit(float a, float b, u32& ph, u32& pl) {
    float ah = __bfloat162float(__float2bfloat16(a));
    float bh = __bfloat162float(__float2bfloat16(b));
    __nv_bfloat162 hv = __floats2bfloat162_rn(ah, bh);
    __nv_bfloat162 lv = __floats2bfloat162_rn(a - ah, b - bh);
    ph = *reinterpret_cast<u32*>(&hv);
    pl = *reinterpret_cast<u32*>(&lv);
}
__device__ __forceinline__ void ldsm4(u32 addr, u32& r0, u32& r1, u32& r2, u32& r3) {
    asm volatile("ldmatrix.sync.aligned.m8n8.x4.shared.b16 {%0,%1,%2,%3}, [%4];"
                 : "=r"(r0), "=r"(r1), "=r"(r2), "=r"(r3) : "r"(addr));
}
__device__ __forceinline__ void hmma(float* c, u32 a0, u32 a1, u32 a2, u32 a3,
                                     u32 b0, u32 b1) {
    asm volatile("mma.sync.aligned.m16n8k16.row.col.f32.bf16.bf16.f32 "
                 "{%0,%1,%2,%3},{%4,%5,%6,%7},{%8,%9},{%0,%1,%2,%3};"
                 : "+f"(c[0]), "+f"(c[1]), "+f"(c[2]), "+f"(c[3])
                 : "r"(a0), "r"(a1), "r"(a2), "r"(a3), "r"(b0), "r"(b1));
}
__device__ __forceinline__ u32 addrA(u32 base, int ldb, int m0, int k0, int lane) {
    int g = lane & 7, grp = lane >> 3;
    return base + (u32)((m0 + g + (grp & 1) * 8) * ldb + (k0 + (grp >> 1) * 8) * 2);
}
__device__ __forceinline__ u32 addrB(u32 base, int ldb, int n0, int k0, int lane) {
    int g = lane & 7, grp = lane >> 3;
    return base + (u32)((n0 + g + (grp >> 1) * 8) * ldb + (k0 + (grp & 1) * 8) * 2);
}
__device__ __forceinline__ void cpasync16(u32 dst, const void* src) {
    asm volatile("cp.async.cg.shared.global [%0], [%1], 16;" :: "r"(dst), "l"(src));
}
__device__ __forceinline__ void cpcommit() { asm volatile("cp.async.commit_group;"); }
__device__ __forceinline__ void cpwait0() { asm volatile("cp.async.wait_group 0;"); }
__device__ __forceinline__ void cpwait1() { asm volatile("cp.async.wait_group 1;"); }

// ---------------- input split ----------------
__global__ void split_in(const float* __restrict__ x, const float* __restrict__ s) {
    int i = blockIdx.x * 256 + threadIdx.x;
    if (i < L_SEQ * DM) {
        split2(x[i], g_xh[i], g_xl[i]);
    } else {
        int k = i - L_SEQ * DM;
        if (k < L_SEQ * DM) split2(s[k], g_sh[k], g_sl[k]);
    }
}

// ---------------- weight transpose + split ----------------
__global__ void tsplit_big(const float* __restrict__ w0, const float* __restrict__ w1,
                           const float* __restrict__ w2) {
    __shared__ float t[32][33];
    int z = blockIdx.z;
    const float* src = (z == 0) ? w0 : (z == 1) ? w1 : w2;
    bf16* dh = (z == 0) ? g_wqah : (z == 1) ? g_wqrh : g_woh;
    bf16* dl = (z == 0) ? g_wqal : (z == 1) ? g_wqrl : g_wol;
    int k0 = blockIdx.x * 32, n0 = blockIdx.y * 32;
    int tx = threadIdx.x & 31, ty0 = threadIdx.x >> 5;
#pragma unroll
    for (int q = 0; q < 4; ++q) {
        int ty = ty0 * 4 + q;
        t[ty][tx] = src[(size_t)(k0 + ty) * DM + n0 + tx];
    }
    __syncthreads();
#pragma unroll
    for (int q = 0; q < 4; ++q) {
        int ty = ty0 * 4 + q;
        bf16 hh, ll; split2(t[tx][ty], hh, ll);
        size_t o = (size_t)(n0 + ty) * DM + k0 + tx;
        dh[o] = hh; dl[o] = ll;
    }
}
__global__ void tsplit_small(const float* __restrict__ w0, const float* __restrict__ w1,
                             const float* __restrict__ w2) {
    __shared__ float t[32][33];
    int z = blockIdx.z;
    const float* src = (z == 0) ? w0 : (z == 1) ? w1 : w2;
    bf16* dh = (z == 0) ? g_wkah : (z == 1) ? g_wkrh : g_wvh;
    bf16* dl = (z == 0) ? g_wkal : (z == 1) ? g_wkrl : g_wvl;
    int k0 = blockIdx.x * 32, n0 = blockIdx.y * 32;
    int tx = threadIdx.x & 31, ty0 = threadIdx.x >> 5;
#pragma unroll
    for (int q = 0; q < 4; ++q) {
        int ty = ty0 * 4 + q;
        t[ty][tx] = src[(size_t)(k0 + ty) * HD + n0 + tx];
    }
    __syncthreads();
#pragma unroll
    for (int q = 0; q < 4; ++q) {
        int ty = ty0 * 4 + q;
        bf16 hh, ll; split2(t[tx][ty], hh, ll);
        size_t o = (size_t)(n0 + ty) * DM + k0 + tx;
        dh[o] = hh; dl[o] = ll;
    }
}

// ---------------- big GEMM: BM=128 BN=64 BK=32, 3-stage, 2 CTA/SM, grid.z fused ------
__global__ __launch_bounds__(256, 2) void gemm_big(
    const bf16* __restrict__ Ah,  const bf16* __restrict__ Al,
    const bf16* __restrict__ Bh0, const bf16* __restrict__ Bl0, float* __restrict__ C0,
    const bf16* __restrict__ Bh1, const bf16* __restrict__ Bl1, float* __restrict__ C1) {
    extern __shared__ bf16 dsm[];
    const bf16* Bh = blockIdx.z ? Bh1 : Bh0;
    const bf16* Bl = blockIdx.z ? Bl1 : Bl0;
    float* C = blockIdx.z ? C1 : C0;
    const int tid = threadIdx.x, lane = tid & 31, warp = tid >> 5;
    const int wm = warp & 3, wn = warp >> 2;
    const int m0 = blockIdx.y * 128, n0 = blockIdx.x * 64;
    u32 ub = (u32)__cvta_generic_to_shared(dsm);

    float acc[2][4][4];
#pragma unroll
    for (int m2 = 0; m2 < 2; ++m2)
#pragma unroll
        for (int o = 0; o < 4; ++o)
#pragma unroll
            for (int k = 0; k < 4; ++k) acc[m2][o][k] = 0.f;

    auto issue = [&](int k0, int st) {
        u32 base = ub + (u32)st * 30720u;
#pragma unroll
        for (int it = 0; it < 4; ++it) {
            int idx = it * 256 + tid;
            int pl = idx >> 9, rem = idx & 511, r = rem >> 2, s = rem & 3;
            const bf16* src = pl ? Al : Ah;
            cpasync16(base + (u32)pl * 10240u + r * 80 + s * 16,
                      src + (size_t)(m0 + r) * DM + k0 + s * 8);
        }
#pragma unroll
        for (int it = 0; it < 2; ++it) {
            int idx = it * 256 + tid;
            int pl = idx >> 8, rem = idx & 255, r = rem >> 2, s = rem & 3;
            const bf16* src = pl ? Bl : Bh;
            cpasync16(base + 20480u + (u32)pl * 5120u + r * 80 + s * 16,
                      src + (size_t)(n0 + r) * DM + k0 + s * 8);
        }
        cpcommit();
    };

    const int NK = DM / 32;
    issue(0, 0);
    issue(32, 1);
    for (int kt = 0; kt < NK; ++kt) {
        if (kt == NK - 1) cpwait0(); else cpwait1();
        __syncthreads();
        if (kt + 2 < NK) issue((kt + 2) * 32, (kt + 2) % 3);
        u32 base = ub + (u32)(kt % 3) * 30720u;
        u32 aH = base, aL = base + 10240u, bH = base + 20480u, bL = base + 25600u;
#pragma unroll
        for (int ks = 0; ks < 2; ++ks) {
            int kk = ks * 16;
            u32 ah[2][4], al[2][4], bh[2][4], bl[2][4];
#pragma unroll
            for (int m2 = 0; m2 < 2; ++m2) {
                ldsm4(addrA(aH, 80, wm * 32 + m2 * 16, kk, lane),
                      ah[m2][0], ah[m2][1], ah[m2][2], ah[m2][3]);
                ldsm4(addrA(aL, 80, wm * 32 + m2 * 16, kk, lane),
                      al[m2][0], al[m2][1], al[m2][2], al[m2][3]);
            }
#pragma unroll
            for (int q = 0; q < 2; ++q) {
                ldsm4(addrB(bH, 80, wn * 32 + q * 16, kk, lane),
                      bh[q][0], bh[q][1], bh[q][2], bh[q][3]);
                ldsm4(addrB(bL, 80, wn * 32 + q * 16, kk, lane),
                      bl[q][0], bl[q][1], bl[q][2], bl[q][3]);
            }
#pragma unroll
            for (int m2 = 0; m2 < 2; ++m2)
#pragma unroll
                for (int o = 0; o < 4; ++o) {
                    int q = o >> 1, pp = (o & 1) * 2;
                    hmma(acc[m2][o], ah[m2][0], ah[m2][1], ah[m2][2], ah[m2][3],
                         bh[q][pp], bh[q][pp + 1]);
                    hmma(acc[m2][o], ah[m2][0], ah[m2][1], ah[m2][2], ah[m2][3],
                         bl[q][pp], bl[q][pp + 1]);
                    hmma(acc[m2][o], al[m2][0], al[m2][1], al[m2][2], al[m2][3],
                         bh[q][pp], bh[q][pp + 1]);
                }
        }
    }
    const int g = lane >> 2, t = lane & 3;
#pragma unroll
    for (int m2 = 0; m2 < 2; ++m2)
#pragma unroll
        for (int o = 0; o < 4; ++o) {
            int row = m0 + wm * 32 + m2 * 16 + g;
            int col = n0 + wn * 32 + o * 8 + 2 * t;
            *(float2*)&C[(size_t)row * DM + col] = make_float2(acc[m2][o][0], acc[m2][o][1]);
            *(float2*)&C[(size_t)(row + 8) * DM + col] = make_float2(acc[m2][o][2], acc[m2][o][3]);
        }
}

// ---------------- 3 small projections fused: BM=64, grid (32,3) ----------------
__global__ __launch_bounds__(256, 2) void proj3() {
    __shared__ bf16 sA[2 * 2 * 64 * 40];
    __shared__ bf16 sB[2 * 2 * 64 * 40];
    const int z = blockIdx.y;
    const bf16* Ah = (z == 2) ? g_sh : g_xh;
    const bf16* Al = (z == 2) ? g_sl : g_xl;
    const bf16* Bh = (z == 0) ? g_wkah : (z == 1) ? g_wkrh : g_wvh;
    const bf16* Bl = (z == 0) ? g_wkal : (z == 1) ? g_wkrl : g_wvl;
    float* C = (z == 0) ? g_kaf : (z == 1) ? g_krf : g_vf;

    const int tid = threadIdx.x, lane = tid & 31, warp = tid >> 5;
    const int wm = warp & 3, wn = warp >> 2;
    const int m0 = blockIdx.x * 64;
    u32 ua = (u32)__cvta_generic_to_shared(sA);
    u32 ub = (u32)__cvta_generic_to_shared(sB);

    float acc[4][4];
#pragma unroll
    for (int o = 0; o < 4; ++o)
#pragma unroll
        for (int k = 0; k < 4; ++k) acc[o][k] = 0.f;

    auto issue = [&](int k0, int st) {
#pragma unroll
        for (int it = 0; it < 2; ++it) {
            int idx = it * 256 + tid;
            int pl = idx >> 8, rem = idx & 255, r = rem >> 2, s = rem & 3;
            const bf16* src = pl ? Al : Ah;
            cpasync16(ua + (u32)(st * 2 + pl) * 5120u + r * 80 + s * 16,
                      src + (size_t)(m0 + r) * DM + k0 + s * 8);
        }
#pragma unroll
        for (int it = 0; it < 2; ++it) {
            int idx = it * 256 + tid;
            int pl = idx >> 8, rem = idx & 255, r = rem >> 2, s = rem & 3;
            const bf16* src = pl ? Bl : Bh;
            cpasync16(ub + (u32)(st * 2 + pl) * 5120u + r * 80 + s * 16,
                      src + (size_t)r * DM + k0 + s * 8);
        }
        cpcommit();
    };

    issue(0, 0);
    const int NK = DM / 32;
    for (int kt = 0; kt < NK; ++kt) {
        if (kt + 1 < NK) { issue((kt + 1) * 32, (kt + 1) & 1); cpwait1(); }
        else cpwait0();
        __syncthreads();
        int st = kt & 1;
        u32 aH = ua + (u32)(st * 2) * 5120u, aL = aH + 5120u;
        u32 bH = ub + (u32)(st * 2) * 5120u, bL = bH + 5120u;
#pragma unroll
        for (int ks = 0; ks < 2; ++ks) {
            int kk = ks * 16;
            u32 ah[4], al[4], bh[2][4], bl[2][4];
            ldsm4(addrA(aH, 80, wm * 16, kk, lane), ah[0], ah[1], ah[2], ah[3]);
            ldsm4(addrA(aL, 80, wm * 16, kk, lane), al[0], al[1], al[2], al[3]);
#pragma unroll
            for (int q = 0; q < 2; ++q) {
                ldsm4(addrB(bH, 80, wn * 32 + q * 16, kk, lane),
                      bh[q][0], bh[q][1], bh[q][2], bh[q][3]);
                ldsm4(addrB(bL, 80, wn * 32 + q * 16, kk, lane),
                      bl[q][0], bl[q][1], bl[q][2], bl[q][3]);
            }
#pragma unroll
            for (int o = 0; o < 4; ++o) {
                int q = o >> 1, pp = (o & 1) * 2;
                hmma(acc[o], ah[0], ah[1], ah[2], ah[3], bh[q][pp], bh[q][pp + 1]);
                hmma(acc[o], ah[0], ah[1], ah[2], ah[3], bl[q][pp], bl[q][pp + 1]);
                hmma(acc[o], al[0], al[1], al[2], al[3], bh[q][pp], bh[q][pp + 1]);
            }
        }
        __syncthreads();
    }
    const int g = lane >> 2, t = lane & 3;
#pragma unroll
    for (int o = 0; o < 4; ++o) {
        int row = m0 + wm * 16 + g;
        int col = wn * 32 + o * 8 + 2 * t;
        *(float2*)&C[(size_t)row * HD + col] = make_float2(acc[o][0], acc[o][1]);
        *(float2*)&C[(size_t)(row + 8) * HD + col] = make_float2(acc[o][2], acc[o][3]);
    }
}

// ---------------- rope + permute + split ----------------
__global__ void rope_split(const float* __restrict__ fcos, const float* __restrict__ fsin) {
    const int NQ = L_SEQ * NH * 32;
    int idx = blockIdx.x * 256 + threadIdx.x;
    if (idx < NQ) {
        int p = idx & 31, hq = (idx >> 5) & 15, i = idx >> 9;
        float xr = g_t0[(size_t)i * DM + hq * 64 + 2 * p];
        float xi = g_t0[(size_t)i * DM + hq * 64 + 2 * p + 1];
        float c = fcos[i * 32 + p], s = fsin[i * 32 + p];
        float o0 = (xr * c - xi * s) * RSCALE, o1 = (xr * s + xi * c) * RSCALE;
        size_t o = ((size_t)hq * L_SEQ + i) * HD + 2 * p;
        split2(o0, g_qah[o], g_qal[o]);
        split2(o1, g_qah[o + 1], g_qal[o + 1]);
    } else if (idx < 2 * NQ) {
        int k = idx - NQ;
        int p = k & 31, hq = (k >> 5) & 15, i = k >> 9;
        float xr = g_t1[(size_t)i * DM + hq * 64 + 2 * p] * RSCALE;
        float xi = g_t1[(size_t)i * DM + hq * 64 + 2 * p + 1] * RSCALE;
        size_t o = ((size_t)hq * L_SEQ + i) * HD + 2 * p;
        split2(xr, g_qrh[o], g_qrl[o]);
        split2(xi, g_qrh[o + 1], g_qrl[o + 1]);
    } else if (idx < 2 * NQ + 65536) {
        int k = idx - 2 * NQ;
        int p = k & 31, i = k >> 5;
        float xr = g_kaf[i * HD + 2 * p], xi = g_kaf[i * HD + 2 * p + 1];
        float c = fcos[i * 32 + p], s = fsin[i * 32 + p];
        split2(xr * c - xi * s, g_kah[i * HD + 2 * p], g_kal[i * HD + 2 * p]);
        split2(xr * s + xi * c, g_kah[i * HD + 2 * p + 1], g_kal[i * HD + 2 * p + 1]);
    } else if (idx < 2 * NQ + 131072) {
        int k = idx - 2 * NQ - 65536;
        int p = k & 31, i = k >> 5;
        split2(g_krf[i * HD + 2 * p], g_krh[i * HD + 2 * p], g_krl[i * HD + 2 * p]);
        split2(g_krf[i * HD + 2 * p + 1], g_krh[i * HD + 2 * p + 1], g_krl[i * HD + 2 * p + 1]);
    } else if (idx < 2 * NQ + 262144) {
        int k = idx - 2 * NQ - 131072;
        int j = k & (L_SEQ - 1), d = k >> 11;
        split2(g_vf[(size_t)j * HD + d], g_vth[(size_t)d * L_SEQ + j], g_vtl[(size_t)d * L_SEQ + j]);
    }
}

// ---------------- attention: 512 thr, warp = 16 rows x 32 cols ----------------
__device__ __forceinline__ void mma_qk16(u32 aH, u32 aL, u32 bH, u32 bL,
                                         int wm, int wn, int lane, float cs[4][4]) {
#pragma unroll
    for (int ks = 0; ks < 4; ++ks) {
        int k0 = ks * 16;
        u32 ah[4], al[4], bh[2][4], bl[2][4];
        ldsm4(addrA(aH, 144, wm * 16, k0, lane), ah[0], ah[1], ah[2], ah[3]);
        ldsm4(addrA(aL, 144, wm * 16, k0, lane), al[0], al[1], al[2], al[3]);
#pragma unroll
        for (int q = 0; q < 2; ++q) {
            ldsm4(addrB(bH, 144, wn * 32 + q * 16, k0, lane),
                  bh[q][0], bh[q][1], bh[q][2], bh[q][3]);
            ldsm4(addrB(bL, 144, wn * 32 + q * 16, k0, lane),
                  bl[q][0], bl[q][1], bl[q][2], bl[q][3]);
        }
#pragma unroll
        for (int o = 0; o < 4; ++o) {
            int q = o >> 1, pp = (o & 1) * 2;
            hmma(cs[o], ah[0], ah[1], ah[2], ah[3], bh[q][pp], bh[q][pp + 1]);
            hmma(cs[o], ah[0], ah[1], ah[2], ah[3], bl[q][pp], bl[q][pp + 1]);
            hmma(cs[o], al[0], al[1], al[2], al[3], bh[q][pp], bh[q][pp + 1]);
        }
    }
}

__device__ __forceinline__ void store_frag16(float* dst, float c[4][4],
                                             int wm, int wn, int g, int t) {
#pragma unroll
    for (int o = 0; o < 4; ++o) {
        int row = wm * 16 + g;
        int col = wn * 32 + o * 8 + 2 * t;
        *(float2*)&dst[(size_t)row * L_SEQ + col] = make_float2(c[o][0], c[o][1]);
        *(float2*)&dst[(size_t)(row + 8) * L_SEQ + col] = make_float2(c[o][2], c[o][3]);
    }
}

__global__ __launch_bounds__(512, 1) void attn_mma(float* __restrict__ attn_out,
                                                   float* __restrict__ rel_out) {
    extern __shared__ char smraw[];
    u32 usm = (u32)__cvta_generic_to_shared(smraw);
    float* lsum = (float*)(smraw + 184320);
    float* linv = lsum + 256;
    float* osc  = (float*)(smraw + 73728);

    const int hq = blockIdx.y;
    const int ib = 15 - blockIdx.x;
    const int i0 = ib * 128;
    const int tid = threadIdx.x, lane = tid & 31, warp = tid >> 5;
    const int wm = warp >> 1, wn = warp & 1;
    const int g = lane >> 2, t = lane & 3;
    const int jtmax = 2 * ib + 1;

    {
        const bf16* srcs[4] = {g_qah + ((size_t)hq * L_SEQ + i0) * HD,
                               g_qal + ((size_t)hq * L_SEQ + i0) * HD,
                               g_qrh + ((size_t)hq * L_SEQ + i0) * HD,
                               g_qrl + ((size_t)hq * L_SEQ + i0) * HD};
#pragma unroll
        for (int a = 0; a < 4; ++a)
#pragma unroll
            for (int it = 0; it < 2; ++it) {
                int idx = it * 512 + tid;
                int r = idx >> 3, s = idx & 7;
                *(uint4*)(smraw + a * 18432 + r * 144 + s * 16) =
                    *(const uint4*)&srcs[a][(size_t)r * HD + s * 8];
            }
    }
    const u32 uqa_h = usm, uqa_l = usm + 18432u;
    const u32 uqr_h = usm + 36864u, uqr_l = usm + 55296u;
    auto ring = [&](int st, int pl) -> u32 {
        return usm + 73728u + (u32)st * 55296u + (u32)pl * 9216u;
    };

    auto issue_tiles = [&](int jt, int st, bool causal) {
#pragma unroll
        for (int it = 0; it < 2; ++it) {
            int idx = it * 512 + tid;
            int pl = idx >> 9, rem = idx & 511, r = rem >> 3, s = rem & 7;
            const bf16* src = pl ? g_krl : g_krh;
            cpasync16(ring(st, 2 + pl) + r * 144 + s * 16,
                      src + (size_t)(jt * 64 + r) * HD + s * 8);
        }
        if (causal) {
#pragma unroll
            for (int it = 0; it < 2; ++it) {
                int idx = it * 512 + tid;
                int pl = idx >> 9, rem = idx & 511, r = rem >> 3, s = rem & 7;
                const bf16* src = pl ? g_kal : g_kah;
                cpasync16(ring(st, pl) + r * 144 + s * 16,
                          src + (size_t)(jt * 64 + r) * HD + s * 8);
            }
#pragma unroll
            for (int it = 0; it < 2; ++it) {
                int idx = it * 512 + tid;
                int pl = idx >> 9, rem = idx & 511, r = rem >> 3, s = rem & 7;
                const bf16* src = pl ? g_vtl : g_vth;
                cpasync16(ring(st, 4 + pl) + r * 144 + s * 16,
                          src + (size_t)r * L_SEQ + jt * 64 + s * 8);
            }
        }
        cpcommit();
    };

    float esum[2] = {0.f, 0.f};
    float co[8][4];
#pragma unroll
    for (int o = 0; o < 8; ++o)
#pragma unroll
        for (int k = 0; k < 4; ++k) co[o][k] = 0.f;

    float* attnp = attn_out + (size_t)hq * L_SEQ * L_SEQ + (size_t)i0 * L_SEQ;
    float* relp  = rel_out  + (size_t)hq * L_SEQ * L_SEQ + (size_t)i0 * L_SEQ;

    issue_tiles(0, 0, true);
    for (int jt = 0; jt < 32; ++jt) {
        const bool causal = (jt <= jtmax);
        cpwait0();
        __syncthreads();
        if (jt < 31) issue_tiles(jt + 1, (jt + 1) & 1, (jt + 1) <= jtmax);
        int st = jt & 1;

        float cr[4][4];
#pragma unroll
        for (int o = 0; o < 4; ++o)
#pragma unroll
            for (int k = 0; k < 4; ++k) cr[o][k] = 0.f;
        mma_qk16(uqr_h, uqr_l, ring(st, 2), ring(st, 3), wm, wn, lane, cr);
        store_frag16(relp + jt * 64, cr, wm, wn, g, t);

        if (!causal) continue;   // zeros for attn written by rescale_zero kernel

        float csq[4][4];
#pragma unroll
        for (int o = 0; o < 4; ++o)
#pragma unroll
            for (int k = 0; k < 4; ++k) csq[o][k] = 0.f;
        mma_qk16(uqa_h, uqa_l, ring(st, 0), ring(st, 1), wm, wn, lane, csq);

        const bool dia = (jt >= 2 * ib);
        const int r0 = i0 + wm * 16 + g;
#pragma unroll
        for (int o = 0; o < 4; ++o) {
            int cb = jt * 64 + wn * 32 + o * 8 + 2 * t;
            float p0 = __expf(csq[o][0]);
            float p1 = __expf(csq[o][1]);
            float p2 = __expf(csq[o][2]);
            float p3 = __expf(csq[o][3]);
            if (dia) {
                if (cb     > r0)     p0 = 0.f;
                if (cb + 1 > r0)     p1 = 0.f;
                if (cb     > r0 + 8) p2 = 0.f;
                if (cb + 1 > r0 + 8) p3 = 0.f;
            }
            esum[0] += p0 + p1;
            esum[1] += p2 + p3;
            csq[o][0] = p0; csq[o][1] = p1; csq[o][2] = p2; csq[o][3] = p3;
        }
        store_frag16(attnp + jt * 64, csq, wm, wn, g, t);

#pragma unroll
        for (int b = 0; b < 2; ++b) {
            float pr[8];
#pragma unroll
            for (int k = 0; k < 4; ++k) {
                pr[k]     = csq[2 * b][k]     * cr[2 * b][k];
                pr[4 + k] = csq[2 * b + 1][k] * cr[2 * b + 1][k];
            }
            u32 aH[4], aL[4];
            packsplit(pr[0], pr[1], aH[0], aL[0]);
            packsplit(pr[2], pr[3], aH[1], aL[1]);
            packsplit(pr[4], pr[5], aH[2], aL[2]);
            packsplit(pr[6], pr[7], aH[3], aL[3]);
#pragma unroll
            for (int q2 = 0; q2 < 4; ++q2) {
                u32 vh[4], vl[4];
                ldsm4(addrB(ring(st, 4), 144, q2 * 16, wn * 32 + b * 16, lane),
                      vh[0], vh[1], vh[2], vh[3]);
                ldsm4(addrB(ring(st, 5), 144, q2 * 16, wn * 32 + b * 16, lane),
                      vl[0], vl[1], vl[2], vl[3]);
#pragma unroll
                for (int sub = 0; sub < 2; ++sub) {
                    int o = q2 * 2 + sub, pp = sub * 2;
                    hmma(co[o], aH[0], aH[1], aH[2], aH[3], vh[pp], vh[pp + 1]);
                    hmma(co[o], aH[0], aH[1], aH[2], aH[3], vl[pp], vl[pp + 1]);
                    hmma(co[o], aL[0], aL[1], aL[2], aL[3], vh[pp], vh[pp + 1]);
                }
            }
        }
    }

#pragma unroll
    for (int hf = 0; hf < 2; ++hf) {
        float v = esum[hf];
        v += __shfl_xor_sync(0xffffffffu, v, 1);
        v += __shfl_xor_sync(0xffffffffu, v, 2);
        esum[hf] = v;
    }
    __syncthreads();
    if (t == 0) {
        lsum[wn * 128 + wm * 16 + g] = esum[0];
        lsum[wn * 128 + wm * 16 + g + 8] = esum[1];
    }
    __syncthreads();
    if (tid < 128) {
        float v = __fdividef(1.f, lsum[tid] + lsum[128 + tid]);
        linv[tid] = v;
        g_linv[hq * L_SEQ + i0 + tid] = v;
    }

    if (wn == 0) {
#pragma unroll
        for (int o = 0; o < 8; ++o) {
            int row = wm * 16 + g;
            int col = o * 8 + 2 * t;
            *(float2*)&osc[row * 68 + col] = make_float2(co[o][0], co[o][1]);
            *(float2*)&osc[(row + 8) * 68 + col] = make_float2(co[o][2], co[o][3]);
        }
    }
    __syncthreads();
    if (wn == 1) {
#pragma unroll
        for (int o = 0; o < 8; ++o) {
            int row = wm * 16 + g;
            int col = o * 8 + 2 * t;
            osc[row * 68 + col]           += co[o][0];
            osc[row * 68 + col + 1]       += co[o][1];
            osc[(row + 8) * 68 + col]     += co[o][2];
            osc[(row + 8) * 68 + col + 1] += co[o][3];
        }
    }
    __syncthreads();
#pragma unroll
    for (int it = 0; it < 16; ++it) {
        int idx = it * 512 + tid;
        int r = idx >> 6, d = idx & 63;
        float v = osc[r * 68 + d] * linv[r];
        bf16 hh, ll; split2(v, hh, ll);
        size_t off = (size_t)(i0 + r) * DM + hq * 64 + d;
        g_aoh[off] = hh; g_aol[off] = ll;
    }
}

// ---------------- rescale causal region by 1/l, zero-fill the rest ----------------
__global__ __launch_bounds__(256) void rescale_zero(float* __restrict__ attn) {
    const int i = blockIdx.x, hq = blockIdx.y;
    const float s = g_linv[hq * L_SEQ + i];
    float* row = attn + ((size_t)hq * L_SEQ + i) * L_SEQ;
    const int W = (((i >> 6) + 1) << 6);   // causal tile width (written by attn_mma)
    for (int c = threadIdx.x * 4; c < W; c += 256 * 4) {
        float4 v = *(float4*)&row[c];
        v.x *= s; v.y *= s; v.z *= s; v.w *= s;
        *(float4*)&row[c] = v;
    }
    float4 z = make_float4(0.f, 0.f, 0.f, 0.f);
    for (int c = W + threadIdx.x * 4; c < L_SEQ; c += 256 * 4)
        *(float4*)&row[c] = z;
}

// ---------------------------------- launch ----------------------------------
extern "C" void kernel_launch(void* const* d_in, const int* in_sizes, int n_in,
                              void* d_out, int out_size) {
    (void)in_sizes; (void)n_in; (void)out_size;
    const float* x    = (const float*)d_in[0];
    const float* sym  = (const float*)d_in[1];
    const float* fcos = (const float*)d_in[2];
    const float* fsin = (const float*)d_in[3];
    const float* wqa  = (const float*)d_in[4];
    const float* wka  = (const float*)d_in[5];
    const float* wqr  = (const float*)d_in[6];
    const float* wkr  = (const float*)d_in[7];
    const float* wv   = (const float*)d_in[8];
    const float* wo   = (const float*)d_in[9];

    float* out  = (float*)d_out;
    float* attn = out + (size_t)L_SEQ * DM;
    float* rel  = attn + (size_t)NH * L_SEQ * L_SEQ;

    void* p;
#define GS(var, sym_) cudaGetSymbolAddress(&p, sym_); bf16* var = (bf16*)p;
#define GF(var, sym_) cudaGetSymbolAddress(&p, sym_); float* var = (float*)p;
    GS(xh, g_xh)   GS(xl, g_xl)
    GS(wqah, g_wqah) GS(wqal, g_wqal) GS(wqrh, g_wqrh) GS(wqrl, g_wqrl)
    GS(woh, g_woh)   GS(wol, g_wol)
    GS(aoh, g_aoh)   GS(aol, g_aol)
    GF(t0, g_t0) GF(t1, g_t1)
#undef GS
#undef GF

    static cudaStream_t s2 = nullptr;
    static cudaEvent_t ev0 = nullptr, ev1 = nullptr, evC = nullptr, evD = nullptr;
    if (!s2) {
        cudaStreamCreateWithFlags(&s2, cudaStreamNonBlocking);
        cudaEventCreateWithFlags(&ev0, cudaEventDisableTiming);
        cudaEventCreateWithFlags(&ev1, cudaEventDisableTiming);
        cudaEventCreateWithFlags(&evC, cudaEventDisableTiming);
        cudaEventCreateWithFlags(&evD, cudaEventDisableTiming);
        cudaFuncSetAttribute(gemm_big, cudaFuncAttributeMaxDynamicSharedMemorySize, 92160);
        cudaFuncSetAttribute(attn_mma, cudaFuncAttributeMaxDynamicSharedMemorySize, 185856);
    }

    // s0: input split -> fork
    split_in<<<(2 * L_SEQ * DM) / 256, 256>>>(x, sym);
    cudaEventRecord(ev0, 0);

    // s2: small weights + small projections (concurrent with big path)
    cudaStreamWaitEvent(s2, ev0, 0);
    tsplit_small<<<dim3(32, 2, 3), 256, 0, s2>>>(wka, wkr, wv);
    proj3<<<dim3(32, 3), 256, 0, s2>>>();
    cudaEventRecord(ev1, s2);

    // s0: big weights + both big projections
    tsplit_big<<<dim3(32, 32, 3), 256>>>(wqa, wqr, wo);
    gemm_big<<<dim3(16, 16, 2), 256, 92160>>>(xh, xl, wqah, wqal, t0, wqrh, wqrl, t1);
    cudaStreamWaitEvent(0, ev1, 0);

    {
        int total = 2 * L_SEQ * NH * 32 + 262144;
        rope_split<<<(total + 255) / 256, 256>>>(fcos, fsin);
    }
    attn_mma<<<dim3(16, 16), 512, 185856>>>(attn, rel);

    // fork: rescale+zero on s2, wo-projection on s0 (disjoint buffers)
    cudaEventRecord(evC, 0);
    cudaStreamWaitEvent(s2, evC, 0);
    rescale_zero<<<dim3(L_SEQ, NH), 256, 0, s2>>>(attn);
    cudaEventRecord(evD, s2);

    gemm_big<<<dim3(16, 16, 1), 256, 92160>>>(aoh, aol, woh, wol, out, woh, wol, out);
    cudaStreamWaitEvent(0, evD, 0);
}